// round 1
// baseline (speedup 1.0000x reference)
#include <cuda_runtime.h>
#include <mma.h>

using namespace nvcuda;

#define CB   8
#define CNQ  1024
#define CNC  2048
#define CE   768
#define CD   384
#define CNH  6
#define CHD  64
#define CHID 3072
#define CRQ  (CB*CNQ)   /* 8192  */
#define CRC  (CB*CNC)   /* 16384 */

// ---------------- scratch (no cudaMalloc allowed) ----------------
__device__ float g_cn[(size_t)CRC*CE];
__device__ float g_Q [(size_t)CRQ*CD];
__device__ float g_KV[(size_t)CRC*2*CD];
__device__ float g_S [(size_t)CB*CNH*CNQ*CNC];
__device__ float g_AO[(size_t)CRQ*CD];
__device__ float g_c [(size_t)CRQ*CE];
__device__ float g_t [(size_t)CRQ*CE];
__device__ float g_H [(size_t)CRQ*CHID];

// ---------------- LayerNorm: one block per 768-wide row ----------------
__global__ void ln_kernel(const float* __restrict__ x, const float* __restrict__ w,
                          const float* __restrict__ b, float* __restrict__ y)
{
    __shared__ float sm[8];
    size_t row = blockIdx.x;
    const float* xr = x + row * CE;
    float* yr = y + row * CE;
    int t = threadIdx.x;
    float v0 = xr[t], v1 = xr[t+256], v2 = xr[t+512];

    float s = v0 + v1 + v2;
    #pragma unroll
    for (int o=16;o;o>>=1) s += __shfl_xor_sync(0xffffffffu, s, o);
    if ((t&31)==0) sm[t>>5] = s;
    __syncthreads();
    if (t < 32) {
        float z = (t<8) ? sm[t] : 0.f;
        #pragma unroll
        for (int o=4;o;o>>=1) z += __shfl_xor_sync(0xffffffffu, z, o);
        if (t==0) sm[0] = z;
    }
    __syncthreads();
    float mean = sm[0] * (1.0f/CE);
    __syncthreads();

    float d0 = v0-mean, d1 = v1-mean, d2 = v2-mean;
    float q = d0*d0 + d1*d1 + d2*d2;
    #pragma unroll
    for (int o=16;o;o>>=1) q += __shfl_xor_sync(0xffffffffu, q, o);
    if ((t&31)==0) sm[t>>5] = q;
    __syncthreads();
    if (t < 32) {
        float z = (t<8) ? sm[t] : 0.f;
        #pragma unroll
        for (int o=4;o;o>>=1) z += __shfl_xor_sync(0xffffffffu, z, o);
        if (t==0) sm[0] = z;
    }
    __syncthreads();
    float inv = rsqrtf(sm[0]*(1.0f/CE) + 1e-5f);

    yr[t]     = d0*inv*w[t]     + b[t];
    yr[t+256] = d1*inv*w[t+256] + b[t+256];
    yr[t+512] = d2*inv*w[t+512] + b[t+512];
}

// ---------------- row softmax (cols = PER*256) ----------------
template<int PER>
__global__ void softmax_kernel(float* __restrict__ S)
{
    __shared__ float sm[8];
    size_t row = blockIdx.x;
    float* x = S + row * (size_t)(PER*256);
    int t = threadIdx.x;
    float v[PER];
    float mx = -3.0e38f;
    #pragma unroll
    for (int e=0;e<PER;e++){ v[e] = x[t + (e<<8)]; mx = fmaxf(mx, v[e]); }
    #pragma unroll
    for (int o=16;o;o>>=1) mx = fmaxf(mx, __shfl_xor_sync(0xffffffffu, mx, o));
    if ((t&31)==0) sm[t>>5] = mx;
    __syncthreads();
    if (t<32){
        float z = (t<8)? sm[t] : -3.0e38f;
        #pragma unroll
        for (int o=4;o;o>>=1) z = fmaxf(z, __shfl_xor_sync(0xffffffffu, z, o));
        if (t==0) sm[0] = z;
    }
    __syncthreads();
    mx = sm[0];
    __syncthreads();
    float s = 0.f;
    #pragma unroll
    for (int e=0;e<PER;e++){ v[e] = expf(v[e]-mx); s += v[e]; }
    #pragma unroll
    for (int o=16;o;o>>=1) s += __shfl_xor_sync(0xffffffffu, s, o);
    if ((t&31)==0) sm[t>>5] = s;
    __syncthreads();
    if (t<32){
        float z = (t<8)? sm[t] : 0.f;
        #pragma unroll
        for (int o=4;o;o>>=1) z += __shfl_xor_sync(0xffffffffu, z, o);
        if (t==0) sm[0] = z;
    }
    __syncthreads();
    float inv = 1.0f / sm[0];
    #pragma unroll
    for (int e=0;e<PER;e++) x[t + (e<<8)] = v[e]*inv;
}

// ---------------- generic tf32 GEMM 128x128x32, fused epilogue ----------------
// C[M,N] = A[M,K] @ B[K,N]  (+bias, +gelu, +res)   M%128==0, N%128==0, K%32==0
__global__ void __launch_bounds__(256) gemm_kernel(
    const float* __restrict__ A, const float* __restrict__ Bm,
    float* __restrict__ C, const float* __restrict__ bias,
    const float* __restrict__ res, int M, int N, int K, int gelu)
{
    __shared__ float As[128*36];
    __shared__ float Bs[32*132];
    int tid = threadIdx.x;
    int bm = blockIdx.y << 7, bn = blockIdx.x << 7;
    int warp = tid >> 5, lane = tid & 31;
    int wm = warp & 3, wn = warp >> 2;

    wmma::fragment<wmma::accumulator,16,16,8,float> acc[2][4];
    #pragma unroll
    for (int i=0;i<2;i++)
        #pragma unroll
        for (int j=0;j<4;j++) wmma::fill_fragment(acc[i][j], 0.0f);

    const float* Ab = A + (size_t)bm * K;
    const float* Bb = Bm + bn;
    int KT = K >> 5;

    float4 ar[4], br[4];
    #pragma unroll
    for (int p=0;p<4;p++){ int l=tid+(p<<8); int r=l>>3; int c=(l&7)<<2;
        ar[p] = *(const float4*)(Ab + (size_t)r*K + c); }
    #pragma unroll
    for (int p=0;p<4;p++){ int l=tid+(p<<8); int r=l>>5; int c=(l&31)<<2;
        br[p] = *(const float4*)(Bb + (size_t)r*N + c); }

    for (int kt=0; kt<KT; kt++) {
        __syncthreads();
        #pragma unroll
        for (int p=0;p<4;p++){ int l=tid+(p<<8); int r=l>>3; int c=(l&7)<<2;
            *(float4*)(As + r*36 + c) = ar[p]; }
        #pragma unroll
        for (int p=0;p<4;p++){ int l=tid+(p<<8); int r=l>>5; int c=(l&31)<<2;
            *(float4*)(Bs + r*132 + c) = br[p]; }
        __syncthreads();
        if (kt+1 < KT) {
            int k0 = (kt+1) << 5;
            #pragma unroll
            for (int p=0;p<4;p++){ int l=tid+(p<<8); int r=l>>3; int c=(l&7)<<2;
                ar[p] = *(const float4*)(Ab + (size_t)r*K + k0 + c); }
            #pragma unroll
            for (int p=0;p<4;p++){ int l=tid+(p<<8); int r=l>>5; int c=(l&31)<<2;
                br[p] = *(const float4*)(Bb + (size_t)(k0+r)*N + c); }
        }
        #pragma unroll
        for (int ks=0; ks<4; ks++) {
            wmma::fragment<wmma::matrix_a,16,16,8,wmma::precision::tf32,wmma::row_major> af[2];
            wmma::fragment<wmma::matrix_b,16,16,8,wmma::precision::tf32,wmma::row_major> bf[4];
            #pragma unroll
            for (int i=0;i<2;i++){
                wmma::load_matrix_sync(af[i], As + (wm*32 + i*16)*36 + ks*8, 36);
                #pragma unroll
                for (int e=0;e<af[i].num_elements;e++) af[i].x[e] = wmma::__float_to_tf32(af[i].x[e]);
            }
            #pragma unroll
            for (int j=0;j<4;j++){
                wmma::load_matrix_sync(bf[j], Bs + (ks*8)*132 + wn*64 + j*16, 132);
                #pragma unroll
                for (int e=0;e<bf[j].num_elements;e++) bf[j].x[e] = wmma::__float_to_tf32(bf[j].x[e]);
            }
            #pragma unroll
            for (int i=0;i<2;i++)
                #pragma unroll
                for (int j=0;j<4;j++)
                    wmma::mma_sync(acc[i][j], af[i], bf[j], acc[i][j]);
        }
    }

    // epilogue via per-warp smem staging (reuse As)
    __syncthreads();
    float* scratch = As + warp*256;
    #pragma unroll
    for (int i=0;i<2;i++)
        #pragma unroll
        for (int j=0;j<4;j++) {
            wmma::store_matrix_sync(scratch, acc[i][j], 16, wmma::mem_row_major);
            __syncwarp();
            int r0 = bm + wm*32 + i*16;
            int c0 = bn + wn*64 + j*16;
            #pragma unroll
            for (int e=0;e<8;e++) {
                int el = (e<<5) + lane;
                int rr = el >> 4, cc = el & 15;
                float v = scratch[el];
                int gc = c0 + cc;
                if (bias) v += bias[gc];
                if (gelu) v = 0.5f*v*(1.0f + erff(v*0.70710678118654752f));
                size_t o = (size_t)(r0+rr)*N + gc;
                if (res) v += res[o];
                C[o] = v;
            }
            __syncwarp();
        }
}

// ---------------- batched scores: S[bh,i,j] = scale * Q_h[i,:] . K_h[j,:] ----------------
__global__ void __launch_bounds__(256) scores_kernel(
    const float* __restrict__ Q, const float* __restrict__ KV,
    float* __restrict__ S, int ctx)
{
    __shared__ float Qs[128*36];
    __shared__ float Ks[128*36];
    int bh = blockIdx.z; int b = bh / CNH, h = bh % CNH;
    const float* Qb = Q  + (size_t)b*CNQ*CD       + h*CHD;   // row stride CD
    const float* Kb = KV + (size_t)b*ctx*(2*CD)   + h*CHD;   // row stride 768
    int i0 = blockIdx.y << 7, j0 = blockIdx.x << 7;
    int tid = threadIdx.x, warp = tid>>5;
    int wm = warp & 3, wn = warp >> 2;

    wmma::fragment<wmma::accumulator,16,16,8,float> acc[2][4];
    #pragma unroll
    for (int i=0;i<2;i++)
        #pragma unroll
        for (int j=0;j<4;j++) wmma::fill_fragment(acc[i][j], 0.0f);

    #pragma unroll
    for (int kt=0; kt<2; kt++) {
        if (kt) __syncthreads();
        #pragma unroll
        for (int p=0;p<4;p++){
            int l = tid + (p<<8); int r = l>>3; int c = (l&7)<<2;
            *(float4*)(Qs + r*36 + c) = *(const float4*)(Qb + (size_t)(i0+r)*CD     + kt*32 + c);
            *(float4*)(Ks + r*36 + c) = *(const float4*)(Kb + (size_t)(j0+r)*(2*CD) + kt*32 + c);
        }
        __syncthreads();
        #pragma unroll
        for (int ks=0; ks<4; ks++) {
            wmma::fragment<wmma::matrix_a,16,16,8,wmma::precision::tf32,wmma::row_major> af[2];
            wmma::fragment<wmma::matrix_b,16,16,8,wmma::precision::tf32,wmma::col_major> bf[4];
            #pragma unroll
            for (int i=0;i<2;i++){
                wmma::load_matrix_sync(af[i], Qs + (wm*32 + i*16)*36 + ks*8, 36);
                #pragma unroll
                for (int e=0;e<af[i].num_elements;e++) af[i].x[e] = wmma::__float_to_tf32(af[i].x[e]);
            }
            #pragma unroll
            for (int j=0;j<4;j++){
                wmma::load_matrix_sync(bf[j], Ks + (wn*64 + j*16)*36 + ks*8, 36);
                #pragma unroll
                for (int e=0;e<bf[j].num_elements;e++) bf[j].x[e] = wmma::__float_to_tf32(bf[j].x[e]);
            }
            #pragma unroll
            for (int i=0;i<2;i++)
                #pragma unroll
                for (int j=0;j<4;j++)
                    wmma::mma_sync(acc[i][j], af[i], bf[j], acc[i][j]);
        }
    }

    const float scale = 0.125f;  // 64^-0.5
    float* Sb = S + (size_t)bh * CNQ * ctx;
    #pragma unroll
    for (int i=0;i<2;i++)
        #pragma unroll
        for (int j=0;j<4;j++){
            #pragma unroll
            for (int e=0;e<acc[i][j].num_elements;e++) acc[i][j].x[e] *= scale;
            wmma::store_matrix_sync(Sb + (size_t)(i0 + wm*32 + i*16)*ctx + j0 + wn*64 + j*16,
                                    acc[i][j], ctx, wmma::mem_row_major);
        }
}

// ---------------- batched PV: AO[b,i,h*64+d] = sum_j P[bh,i,j] * V_h[j,d] ----------------
__global__ void __launch_bounds__(256) pv_kernel(
    const float* __restrict__ P, const float* __restrict__ KV,
    float* __restrict__ AO, int ctx)
{
    __shared__ float Ps[128*36];
    __shared__ float Vs[32*68];
    int bh = blockIdx.y; int b = bh / CNH, h = bh % CNH;
    int i0 = blockIdx.x << 7;
    const float* Pb = P  + (size_t)bh*CNQ*ctx + (size_t)i0*ctx;
    const float* Vb = KV + (size_t)b*ctx*(2*CD) + CD + h*CHD;
    int tid = threadIdx.x, warp = tid >> 5;

    wmma::fragment<wmma::accumulator,16,16,8,float> acc[4];
    #pragma unroll
    for (int j=0;j<4;j++) wmma::fill_fragment(acc[j], 0.0f);

    int KT = ctx >> 5;
    float4 pr[4], vr[2];
    #pragma unroll
    for (int p=0;p<4;p++){ int l=tid+(p<<8); int r=l>>3; int c=(l&7)<<2;
        pr[p] = *(const float4*)(Pb + (size_t)r*ctx + c); }
    #pragma unroll
    for (int p=0;p<2;p++){ int l=tid+(p<<8); int r=l>>4; int c=(l&15)<<2;
        vr[p] = *(const float4*)(Vb + (size_t)r*(2*CD) + c); }

    for (int kt=0; kt<KT; kt++) {
        __syncthreads();
        #pragma unroll
        for (int p=0;p<4;p++){ int l=tid+(p<<8); int r=l>>3; int c=(l&7)<<2;
            *(float4*)(Ps + r*36 + c) = pr[p]; }
        #pragma unroll
        for (int p=0;p<2;p++){ int l=tid+(p<<8); int r=l>>4; int c=(l&15)<<2;
            *(float4*)(Vs + r*68 + c) = vr[p]; }
        __syncthreads();
        if (kt+1 < KT) {
            int k0 = (kt+1) << 5;
            #pragma unroll
            for (int p=0;p<4;p++){ int l=tid+(p<<8); int r=l>>3; int c=(l&7)<<2;
                pr[p] = *(const float4*)(Pb + (size_t)r*ctx + k0 + c); }
            #pragma unroll
            for (int p=0;p<2;p++){ int l=tid+(p<<8); int r=l>>4; int c=(l&15)<<2;
                vr[p] = *(const float4*)(Vb + (size_t)(k0+r)*(2*CD) + c); }
        }
        #pragma unroll
        for (int ks=0; ks<4; ks++) {
            wmma::fragment<wmma::matrix_a,16,16,8,wmma::precision::tf32,wmma::row_major> af;
            wmma::fragment<wmma::matrix_b,16,16,8,wmma::precision::tf32,wmma::row_major> bf[4];
            wmma::load_matrix_sync(af, Ps + (warp*16)*36 + ks*8, 36);
            #pragma unroll
            for (int e=0;e<af.num_elements;e++) af.x[e] = wmma::__float_to_tf32(af.x[e]);
            #pragma unroll
            for (int j=0;j<4;j++){
                wmma::load_matrix_sync(bf[j], Vs + (ks*8)*68 + j*16, 68);
                #pragma unroll
                for (int e=0;e<bf[j].num_elements;e++) bf[j].x[e] = wmma::__float_to_tf32(bf[j].x[e]);
                wmma::mma_sync(acc[j], af, bf[j], acc[j]);
            }
        }
    }

    float* Ob = AO + (size_t)((size_t)b*CNQ + i0 + warp*16)*CD + h*CHD;
    #pragma unroll
    for (int j=0;j<4;j++)
        wmma::store_matrix_sync(Ob + j*16, acc[j], CD, wmma::mem_row_major);
}

// ---------------- driver ----------------
extern "C" void kernel_launch(void* const* d_in, const int* in_sizes, int n_in,
                              void* d_out, int out_size)
{
    const float* query   = (const float*)d_in[0];
    const float* context = (const float*)d_in[1];
    const float* ln_w    = (const float*)d_in[2];
    const float* ln_b    = (const float*)d_in[3];
    const float* a1_wq   = (const float*)d_in[4];
    const float* a1_wkv  = (const float*)d_in[5];
    const float* a1_wp   = (const float*)d_in[6];
    const float* a1_bp   = (const float*)d_in[7];
    const float* m1_w1   = (const float*)d_in[8];
    const float* m1_b1   = (const float*)d_in[9];
    const float* m1_w2   = (const float*)d_in[10];
    const float* m1_b2   = (const float*)d_in[11];
    const float* a2_wq   = (const float*)d_in[12];
    const float* a2_wkv  = (const float*)d_in[13];
    const float* a2_wp   = (const float*)d_in[14];
    const float* a2_bp   = (const float*)d_in[15];
    const float* m2_w1   = (const float*)d_in[16];
    const float* m2_b1   = (const float*)d_in[17];
    const float* m2_w2   = (const float*)d_in[18];
    const float* m2_b2   = (const float*)d_in[19];

    float* out   = (float*)d_out;
    float* out_c = out;                       // first half: c
    float* out_q = out + (size_t)CRQ * CE;    // second half: ln(query)

    float *cn, *Qp, *KVp, *Sp, *AOp, *cp, *tp, *Hp;
    cudaGetSymbolAddress((void**)&cn,  g_cn);
    cudaGetSymbolAddress((void**)&Qp,  g_Q);
    cudaGetSymbolAddress((void**)&KVp, g_KV);
    cudaGetSymbolAddress((void**)&Sp,  g_S);
    cudaGetSymbolAddress((void**)&AOp, g_AO);
    cudaGetSymbolAddress((void**)&cp,  g_c);
    cudaGetSymbolAddress((void**)&tp,  g_t);
    cudaGetSymbolAddress((void**)&Hp,  g_H);

    // q = LN(query) -> out_q ; cn = LN(context)
    ln_kernel<<<CRQ, 256>>>(query,   ln_w, ln_b, out_q);
    ln_kernel<<<CRC, 256>>>(context, ln_w, ln_b, cn);

    // ---- block 1: cross-attention over context (m=2048) ----
    gemm_kernel<<<dim3(3, 64),  256>>>(out_q, a1_wq,  Qp,  nullptr, nullptr, CRQ, CD,   CE, 0);
    gemm_kernel<<<dim3(6, 128), 256>>>(cn,    a1_wkv, KVp, nullptr, nullptr, CRC, 2*CD, CE, 0);
    scores_kernel<<<dim3(16, 8, 48), 256>>>(Qp, KVp, Sp, CNC);
    softmax_kernel<8><<<CB*CNH*CNQ, 256>>>(Sp);
    pv_kernel<<<dim3(8, 48), 256>>>(Sp, KVp, AOp, CNC);
    gemm_kernel<<<dim3(6, 64), 256>>>(AOp, a1_wp, cp, a1_bp, nullptr, CRQ, CE, CD, 0);

    // ---- MLP 1 (with residual) ----
    ln_kernel<<<CRQ, 256>>>(cp, ln_w, ln_b, tp);
    gemm_kernel<<<dim3(24, 64), 256>>>(tp, m1_w1, Hp, m1_b1, nullptr, CRQ, CHID, CE,   1);
    gemm_kernel<<<dim3(6, 64),  256>>>(Hp, m1_w2, cp, m1_b2, cp,      CRQ, CE,   CHID, 0);

    // ---- block 2: cross-attention over c (m=1024), residual ----
    ln_kernel<<<CRQ, 256>>>(cp, ln_w, ln_b, tp);
    gemm_kernel<<<dim3(3, 64), 256>>>(out_q, a2_wq,  Qp,  nullptr, nullptr, CRQ, CD,   CE, 0);
    gemm_kernel<<<dim3(6, 64), 256>>>(tp,    a2_wkv, KVp, nullptr, nullptr, CRQ, 2*CD, CE, 0);
    scores_kernel<<<dim3(8, 8, 48), 256>>>(Qp, KVp, Sp, CNQ);
    softmax_kernel<4><<<CB*CNH*CNQ, 256>>>(Sp);
    pv_kernel<<<dim3(8, 48), 256>>>(Sp, KVp, AOp, CNQ);
    gemm_kernel<<<dim3(6, 64), 256>>>(AOp, a2_wp, cp, a2_bp, cp, CRQ, CE, CD, 0);

    // ---- MLP 2 (with residual), final write straight into d_out ----
    ln_kernel<<<CRQ, 256>>>(cp, ln_w, ln_b, tp);
    gemm_kernel<<<dim3(24, 64), 256>>>(tp, m2_w1, Hp,    m2_b1, nullptr, CRQ, CHID, CE,   1);
    gemm_kernel<<<dim3(6, 64),  256>>>(Hp, m2_w2, out_c, m2_b2, cp,      CRQ, CE,   CHID, 0);
}

// round 2
// speedup vs baseline: 1.0130x; 1.0130x over previous
#include <cuda_runtime.h>
#include <mma.h>

using namespace nvcuda;

#define CB   8
#define CNQ  1024
#define CNC  2048
#define CE   768
#define CD   384
#define CNH  6
#define CHD  64
#define CHID 3072
#define CRQ  (CB*CNQ)   /* 8192  */
#define CRC  (CB*CNC)   /* 16384 */

// ---------------- scratch (no cudaMalloc allowed) ----------------
__device__ float g_cn[(size_t)CRC*CE];
__device__ float g_Q [(size_t)CRQ*CD];
__device__ float g_KV[(size_t)CRC*2*CD];
__device__ float g_S [(size_t)CB*CNH*CNQ*CNC];
__device__ float g_AO[(size_t)CRQ*CD];
__device__ float g_c [(size_t)CRQ*CE];
__device__ float g_t [(size_t)CRQ*CE];
__device__ float g_H [(size_t)CRQ*CHID];

// ---------------- cp.async helpers ----------------
__device__ __forceinline__ void cp16(void* smem, const void* gmem) {
    unsigned s = (unsigned)__cvta_generic_to_shared(smem);
    asm volatile("cp.async.ca.shared.global [%0], [%1], 16;\n" :: "r"(s), "l"(gmem));
}
__device__ __forceinline__ void cp_commit() {
    asm volatile("cp.async.commit_group;\n");
}
template<int N>
__device__ __forceinline__ void cp_wait() {
    asm volatile("cp.async.wait_group %0;\n" :: "n"(N));
}

// ---------------- LayerNorm: one block per 768-wide row ----------------
__global__ void ln_kernel(const float* __restrict__ x, const float* __restrict__ w,
                          const float* __restrict__ b, float* __restrict__ y)
{
    __shared__ float sm[8];
    size_t row = blockIdx.x;
    const float* xr = x + row * CE;
    float* yr = y + row * CE;
    int t = threadIdx.x;
    float v0 = xr[t], v1 = xr[t+256], v2 = xr[t+512];

    float s = v0 + v1 + v2;
    #pragma unroll
    for (int o=16;o;o>>=1) s += __shfl_xor_sync(0xffffffffu, s, o);
    if ((t&31)==0) sm[t>>5] = s;
    __syncthreads();
    if (t < 32) {
        float z = (t<8) ? sm[t] : 0.f;
        #pragma unroll
        for (int o=4;o;o>>=1) z += __shfl_xor_sync(0xffffffffu, z, o);
        if (t==0) sm[0] = z;
    }
    __syncthreads();
    float mean = sm[0] * (1.0f/CE);
    __syncthreads();

    float d0 = v0-mean, d1 = v1-mean, d2 = v2-mean;
    float q = d0*d0 + d1*d1 + d2*d2;
    #pragma unroll
    for (int o=16;o;o>>=1) q += __shfl_xor_sync(0xffffffffu, q, o);
    if ((t&31)==0) sm[t>>5] = q;
    __syncthreads();
    if (t < 32) {
        float z = (t<8) ? sm[t] : 0.f;
        #pragma unroll
        for (int o=4;o;o>>=1) z += __shfl_xor_sync(0xffffffffu, z, o);
        if (t==0) sm[0] = z;
    }
    __syncthreads();
    float inv = rsqrtf(sm[0]*(1.0f/CE) + 1e-5f);

    yr[t]     = d0*inv*w[t]     + b[t];
    yr[t+256] = d1*inv*w[t+256] + b[t+256];
    yr[t+512] = d2*inv*w[t+512] + b[t+512];
}

// ---------------- row softmax (cols = PER*256) ----------------
template<int PER>
__global__ void softmax_kernel(float* __restrict__ S)
{
    __shared__ float sm[8];
    size_t row = blockIdx.x;
    float* x = S + row * (size_t)(PER*256);
    int t = threadIdx.x;
    float v[PER];
    float mx = -3.0e38f;
    #pragma unroll
    for (int e=0;e<PER;e++){ v[e] = x[t + (e<<8)]; mx = fmaxf(mx, v[e]); }
    #pragma unroll
    for (int o=16;o;o>>=1) mx = fmaxf(mx, __shfl_xor_sync(0xffffffffu, mx, o));
    if ((t&31)==0) sm[t>>5] = mx;
    __syncthreads();
    if (t<32){
        float z = (t<8)? sm[t] : -3.0e38f;
        #pragma unroll
        for (int o=4;o;o>>=1) z = fmaxf(z, __shfl_xor_sync(0xffffffffu, z, o));
        if (t==0) sm[0] = z;
    }
    __syncthreads();
    mx = sm[0];
    __syncthreads();
    float s = 0.f;
    #pragma unroll
    for (int e=0;e<PER;e++){ v[e] = expf(v[e]-mx); s += v[e]; }
    #pragma unroll
    for (int o=16;o;o>>=1) s += __shfl_xor_sync(0xffffffffu, s, o);
    if ((t&31)==0) sm[t>>5] = s;
    __syncthreads();
    if (t<32){
        float z = (t<8)? sm[t] : 0.f;
        #pragma unroll
        for (int o=4;o;o>>=1) z += __shfl_xor_sync(0xffffffffu, z, o);
        if (t==0) sm[0] = z;
    }
    __syncthreads();
    float inv = 1.0f / sm[0];
    #pragma unroll
    for (int e=0;e<PER;e++) x[t + (e<<8)] = v[e]*inv;
}

// ---------------- generic tf32 GEMM 128x128x32, cp.async 3-stage, fused epilogue ----
// C[M,N] = A[M,K] @ B[K,N]  (+bias, +gelu, +res)   M%128==0, N%128==0, K%32==0
__global__ void __launch_bounds__(256, 2) gemm_kernel(
    const float* __restrict__ A, const float* __restrict__ Bm,
    float* __restrict__ C, const float* __restrict__ bias,
    const float* __restrict__ res, int M, int N, int K, int gelu)
{
    __shared__ float As[3][128*36];
    __shared__ float Bs[3][32*132];
    int tid = threadIdx.x;
    int bm = blockIdx.y << 7, bn = blockIdx.x << 7;
    int warp = tid >> 5, lane = tid & 31;
    int wm = warp & 3, wn = warp >> 2;

    wmma::fragment<wmma::accumulator,16,16,8,float> acc[2][4];
    #pragma unroll
    for (int i=0;i<2;i++)
        #pragma unroll
        for (int j=0;j<4;j++) wmma::fill_fragment(acc[i][j], 0.0f);

    const float* Ab = A + (size_t)bm * K;
    const float* Bb = Bm + bn;
    int KT = K >> 5;

    // per-thread fixed load coordinates
    // A: 4 chunks, each 16B: row = l>>3, col = (l&7)*4
    // B: 4 chunks, each 16B: row = l>>5, col = (l&31)*4
    int ar[4], ac[4], asoff[4];
    int br_[4], bc[4], bsoff[4];
    #pragma unroll
    for (int p=0;p<4;p++){
        int l = tid + (p<<8);
        ar[p] = l>>3;  ac[p] = (l&7)<<2;  asoff[p] = ar[p]*36  + ac[p];
        br_[p]= l>>5;  bc[p] = (l&31)<<2; bsoff[p] = br_[p]*132 + bc[p];
    }

    auto issue = [&](int s, int kt){
        int k0 = kt << 5;
        #pragma unroll
        for (int p=0;p<4;p++)
            cp16(&As[s][asoff[p]], Ab + (size_t)ar[p]*K + k0 + ac[p]);
        #pragma unroll
        for (int p=0;p<4;p++)
            cp16(&Bs[s][bsoff[p]], Bb + (size_t)(k0 + br_[p])*N + bc[p]);
        cp_commit();
    };

    // prologue: tiles 0 and 1
    issue(0, 0);
    issue(1, (KT > 1) ? 1 : 0);

    for (int kt = 0; kt < KT; kt++) {
        // keep pipeline full (clamped tile index at tail; redundant but correct)
        int nt = kt + 2; if (nt > KT-1) nt = KT-1;
        issue((kt+2)%3, nt);
        cp_wait<2>();            // group for tile kt is 3rd-newest -> complete
        __syncthreads();

        const float* Asb = As[kt%3];
        const float* Bsb = Bs[kt%3];
        #pragma unroll
        for (int ks=0; ks<4; ks++) {
            wmma::fragment<wmma::matrix_a,16,16,8,wmma::precision::tf32,wmma::row_major> af[2];
            wmma::fragment<wmma::matrix_b,16,16,8,wmma::precision::tf32,wmma::row_major> bf[4];
            #pragma unroll
            for (int i=0;i<2;i++){
                wmma::load_matrix_sync(af[i], Asb + (wm*32 + i*16)*36 + ks*8, 36);
                #pragma unroll
                for (int e=0;e<af[i].num_elements;e++) af[i].x[e] = wmma::__float_to_tf32(af[i].x[e]);
            }
            #pragma unroll
            for (int j=0;j<4;j++){
                wmma::load_matrix_sync(bf[j], Bsb + (ks*8)*132 + wn*64 + j*16, 132);
                #pragma unroll
                for (int e=0;e<bf[j].num_elements;e++) bf[j].x[e] = wmma::__float_to_tf32(bf[j].x[e]);
            }
            #pragma unroll
            for (int i=0;i<2;i++)
                #pragma unroll
                for (int j=0;j<4;j++)
                    wmma::mma_sync(acc[i][j], af[i], bf[j], acc[i][j]);
        }
        __syncthreads();   // all warps done with buffer kt%3 before it is refilled
    }

    // epilogue via per-warp smem staging (reuse As[0])
    __syncthreads();
    float* scratch = (float*)As[0] + warp*256;
    #pragma unroll
    for (int i=0;i<2;i++)
        #pragma unroll
        for (int j=0;j<4;j++) {
            wmma::store_matrix_sync(scratch, acc[i][j], 16, wmma::mem_row_major);
            __syncwarp();
            int r0 = bm + wm*32 + i*16;
            int c0 = bn + wn*64 + j*16;
            #pragma unroll
            for (int e=0;e<8;e++) {
                int el = (e<<5) + lane;
                int rr = el >> 4, cc = el & 15;
                float v = scratch[el];
                int gc = c0 + cc;
                if (bias) v += bias[gc];
                if (gelu) v = 0.5f*v*(1.0f + erff(v*0.70710678118654752f));
                size_t o = (size_t)(r0+rr)*N + gc;
                if (res) v += res[o];
                C[o] = v;
            }
            __syncwarp();
        }
}

// ---------------- batched scores: S[bh,i,j] = scale * Q_h[i,:] . K_h[j,:] ----------------
__global__ void __launch_bounds__(256) scores_kernel(
    const float* __restrict__ Q, const float* __restrict__ KV,
    float* __restrict__ S, int ctx)
{
    __shared__ float Qs[128*36];
    __shared__ float Ks[128*36];
    int bh = blockIdx.z; int b = bh / CNH, h = bh % CNH;
    const float* Qb = Q  + (size_t)b*CNQ*CD       + h*CHD;   // row stride CD
    const float* Kb = KV + (size_t)b*ctx*(2*CD)   + h*CHD;   // row stride 768
    int i0 = blockIdx.y << 7, j0 = blockIdx.x << 7;
    int tid = threadIdx.x, warp = tid>>5;
    int wm = warp & 3, wn = warp >> 2;

    wmma::fragment<wmma::accumulator,16,16,8,float> acc[2][4];
    #pragma unroll
    for (int i=0;i<2;i++)
        #pragma unroll
        for (int j=0;j<4;j++) wmma::fill_fragment(acc[i][j], 0.0f);

    #pragma unroll
    for (int kt=0; kt<2; kt++) {
        if (kt) __syncthreads();
        #pragma unroll
        for (int p=0;p<4;p++){
            int l = tid + (p<<8); int r = l>>3; int c = (l&7)<<2;
            *(float4*)(Qs + r*36 + c) = *(const float4*)(Qb + (size_t)(i0+r)*CD     + kt*32 + c);
            *(float4*)(Ks + r*36 + c) = *(const float4*)(Kb + (size_t)(j0+r)*(2*CD) + kt*32 + c);
        }
        __syncthreads();
        #pragma unroll
        for (int ks=0; ks<4; ks++) {
            wmma::fragment<wmma::matrix_a,16,16,8,wmma::precision::tf32,wmma::row_major> af[2];
            wmma::fragment<wmma::matrix_b,16,16,8,wmma::precision::tf32,wmma::col_major> bf[4];
            #pragma unroll
            for (int i=0;i<2;i++){
                wmma::load_matrix_sync(af[i], Qs + (wm*32 + i*16)*36 + ks*8, 36);
                #pragma unroll
                for (int e=0;e<af[i].num_elements;e++) af[i].x[e] = wmma::__float_to_tf32(af[i].x[e]);
            }
            #pragma unroll
            for (int j=0;j<4;j++){
                wmma::load_matrix_sync(bf[j], Ks + (wn*64 + j*16)*36 + ks*8, 36);
                #pragma unroll
                for (int e=0;e<bf[j].num_elements;e++) bf[j].x[e] = wmma::__float_to_tf32(bf[j].x[e]);
            }
            #pragma unroll
            for (int i=0;i<2;i++)
                #pragma unroll
                for (int j=0;j<4;j++)
                    wmma::mma_sync(acc[i][j], af[i], bf[j], acc[i][j]);
        }
    }

    const float scale = 0.125f;  // 64^-0.5
    float* Sb = S + (size_t)bh * CNQ * ctx;
    #pragma unroll
    for (int i=0;i<2;i++)
        #pragma unroll
        for (int j=0;j<4;j++){
            #pragma unroll
            for (int e=0;e<acc[i][j].num_elements;e++) acc[i][j].x[e] *= scale;
            wmma::store_matrix_sync(Sb + (size_t)(i0 + wm*32 + i*16)*ctx + j0 + wn*64 + j*16,
                                    acc[i][j], ctx, wmma::mem_row_major);
        }
}

// ---------------- batched PV: AO[b,i,h*64+d] = sum_j P[bh,i,j] * V_h[j,d] ----------------
__global__ void __launch_bounds__(256) pv_kernel(
    const float* __restrict__ P, const float* __restrict__ KV,
    float* __restrict__ AO, int ctx)
{
    __shared__ float Ps[128*36];
    __shared__ float Vs[32*68];
    int bh = blockIdx.y; int b = bh / CNH, h = bh % CNH;
    int i0 = blockIdx.x << 7;
    const float* Pb = P  + (size_t)bh*CNQ*ctx + (size_t)i0*ctx;
    const float* Vb = KV + (size_t)b*ctx*(2*CD) + CD + h*CHD;
    int tid = threadIdx.x, warp = tid >> 5;

    wmma::fragment<wmma::accumulator,16,16,8,float> acc[4];
    #pragma unroll
    for (int j=0;j<4;j++) wmma::fill_fragment(acc[j], 0.0f);

    int KT = ctx >> 5;
    float4 pr[4], vr[2];
    #pragma unroll
    for (int p=0;p<4;p++){ int l=tid+(p<<8); int r=l>>3; int c=(l&7)<<2;
        pr[p] = *(const float4*)(Pb + (size_t)r*ctx + c); }
    #pragma unroll
    for (int p=0;p<2;p++){ int l=tid+(p<<8); int r=l>>4; int c=(l&15)<<2;
        vr[p] = *(const float4*)(Vb + (size_t)r*(2*CD) + c); }

    for (int kt=0; kt<KT; kt++) {
        __syncthreads();
        #pragma unroll
        for (int p=0;p<4;p++){ int l=tid+(p<<8); int r=l>>3; int c=(l&7)<<2;
            *(float4*)(Ps + r*36 + c) = pr[p]; }
        #pragma unroll
        for (int p=0;p<2;p++){ int l=tid+(p<<8); int r=l>>4; int c=(l&15)<<2;
            *(float4*)(Vs + r*68 + c) = vr[p]; }
        __syncthreads();
        if (kt+1 < KT) {
            int k0 = (kt+1) << 5;
            #pragma unroll
            for (int p=0;p<4;p++){ int l=tid+(p<<8); int r=l>>3; int c=(l&7)<<2;
                pr[p] = *(const float4*)(Pb + (size_t)r*ctx + k0 + c); }
            #pragma unroll
            for (int p=0;p<2;p++){ int l=tid+(p<<8); int r=l>>4; int c=(l&15)<<2;
                vr[p] = *(const float4*)(Vb + (size_t)(k0+r)*(2*CD) + c); }
        }
        #pragma unroll
        for (int ks=0; ks<4; ks++) {
            wmma::fragment<wmma::matrix_a,16,16,8,wmma::precision::tf32,wmma::row_major> af;
            wmma::fragment<wmma::matrix_b,16,16,8,wmma::precision::tf32,wmma::row_major> bf[4];
            wmma::load_matrix_sync(af, Ps + (warp*16)*36 + ks*8, 36);
            #pragma unroll
            for (int e=0;e<af.num_elements;e++) af.x[e] = wmma::__float_to_tf32(af.x[e]);
            #pragma unroll
            for (int j=0;j<4;j++){
                wmma::load_matrix_sync(bf[j], Vs + (ks*8)*68 + j*16, 68);
                #pragma unroll
                for (int e=0;e<bf[j].num_elements;e++) bf[j].x[e] = wmma::__float_to_tf32(bf[j].x[e]);
                wmma::mma_sync(acc[j], af, bf[j], acc[j]);
            }
        }
    }

    float* Ob = AO + (size_t)((size_t)b*CNQ + i0 + warp*16)*CD + h*CHD;
    #pragma unroll
    for (int j=0;j<4;j++)
        wmma::store_matrix_sync(Ob + j*16, acc[j], CD, wmma::mem_row_major);
}

// ---------------- driver ----------------
extern "C" void kernel_launch(void* const* d_in, const int* in_sizes, int n_in,
                              void* d_out, int out_size)
{
    const float* query   = (const float*)d_in[0];
    const float* context = (const float*)d_in[1];
    const float* ln_w    = (const float*)d_in[2];
    const float* ln_b    = (const float*)d_in[3];
    const float* a1_wq   = (const float*)d_in[4];
    const float* a1_wkv  = (const float*)d_in[5];
    const float* a1_wp   = (const float*)d_in[6];
    const float* a1_bp   = (const float*)d_in[7];
    const float* m1_w1   = (const float*)d_in[8];
    const float* m1_b1   = (const float*)d_in[9];
    const float* m1_w2   = (const float*)d_in[10];
    const float* m1_b2   = (const float*)d_in[11];
    const float* a2_wq   = (const float*)d_in[12];
    const float* a2_wkv  = (const float*)d_in[13];
    const float* a2_wp   = (const float*)d_in[14];
    const float* a2_bp   = (const float*)d_in[15];
    const float* m2_w1   = (const float*)d_in[16];
    const float* m2_b1   = (const float*)d_in[17];
    const float* m2_w2   = (const float*)d_in[18];
    const float* m2_b2   = (const float*)d_in[19];

    float* out   = (float*)d_out;
    float* out_c = out;                       // first half: c
    float* out_q = out + (size_t)CRQ * CE;    // second half: ln(query)

    float *cn, *Qp, *KVp, *Sp, *AOp, *cp, *tp, *Hp;
    cudaGetSymbolAddress((void**)&cn,  g_cn);
    cudaGetSymbolAddress((void**)&Qp,  g_Q);
    cudaGetSymbolAddress((void**)&KVp, g_KV);
    cudaGetSymbolAddress((void**)&Sp,  g_S);
    cudaGetSymbolAddress((void**)&AOp, g_AO);
    cudaGetSymbolAddress((void**)&cp,  g_c);
    cudaGetSymbolAddress((void**)&tp,  g_t);
    cudaGetSymbolAddress((void**)&Hp,  g_H);

    // q = LN(query) -> out_q ; cn = LN(context)
    ln_kernel<<<CRQ, 256>>>(query,   ln_w, ln_b, out_q);
    ln_kernel<<<CRC, 256>>>(context, ln_w, ln_b, cn);

    // ---- block 1: cross-attention over context (m=2048) ----
    gemm_kernel<<<dim3(3, 64),  256>>>(out_q, a1_wq,  Qp,  nullptr, nullptr, CRQ, CD,   CE, 0);
    gemm_kernel<<<dim3(6, 128), 256>>>(cn,    a1_wkv, KVp, nullptr, nullptr, CRC, 2*CD, CE, 0);
    scores_kernel<<<dim3(16, 8, 48), 256>>>(Qp, KVp, Sp, CNC);
    softmax_kernel<8><<<CB*CNH*CNQ, 256>>>(Sp);
    pv_kernel<<<dim3(8, 48), 256>>>(Sp, KVp, AOp, CNC);
    gemm_kernel<<<dim3(6, 64), 256>>>(AOp, a1_wp, cp, a1_bp, nullptr, CRQ, CE, CD, 0);

    // ---- MLP 1 (with residual) ----
    ln_kernel<<<CRQ, 256>>>(cp, ln_w, ln_b, tp);
    gemm_kernel<<<dim3(24, 64), 256>>>(tp, m1_w1, Hp, m1_b1, nullptr, CRQ, CHID, CE,   1);
    gemm_kernel<<<dim3(6, 64),  256>>>(Hp, m1_w2, cp, m1_b2, cp,      CRQ, CE,   CHID, 0);

    // ---- block 2: cross-attention over c (m=1024), residual ----
    ln_kernel<<<CRQ, 256>>>(cp, ln_w, ln_b, tp);
    gemm_kernel<<<dim3(3, 64), 256>>>(out_q, a2_wq,  Qp,  nullptr, nullptr, CRQ, CD,   CE, 0);
    gemm_kernel<<<dim3(6, 64), 256>>>(tp,    a2_wkv, KVp, nullptr, nullptr, CRQ, 2*CD, CE, 0);
    scores_kernel<<<dim3(8, 8, 48), 256>>>(Qp, KVp, Sp, CNQ);
    softmax_kernel<4><<<CB*CNH*CNQ, 256>>>(Sp);
    pv_kernel<<<dim3(8, 48), 256>>>(Sp, KVp, AOp, CNQ);
    gemm_kernel<<<dim3(6, 64), 256>>>(AOp, a2_wp, cp, a2_bp, cp, CRQ, CE, CD, 0);

    // ---- MLP 2 (with residual), final write straight into d_out ----
    ln_kernel<<<CRQ, 256>>>(cp, ln_w, ln_b, tp);
    gemm_kernel<<<dim3(24, 64), 256>>>(tp, m2_w1, Hp,    m2_b1, nullptr, CRQ, CHID, CE,   1);
    gemm_kernel<<<dim3(6, 64),  256>>>(Hp, m2_w2, out_c, m2_b2, cp,      CRQ, CE,   CHID, 0);
}

// round 3
// speedup vs baseline: 1.0605x; 1.0469x over previous
#include <cuda_runtime.h>
#include <mma.h>

using namespace nvcuda;

#define CB   8
#define CNQ  1024
#define CNC  2048
#define CE   768
#define CD   384
#define CNH  6
#define CHD  64
#define CHID 3072
#define CRQ  (CB*CNQ)   /* 8192  */
#define CRC  (CB*CNC)   /* 16384 */

// ---------------- scratch (no cudaMalloc allowed) ----------------
__device__ float g_cn[(size_t)CRC*CE];
__device__ float g_Q [(size_t)CRQ*CD];
__device__ float g_KV[(size_t)CRC*2*CD];
__device__ float g_S [(size_t)CB*CNH*CNQ*CNC];
__device__ float g_AO[(size_t)CRQ*CD];
__device__ float g_c [(size_t)CRQ*CE];
__device__ float g_t [(size_t)CRQ*CE];
__device__ float g_tq[(size_t)CRQ*CE];
__device__ float g_H [(size_t)CRQ*CHID];
__device__ float g_W [11796480];   // all weights, tf32-rounded

// ---------------- helpers ----------------
__device__ __forceinline__ float tf32r(float x) {
    asm("cvt.rna.tf32.f32 %0, %1;" : "=f"(x) : "f"(x));
    return x;
}
__device__ __forceinline__ void cp16(void* smem, const void* gmem) {
    unsigned s = (unsigned)__cvta_generic_to_shared(smem);
    asm volatile("cp.async.ca.shared.global [%0], [%1], 16;\n" :: "r"(s), "l"(gmem));
}
__device__ __forceinline__ void cp_commit() {
    asm volatile("cp.async.commit_group;\n");
}
template<int N>
__device__ __forceinline__ void cp_wait() {
    asm volatile("cp.async.wait_group %0;\n" :: "n"(N));
}

// ---------------- weight pre-round ----------------
__global__ void round_kernel(const float* __restrict__ x, float* __restrict__ y, int n)
{
    int i = (blockIdx.x << 8) + threadIdx.x;
    if (i < n) y[i] = tf32r(x[i]);
}

// ---------------- LayerNorm: one block per 768-wide row ----------------
// y  (nullable): exact fp32 output
// y2 (nullable): tf32-rounded output (for GEMM consumption)
__global__ void ln_kernel(const float* __restrict__ x, const float* __restrict__ w,
                          const float* __restrict__ b, float* __restrict__ y,
                          float* __restrict__ y2)
{
    __shared__ float sm[8];
    size_t row = blockIdx.x;
    const float* xr = x + row * CE;
    int t = threadIdx.x;
    float v0 = xr[t], v1 = xr[t+256], v2 = xr[t+512];

    float s = v0 + v1 + v2;
    #pragma unroll
    for (int o=16;o;o>>=1) s += __shfl_xor_sync(0xffffffffu, s, o);
    if ((t&31)==0) sm[t>>5] = s;
    __syncthreads();
    if (t < 32) {
        float z = (t<8) ? sm[t] : 0.f;
        #pragma unroll
        for (int o=4;o;o>>=1) z += __shfl_xor_sync(0xffffffffu, z, o);
        if (t==0) sm[0] = z;
    }
    __syncthreads();
    float mean = sm[0] * (1.0f/CE);
    __syncthreads();

    float d0 = v0-mean, d1 = v1-mean, d2 = v2-mean;
    float q = d0*d0 + d1*d1 + d2*d2;
    #pragma unroll
    for (int o=16;o;o>>=1) q += __shfl_xor_sync(0xffffffffu, q, o);
    if ((t&31)==0) sm[t>>5] = q;
    __syncthreads();
    if (t < 32) {
        float z = (t<8) ? sm[t] : 0.f;
        #pragma unroll
        for (int o=4;o;o>>=1) z += __shfl_xor_sync(0xffffffffu, z, o);
        if (t==0) sm[0] = z;
    }
    __syncthreads();
    float inv = rsqrtf(sm[0]*(1.0f/CE) + 1e-5f);

    float r0 = d0*inv*w[t]     + b[t];
    float r1 = d1*inv*w[t+256] + b[t+256];
    float r2 = d2*inv*w[t+512] + b[t+512];
    if (y)  { float* yr = y + row*CE;
        yr[t] = r0; yr[t+256] = r1; yr[t+512] = r2; }
    if (y2) { float* yr = y2 + row*CE;
        yr[t] = tf32r(r0); yr[t+256] = tf32r(r1); yr[t+512] = tf32r(r2); }
}

// ---------------- row softmax (cols = PER*256), tf32-rounded output ----------------
template<int PER>
__global__ void softmax_kernel(float* __restrict__ S)
{
    __shared__ float sm[8];
    size_t row = blockIdx.x;
    float* x = S + row * (size_t)(PER*256);
    int t = threadIdx.x;
    float v[PER];
    float mx = -3.0e38f;
    #pragma unroll
    for (int e=0;e<PER;e++){ v[e] = x[t + (e<<8)]; mx = fmaxf(mx, v[e]); }
    #pragma unroll
    for (int o=16;o;o>>=1) mx = fmaxf(mx, __shfl_xor_sync(0xffffffffu, mx, o));
    if ((t&31)==0) sm[t>>5] = mx;
    __syncthreads();
    if (t<32){
        float z = (t<8)? sm[t] : -3.0e38f;
        #pragma unroll
        for (int o=4;o;o>>=1) z = fmaxf(z, __shfl_xor_sync(0xffffffffu, z, o));
        if (t==0) sm[0] = z;
    }
    __syncthreads();
    mx = sm[0];
    __syncthreads();
    float s = 0.f;
    #pragma unroll
    for (int e=0;e<PER;e++){ v[e] = expf(v[e]-mx); s += v[e]; }
    #pragma unroll
    for (int o=16;o;o>>=1) s += __shfl_xor_sync(0xffffffffu, s, o);
    if ((t&31)==0) sm[t>>5] = s;
    __syncthreads();
    if (t<32){
        float z = (t<8)? sm[t] : 0.f;
        #pragma unroll
        for (int o=4;o;o>>=1) z += __shfl_xor_sync(0xffffffffu, z, o);
        if (t==0) sm[0] = z;
    }
    __syncthreads();
    float inv = 1.0f / sm[0];
    #pragma unroll
    for (int e=0;e<PER;e++) x[t + (e<<8)] = tf32r(v[e]*inv);
}

// ---------------- tf32 GEMM 128x128x32, warp tile 64x64, cp.async 2-stage ----------
// Inputs A,B must be tf32-pre-rounded. C = A@B (+bias,+gelu,+res), optional tf32 round.
__global__ void __launch_bounds__(128, 2) gemm_kernel(
    const float* __restrict__ A, const float* __restrict__ Bm,
    float* __restrict__ C, const float* __restrict__ bias,
    const float* __restrict__ res, int M, int N, int K, int gelu, int roundout)
{
    __shared__ float As[2][128*36];
    __shared__ float Bs[2][32*132];
    int tid = threadIdx.x;
    int bm = blockIdx.y << 7, bn = blockIdx.x << 7;
    int warp = tid >> 5, lane = tid & 31;
    int wm = warp & 1, wn = warp >> 1;

    wmma::fragment<wmma::accumulator,16,16,8,float> acc[4][4];
    #pragma unroll
    for (int i=0;i<4;i++)
        #pragma unroll
        for (int j=0;j<4;j++) wmma::fill_fragment(acc[i][j], 0.0f);

    const float* Ab = A + (size_t)bm * K;
    const float* Bb = Bm + bn;
    int KT = K >> 5;

    int arow[8], acol[8], asoff[8];
    int brow[8], bcol[8], bsoff[8];
    #pragma unroll
    for (int p=0;p<8;p++){
        int l = tid + (p<<7);
        arow[p] = l>>3;  acol[p] = (l&7)<<2;  asoff[p] = arow[p]*36  + acol[p];
        brow[p] = l>>5;  bcol[p] = (l&31)<<2; bsoff[p] = brow[p]*132 + bcol[p];
    }

    auto issue = [&](int s, int kt){
        int k0 = kt << 5;
        #pragma unroll
        for (int p=0;p<8;p++)
            cp16(&As[s][asoff[p]], Ab + (size_t)arow[p]*K + k0 + acol[p]);
        #pragma unroll
        for (int p=0;p<8;p++)
            cp16(&Bs[s][bsoff[p]], Bb + (size_t)(k0 + brow[p])*N + bcol[p]);
        cp_commit();
    };

    issue(0, 0);

    for (int kt = 0; kt < KT; kt++) {
        int cur = kt & 1;
        if (kt + 1 < KT) { issue(cur^1, kt+1); cp_wait<1>(); }
        else             { cp_wait<0>(); }
        __syncthreads();

        const float* Asb = As[cur];
        const float* Bsb = Bs[cur];
        #pragma unroll
        for (int ks=0; ks<4; ks++) {
            wmma::fragment<wmma::matrix_a,16,16,8,wmma::precision::tf32,wmma::row_major> af[4];
            wmma::fragment<wmma::matrix_b,16,16,8,wmma::precision::tf32,wmma::row_major> bf[4];
            #pragma unroll
            for (int i=0;i<4;i++)
                wmma::load_matrix_sync(af[i], Asb + (wm*64 + i*16)*36 + ks*8, 36);
            #pragma unroll
            for (int j=0;j<4;j++)
                wmma::load_matrix_sync(bf[j], Bsb + (ks*8)*132 + wn*64 + j*16, 132);
            #pragma unroll
            for (int i=0;i<4;i++)
                #pragma unroll
                for (int j=0;j<4;j++)
                    wmma::mma_sync(acc[i][j], af[i], bf[j], acc[i][j]);
        }
        __syncthreads();
    }

    // epilogue via per-warp smem staging (reuse As[0])
    __syncthreads();
    float* scratch = (float*)As[0] + warp*256;
    #pragma unroll
    for (int i=0;i<4;i++)
        #pragma unroll
        for (int j=0;j<4;j++) {
            wmma::store_matrix_sync(scratch, acc[i][j], 16, wmma::mem_row_major);
            __syncwarp();
            int r0 = bm + wm*64 + i*16;
            int c0 = bn + wn*64 + j*16;
            #pragma unroll
            for (int e=0;e<8;e++) {
                int el = (e<<5) + lane;
                int rr = el >> 4, cc = el & 15;
                float v = scratch[el];
                int gc = c0 + cc;
                if (bias) v += bias[gc];
                if (gelu) v = 0.5f*v*(1.0f + erff(v*0.70710678118654752f));
                if (roundout) v = tf32r(v);
                size_t o = (size_t)(r0+rr)*N + gc;
                if (res) v += res[o];
                C[o] = v;
            }
            __syncwarp();
        }
}

// ---------------- batched scores: S[bh,i,j] = scale * Q_h[i,:] . K_h[j,:] ----------------
// Q, KV pre-rounded to tf32.
__global__ void __launch_bounds__(256) scores_kernel(
    const float* __restrict__ Q, const float* __restrict__ KV,
    float* __restrict__ S, int ctx)
{
    __shared__ float Qs[128*36];
    __shared__ float Ks[128*36];
    int bh = blockIdx.z; int b = bh / CNH, h = bh % CNH;
    const float* Qb = Q  + (size_t)b*CNQ*CD       + h*CHD;
    const float* Kb = KV + (size_t)b*ctx*(2*CD)   + h*CHD;
    int i0 = blockIdx.y << 7, j0 = blockIdx.x << 7;
    int tid = threadIdx.x, warp = tid>>5;
    int wm = warp & 3, wn = warp >> 2;

    wmma::fragment<wmma::accumulator,16,16,8,float> acc[2][4];
    #pragma unroll
    for (int i=0;i<2;i++)
        #pragma unroll
        for (int j=0;j<4;j++) wmma::fill_fragment(acc[i][j], 0.0f);

    #pragma unroll
    for (int kt=0; kt<2; kt++) {
        if (kt) __syncthreads();
        #pragma unroll
        for (int p=0;p<4;p++){
            int l = tid + (p<<8); int r = l>>3; int c = (l&7)<<2;
            *(float4*)(Qs + r*36 + c) = *(const float4*)(Qb + (size_t)(i0+r)*CD     + kt*32 + c);
            *(float4*)(Ks + r*36 + c) = *(const float4*)(Kb + (size_t)(j0+r)*(2*CD) + kt*32 + c);
        }
        __syncthreads();
        #pragma unroll
        for (int ks=0; ks<4; ks++) {
            wmma::fragment<wmma::matrix_a,16,16,8,wmma::precision::tf32,wmma::row_major> af[2];
            wmma::fragment<wmma::matrix_b,16,16,8,wmma::precision::tf32,wmma::col_major> bf[4];
            #pragma unroll
            for (int i=0;i<2;i++)
                wmma::load_matrix_sync(af[i], Qs + (wm*32 + i*16)*36 + ks*8, 36);
            #pragma unroll
            for (int j=0;j<4;j++)
                wmma::load_matrix_sync(bf[j], Ks + (wn*64 + j*16)*36 + ks*8, 36);
            #pragma unroll
            for (int i=0;i<2;i++)
                #pragma unroll
                for (int j=0;j<4;j++)
                    wmma::mma_sync(acc[i][j], af[i], bf[j], acc[i][j]);
        }
    }

    const float scale = 0.125f;  // 64^-0.5
    float* Sb = S + (size_t)bh * CNQ * ctx;
    #pragma unroll
    for (int i=0;i<2;i++)
        #pragma unroll
        for (int j=0;j<4;j++){
            #pragma unroll
            for (int e=0;e<acc[i][j].num_elements;e++) acc[i][j].x[e] *= scale;
            wmma::store_matrix_sync(Sb + (size_t)(i0 + wm*32 + i*16)*ctx + j0 + wn*64 + j*16,
                                    acc[i][j], ctx, wmma::mem_row_major);
        }
}

// ---------------- batched PV: AO[b,i,h*64+d] = sum_j P[bh,i,j] * V_h[j,d] ----------------
// P, KV pre-rounded; output rounded (consumed by GEMM).
__global__ void __launch_bounds__(256) pv_kernel(
    const float* __restrict__ P, const float* __restrict__ KV,
    float* __restrict__ AO, int ctx)
{
    __shared__ float Ps[128*36];
    __shared__ float Vs[32*68];
    int bh = blockIdx.y; int b = bh / CNH, h = bh % CNH;
    int i0 = blockIdx.x << 7;
    const float* Pb = P  + (size_t)bh*CNQ*ctx + (size_t)i0*ctx;
    const float* Vb = KV + (size_t)b*ctx*(2*CD) + CD + h*CHD;
    int tid = threadIdx.x, warp = tid >> 5;

    wmma::fragment<wmma::accumulator,16,16,8,float> acc[4];
    #pragma unroll
    for (int j=0;j<4;j++) wmma::fill_fragment(acc[j], 0.0f);

    int KT = ctx >> 5;
    float4 pr[4], vr[2];
    #pragma unroll
    for (int p=0;p<4;p++){ int l=tid+(p<<8); int r=l>>3; int c=(l&7)<<2;
        pr[p] = *(const float4*)(Pb + (size_t)r*ctx + c); }
    #pragma unroll
    for (int p=0;p<2;p++){ int l=tid+(p<<8); int r=l>>4; int c=(l&15)<<2;
        vr[p] = *(const float4*)(Vb + (size_t)r*(2*CD) + c); }

    for (int kt=0; kt<KT; kt++) {
        __syncthreads();
        #pragma unroll
        for (int p=0;p<4;p++){ int l=tid+(p<<8); int r=l>>3; int c=(l&7)<<2;
            *(float4*)(Ps + r*36 + c) = pr[p]; }
        #pragma unroll
        for (int p=0;p<2;p++){ int l=tid+(p<<8); int r=l>>4; int c=(l&15)<<2;
            *(float4*)(Vs + r*68 + c) = vr[p]; }
        __syncthreads();
        if (kt+1 < KT) {
            int k0 = (kt+1) << 5;
            #pragma unroll
            for (int p=0;p<4;p++){ int l=tid+(p<<8); int r=l>>3; int c=(l&7)<<2;
                pr[p] = *(const float4*)(Pb + (size_t)r*ctx + k0 + c); }
            #pragma unroll
            for (int p=0;p<2;p++){ int l=tid+(p<<8); int r=l>>4; int c=(l&15)<<2;
                vr[p] = *(const float4*)(Vb + (size_t)(k0+r)*(2*CD) + c); }
        }
        #pragma unroll
        for (int ks=0; ks<4; ks++) {
            wmma::fragment<wmma::matrix_a,16,16,8,wmma::precision::tf32,wmma::row_major> af;
            wmma::fragment<wmma::matrix_b,16,16,8,wmma::precision::tf32,wmma::row_major> bf[4];
            wmma::load_matrix_sync(af, Ps + (warp*16)*36 + ks*8, 36);
            #pragma unroll
            for (int j=0;j<4;j++){
                wmma::load_matrix_sync(bf[j], Vs + (ks*8)*68 + j*16, 68);
                wmma::mma_sync(acc[j], af, bf[j], acc[j]);
            }
        }
    }

    float* Ob = AO + (size_t)((size_t)b*CNQ + i0 + warp*16)*CD + h*CHD;
    #pragma unroll
    for (int j=0;j<4;j++){
        #pragma unroll
        for (int e=0;e<acc[j].num_elements;e++) acc[j].x[e] = tf32r(acc[j].x[e]);
        wmma::store_matrix_sync(Ob + j*16, acc[j], CD, wmma::mem_row_major);
    }
}

// ---------------- driver ----------------
extern "C" void kernel_launch(void* const* d_in, const int* in_sizes, int n_in,
                              void* d_out, int out_size)
{
    const float* query   = (const float*)d_in[0];
    const float* context = (const float*)d_in[1];
    const float* ln_w    = (const float*)d_in[2];
    const float* ln_b    = (const float*)d_in[3];
    const float* a1_bp   = (const float*)d_in[7];
    const float* m1_b1   = (const float*)d_in[9];
    const float* m1_b2   = (const float*)d_in[11];
    const float* a2_bp   = (const float*)d_in[15];
    const float* m2_b1   = (const float*)d_in[17];
    const float* m2_b2   = (const float*)d_in[19];

    float* out   = (float*)d_out;
    float* out_c = out;                       // first half: c
    float* out_q = out + (size_t)CRQ * CE;    // second half: ln(query)

    float *cn, *Qp, *KVp, *Sp, *AOp, *cp, *tp, *tq, *Hp, *W;
    cudaGetSymbolAddress((void**)&cn,  g_cn);
    cudaGetSymbolAddress((void**)&Qp,  g_Q);
    cudaGetSymbolAddress((void**)&KVp, g_KV);
    cudaGetSymbolAddress((void**)&Sp,  g_S);
    cudaGetSymbolAddress((void**)&AOp, g_AO);
    cudaGetSymbolAddress((void**)&cp,  g_c);
    cudaGetSymbolAddress((void**)&tp,  g_t);
    cudaGetSymbolAddress((void**)&tq,  g_tq);
    cudaGetSymbolAddress((void**)&Hp,  g_H);
    cudaGetSymbolAddress((void**)&W,   g_W);

    // pre-round weights into g_W
    const int widx[10] = {4,5,6,8,10,12,13,14,16,18};
    const int wsz [10] = {CE*CD, CE*2*CD, CD*CE, CE*CHID, CHID*CE,
                          CE*CD, CE*2*CD, CD*CE, CE*CHID, CHID*CE};
    float* wptr[10];
    {
        size_t off = 0;
        for (int i=0;i<10;i++){ wptr[i] = W + off; off += wsz[i]; }
    }
    for (int i=0;i<10;i++)
        round_kernel<<<(wsz[i]+255)/256, 256>>>((const float*)d_in[widx[i]], wptr[i], wsz[i]);
    float* a1_wq = wptr[0];  float* a1_wkv = wptr[1]; float* a1_wp = wptr[2];
    float* m1_w1 = wptr[3];  float* m1_w2  = wptr[4];
    float* a2_wq = wptr[5];  float* a2_wkv = wptr[6]; float* a2_wp = wptr[7];
    float* m2_w1 = wptr[8];  float* m2_w2  = wptr[9];

    // q = LN(query) -> out_q(exact) + tq(rounded) ; cn = LN(context) rounded
    ln_kernel<<<CRQ, 256>>>(query,   ln_w, ln_b, out_q, tq);
    ln_kernel<<<CRC, 256>>>(context, ln_w, ln_b, nullptr, cn);

    // ---- block 1: cross-attention over context (m=2048) ----
    gemm_kernel<<<dim3(3, 64),  128>>>(tq, a1_wq,  Qp,  nullptr, nullptr, CRQ, CD,   CE, 0, 1);
    gemm_kernel<<<dim3(6, 128), 128>>>(cn, a1_wkv, KVp, nullptr, nullptr, CRC, 2*CD, CE, 0, 1);
    scores_kernel<<<dim3(16, 8, 48), 256>>>(Qp, KVp, Sp, CNC);
    softmax_kernel<8><<<CB*CNH*CNQ, 256>>>(Sp);
    pv_kernel<<<dim3(8, 48), 256>>>(Sp, KVp, AOp, CNC);
    gemm_kernel<<<dim3(6, 64), 128>>>(AOp, a1_wp, cp, a1_bp, nullptr, CRQ, CE, CD, 0, 0);

    // ---- MLP 1 (with residual) ----
    ln_kernel<<<CRQ, 256>>>(cp, ln_w, ln_b, nullptr, tp);
    gemm_kernel<<<dim3(24, 64), 128>>>(tp, m1_w1, Hp, m1_b1, nullptr, CRQ, CHID, CE,   1, 1);
    gemm_kernel<<<dim3(6, 64),  128>>>(Hp, m1_w2, cp, m1_b2, cp,      CRQ, CE,   CHID, 0, 0);

    // ---- block 2: cross-attention over c (m=1024), residual ----
    ln_kernel<<<CRQ, 256>>>(cp, ln_w, ln_b, nullptr, tp);
    gemm_kernel<<<dim3(3, 64), 128>>>(tq, a2_wq,  Qp,  nullptr, nullptr, CRQ, CD,   CE, 0, 1);
    gemm_kernel<<<dim3(6, 64), 128>>>(tp, a2_wkv, KVp, nullptr, nullptr, CRQ, 2*CD, CE, 0, 1);
    scores_kernel<<<dim3(8, 8, 48), 256>>>(Qp, KVp, Sp, CNQ);
    softmax_kernel<4><<<CB*CNH*CNQ, 256>>>(Sp);
    pv_kernel<<<dim3(8, 48), 256>>>(Sp, KVp, AOp, CNQ);
    gemm_kernel<<<dim3(6, 64), 128>>>(AOp, a2_wp, cp, a2_bp, cp, CRQ, CE, CD, 0, 0);

    // ---- MLP 2 (with residual), final write straight into d_out ----
    ln_kernel<<<CRQ, 256>>>(cp, ln_w, ln_b, nullptr, tp);
    gemm_kernel<<<dim3(24, 64), 128>>>(tp, m2_w1, Hp,    m2_b1, nullptr, CRQ, CHID, CE,   1, 1);
    gemm_kernel<<<dim3(6, 64),  128>>>(Hp, m2_w2, out_c, m2_b2, cp,      CRQ, CE,   CHID, 0, 0);
}

// round 5
// speedup vs baseline: 3.4905x; 3.2912x over previous
#include <cuda_runtime.h>
#include <cuda_fp16.h>
#include <mma.h>
#include <cstdint>

using namespace nvcuda;

#define CB   8
#define CNQ  1024
#define CNC  2048
#define CE   768
#define CD   384
#define CNH  6
#define CHD  64
#define CHID 3072
#define CRQ  (CB*CNQ)   /* 8192  */
#define CRC  (CB*CNC)   /* 16384 */

// ---------------- scratch (no cudaMalloc allowed) ----------------
__device__ __half g_cn[(size_t)CRC*CE];
__device__ __half g_Q [(size_t)CRQ*CD];
__device__ __half g_KV[(size_t)CRC*2*CD];
__device__ __half g_S [(size_t)CB*CNH*CNQ*CNC];
__device__ __half g_AO[(size_t)CRQ*CD];
__device__ float  g_c [(size_t)CRQ*CE];
__device__ __half g_t [(size_t)CRQ*CE];
__device__ __half g_tq[(size_t)CRQ*CE];
__device__ __half g_H [(size_t)CRQ*CHID];
__device__ __half g_W [11796480];   // all weights, fp16-rounded

// ---------------- helpers ----------------
__device__ __forceinline__ void cp16(void* smem, const void* gmem) {
    unsigned s = (unsigned)__cvta_generic_to_shared(smem);
    asm volatile("cp.async.ca.shared.global [%0], [%1], 16;\n" :: "r"(s), "l"(gmem));
}
__device__ __forceinline__ void cp_commit() {
    asm volatile("cp.async.commit_group;\n");
}
template<int N>
__device__ __forceinline__ void cp_wait() {
    asm volatile("cp.async.wait_group %0;\n" :: "n"(N));
}

// ---------------- weight round to fp16 ----------------
__global__ void round_kernel(const float* __restrict__ x, __half* __restrict__ y, int n)
{
    int i = (blockIdx.x << 8) + threadIdx.x;
    if (i < n) y[i] = __float2half(x[i]);
}

// ---------------- LayerNorm: one block per 768-wide row ----------------
__global__ void ln_kernel(const float* __restrict__ x, const float* __restrict__ w,
                          const float* __restrict__ b, float* __restrict__ y,
                          __half* __restrict__ y2)
{
    __shared__ float sm[8];
    size_t row = blockIdx.x;
    const float* xr = x + row * CE;
    int t = threadIdx.x;
    float v0 = xr[t], v1 = xr[t+256], v2 = xr[t+512];

    float s = v0 + v1 + v2;
    #pragma unroll
    for (int o=16;o;o>>=1) s += __shfl_xor_sync(0xffffffffu, s, o);
    if ((t&31)==0) sm[t>>5] = s;
    __syncthreads();
    if (t < 32) {
        float z = (t<8) ? sm[t] : 0.f;
        #pragma unroll
        for (int o=4;o;o>>=1) z += __shfl_xor_sync(0xffffffffu, z, o);
        if (t==0) sm[0] = z;
    }
    __syncthreads();
    float mean = sm[0] * (1.0f/CE);
    __syncthreads();

    float d0 = v0-mean, d1 = v1-mean, d2 = v2-mean;
    float q = d0*d0 + d1*d1 + d2*d2;
    #pragma unroll
    for (int o=16;o;o>>=1) q += __shfl_xor_sync(0xffffffffu, q, o);
    if ((t&31)==0) sm[t>>5] = q;
    __syncthreads();
    if (t < 32) {
        float z = (t<8) ? sm[t] : 0.f;
        #pragma unroll
        for (int o=4;o;o>>=1) z += __shfl_xor_sync(0xffffffffu, z, o);
        if (t==0) sm[0] = z;
    }
    __syncthreads();
    float inv = rsqrtf(sm[0]*(1.0f/CE) + 1e-5f);

    float r0 = d0*inv*w[t]     + b[t];
    float r1 = d1*inv*w[t+256] + b[t+256];
    float r2 = d2*inv*w[t+512] + b[t+512];
    if (y)  { float* yr = y + row*CE;
        yr[t] = r0; yr[t+256] = r1; yr[t+512] = r2; }
    if (y2) { __half* yr = y2 + row*CE;
        yr[t] = __float2half(r0); yr[t+256] = __float2half(r1); yr[t+512] = __float2half(r2); }
}

// ---------------- row softmax on fp16 rows (cols = PER2*512) ----------------
template<int PER2>
__global__ void softmax_kernel(__half* __restrict__ S)
{
    __shared__ float sm[8];
    size_t row = blockIdx.x;
    __half2* x = (__half2*)(S + row * (size_t)(PER2*512));
    int t = threadIdx.x;
    float2 v[PER2];
    float mx = -3.0e38f;
    #pragma unroll
    for (int e=0;e<PER2;e++){
        v[e] = __half22float2(x[t + (e<<8)]);
        mx = fmaxf(mx, fmaxf(v[e].x, v[e].y));
    }
    #pragma unroll
    for (int o=16;o;o>>=1) mx = fmaxf(mx, __shfl_xor_sync(0xffffffffu, mx, o));
    if ((t&31)==0) sm[t>>5] = mx;
    __syncthreads();
    if (t<32){
        float z = (t<8)? sm[t] : -3.0e38f;
        #pragma unroll
        for (int o=4;o;o>>=1) z = fmaxf(z, __shfl_xor_sync(0xffffffffu, z, o));
        if (t==0) sm[0] = z;
    }
    __syncthreads();
    mx = sm[0];
    __syncthreads();
    float s = 0.f;
    #pragma unroll
    for (int e=0;e<PER2;e++){
        v[e].x = expf(v[e].x-mx); v[e].y = expf(v[e].y-mx);
        s += v[e].x + v[e].y;
    }
    #pragma unroll
    for (int o=16;o;o>>=1) s += __shfl_xor_sync(0xffffffffu, s, o);
    if ((t&31)==0) sm[t>>5] = s;
    __syncthreads();
    if (t<32){
        float z = (t<8)? sm[t] : 0.f;
        #pragma unroll
        for (int o=4;o;o>>=1) z += __shfl_xor_sync(0xffffffffu, z, o);
        if (t==0) sm[0] = z;
    }
    __syncthreads();
    float inv = 1.0f / sm[0];
    #pragma unroll
    for (int e=0;e<PER2;e++)
        x[t + (e<<8)] = __floats2half2_rn(v[e].x*inv, v[e].y*inv);
}

// ---------------- fp16 GEMM 128x128x32, warp tile 64x32, cp.async 2-stage ----------
// C = A@B (+bias,+gelu). If Ch != null -> write fp16 (no residual);
// else write fp32 to Cf (+res).
__global__ void __launch_bounds__(256) gemm_kernel(
    const __half* __restrict__ A, const __half* __restrict__ Bm,
    float* __restrict__ Cf, __half* __restrict__ Ch,
    const float* __restrict__ bias, const float* __restrict__ res,
    int M, int N, int K, int gelu)
{
    __shared__ __half As[2][128*40];
    __shared__ __half Bs[2][32*136];
    int tid = threadIdx.x;
    int bm = blockIdx.y << 7, bn = blockIdx.x << 7;
    int warp = tid >> 5, lane = tid & 31;
    int wm = warp & 1, wn = warp >> 1;

    wmma::fragment<wmma::accumulator,16,16,16,float> acc[4][2];
    #pragma unroll
    for (int i=0;i<4;i++)
        #pragma unroll
        for (int j=0;j<2;j++) wmma::fill_fragment(acc[i][j], 0.0f);

    const __half* Ab = A + (size_t)bm * K;
    const __half* Bb = Bm + bn;
    int KT = K >> 5;

    auto issue = [&](int s, int kt){
        int k0 = kt << 5;
        #pragma unroll
        for (int p=0;p<2;p++){
            int id = tid + (p<<8);
            int r = id>>2, c = (id&3)<<3;
            cp16(&As[s][r*40 + c], Ab + (size_t)r*K + k0 + c);
        }
        #pragma unroll
        for (int p=0;p<2;p++){
            int id = tid + (p<<8);
            int r = id>>4, c = (id&15)<<3;
            cp16(&Bs[s][r*136 + c], Bb + (size_t)(k0+r)*N + c);
        }
        cp_commit();
    };

    issue(0, 0);

    for (int kt = 0; kt < KT; kt++) {
        int cur = kt & 1;
        if (kt + 1 < KT) { issue(cur^1, kt+1); cp_wait<1>(); }
        else             { cp_wait<0>(); }
        __syncthreads();

        const __half* Asb = As[cur];
        const __half* Bsb = Bs[cur];
        #pragma unroll
        for (int ks=0; ks<2; ks++) {
            wmma::fragment<wmma::matrix_a,16,16,16,__half,wmma::row_major> af[4];
            wmma::fragment<wmma::matrix_b,16,16,16,__half,wmma::row_major> bf[2];
            #pragma unroll
            for (int i=0;i<4;i++)
                wmma::load_matrix_sync(af[i], Asb + (wm*64 + i*16)*40 + ks*16, 40);
            #pragma unroll
            for (int j=0;j<2;j++)
                wmma::load_matrix_sync(bf[j], Bsb + (ks*16)*136 + wn*32 + j*16, 136);
            #pragma unroll
            for (int i=0;i<4;i++)
                #pragma unroll
                for (int j=0;j<2;j++)
                    wmma::mma_sync(acc[i][j], af[i], bf[j], acc[i][j]);
        }
        __syncthreads();
    }

    // epilogue via per-warp smem staging (reuse As)
    __syncthreads();
    float* scratch = (float*)(&As[0][0]) + warp*256;
    #pragma unroll
    for (int i=0;i<4;i++)
        #pragma unroll
        for (int j=0;j<2;j++) {
            wmma::store_matrix_sync(scratch, acc[i][j], 16, wmma::mem_row_major);
            __syncwarp();
            int r0 = bm + wm*64 + i*16;
            int c0 = bn + wn*32 + j*16;
            #pragma unroll
            for (int e=0;e<8;e++) {
                int el = (e<<5) + lane;
                int rr = el >> 4, cc = el & 15;
                float v = scratch[el];
                int gc = c0 + cc;
                if (bias) v += bias[gc];
                if (gelu) v = 0.5f*v*(1.0f + erff(v*0.70710678118654752f));
                size_t o = (size_t)(r0+rr)*N + gc;
                if (Ch) Ch[o] = __float2half(v);
                else { if (res) v += res[o]; Cf[o] = v; }
            }
            __syncwarp();
        }
}

// ---------------- batched scores: S[bh,i,j] = scale * Q_h[i,:] . K_h[j,:]  (fp16) ----
__global__ void __launch_bounds__(256) scores_kernel(
    const __half* __restrict__ Q, const __half* __restrict__ KV,
    __half* __restrict__ S, int ctx)
{
    __shared__ __half Qs[128*72];
    __shared__ __half Ks[128*72];
    int bh = blockIdx.z; int b = bh / CNH, h = bh % CNH;
    const __half* Qb = Q  + (size_t)b*CNQ*CD     + h*CHD;
    const __half* Kb = KV + (size_t)b*ctx*(2*CD) + h*CHD;
    int i0 = blockIdx.y << 7, j0 = blockIdx.x << 7;
    int tid = threadIdx.x, warp = tid>>5, lane = tid&31;
    int wm = warp & 3, wn = warp >> 2;

    wmma::fragment<wmma::accumulator,16,16,16,float> acc[2][4];
    #pragma unroll
    for (int i=0;i<2;i++)
        #pragma unroll
        for (int j=0;j<4;j++) wmma::fill_fragment(acc[i][j], 0.0f);

    #pragma unroll
    for (int p=0;p<4;p++){
        int id = tid + (p<<8); int r = id>>3; int c = (id&7)<<3;
        *(uint4*)&Qs[r*72 + c] = *(const uint4*)(Qb + (size_t)(i0+r)*CD     + c);
        *(uint4*)&Ks[r*72 + c] = *(const uint4*)(Kb + (size_t)(j0+r)*(2*CD) + c);
    }
    __syncthreads();

    #pragma unroll
    for (int ks=0; ks<4; ks++) {
        wmma::fragment<wmma::matrix_a,16,16,16,__half,wmma::row_major> af[2];
        wmma::fragment<wmma::matrix_b,16,16,16,__half,wmma::col_major> bf[4];
        #pragma unroll
        for (int i=0;i<2;i++)
            wmma::load_matrix_sync(af[i], Qs + (wm*32 + i*16)*72 + ks*16, 72);
        #pragma unroll
        for (int j=0;j<4;j++)
            wmma::load_matrix_sync(bf[j], Ks + (wn*64 + j*16)*72 + ks*16, 72);
        #pragma unroll
        for (int i=0;i<2;i++)
            #pragma unroll
            for (int j=0;j<4;j++)
                wmma::mma_sync(acc[i][j], af[i], bf[j], acc[i][j]);
    }

    __syncthreads();   // done reading Qs; reuse as scratch
    const float scale = 0.125f;  // 64^-0.5
    __half* Sb = S + (size_t)bh * CNQ * ctx;
    float* scratch = (float*)Qs + warp*256;
    #pragma unroll
    for (int i=0;i<2;i++)
        #pragma unroll
        for (int j=0;j<4;j++){
            wmma::store_matrix_sync(scratch, acc[i][j], 16, wmma::mem_row_major);
            __syncwarp();
            int r0 = i0 + wm*32 + i*16;
            int c0 = j0 + wn*64 + j*16;
            #pragma unroll
            for (int e=0;e<8;e++){
                int el = (e<<5) + lane;
                int rr = el >> 4, cc = el & 15;
                Sb[(size_t)(r0+rr)*ctx + c0 + cc] = __float2half(scratch[el]*scale);
            }
            __syncwarp();
        }
}

// ---------------- batched PV: AO[b,i,h*64+d] = sum_j P[bh,i,j] * V_h[j,d]  (fp16) ----
__global__ void __launch_bounds__(256) pv_kernel(
    const __half* __restrict__ P, const __half* __restrict__ KV,
    __half* __restrict__ AO, int ctx)
{
    __shared__ __half Ps[2][128*40];
    __shared__ __half Vs[2][32*72];
    int bh = blockIdx.y; int b = bh / CNH, h = bh % CNH;
    int i0 = blockIdx.x << 7;
    const __half* Pb = P  + (size_t)bh*CNQ*ctx + (size_t)i0*ctx;
    const __half* Vb = KV + (size_t)b*ctx*(2*CD) + CD + h*CHD;
    int tid = threadIdx.x, warp = tid >> 5, lane = tid & 31;

    wmma::fragment<wmma::accumulator,16,16,16,float> acc[4];
    #pragma unroll
    for (int j=0;j<4;j++) wmma::fill_fragment(acc[j], 0.0f);

    int KT = ctx >> 5;

    auto issue = [&](int s, int kt){
        int k0 = kt << 5;
        #pragma unroll
        for (int p=0;p<2;p++){
            int id = tid + (p<<8);
            int r = id>>2, c = (id&3)<<3;
            cp16(&Ps[s][r*40 + c], Pb + (size_t)r*ctx + k0 + c);
        }
        {
            int r = tid>>3, c = (tid&7)<<3;
            cp16(&Vs[s][r*72 + c], Vb + (size_t)(k0+r)*(2*CD) + c);
        }
        cp_commit();
    };

    issue(0, 0);

    for (int kt=0; kt<KT; kt++) {
        int cur = kt & 1;
        if (kt + 1 < KT) { issue(cur^1, kt+1); cp_wait<1>(); }
        else             { cp_wait<0>(); }
        __syncthreads();

        const __half* Psb = Ps[cur];
        const __half* Vsb = Vs[cur];
        #pragma unroll
        for (int ks=0; ks<2; ks++) {
            wmma::fragment<wmma::matrix_a,16,16,16,__half,wmma::row_major> af;
            wmma::fragment<wmma::matrix_b,16,16,16,__half,wmma::row_major> bf[4];
            wmma::load_matrix_sync(af, Psb + (warp*16)*40 + ks*16, 40);
            #pragma unroll
            for (int j=0;j<4;j++){
                wmma::load_matrix_sync(bf[j], Vsb + (ks*16)*72 + j*16, 72);
                wmma::mma_sync(acc[j], af, bf[j], acc[j]);
            }
        }
        __syncthreads();
    }

    __syncthreads();
    __half* Ob = AO + (size_t)((size_t)b*CNQ + i0 + warp*16)*CD + h*CHD;
    float* scratch = (float*)(&Ps[0][0]) + warp*256;
    #pragma unroll
    for (int j=0;j<4;j++){
        wmma::store_matrix_sync(scratch, acc[j], 16, wmma::mem_row_major);
        __syncwarp();
        #pragma unroll
        for (int e=0;e<8;e++){
            int el = (e<<5) + lane;
            int rr = el >> 4, cc = el & 15;
            Ob[(size_t)rr*CD + j*16 + cc] = __float2half(scratch[el]);
        }
        __syncwarp();
    }
}

// ---------------- driver ----------------
extern "C" void kernel_launch(void* const* d_in, const int* in_sizes, int n_in,
                              void* d_out, int out_size)
{
    const float* query   = (const float*)d_in[0];
    const float* context = (const float*)d_in[1];
    const float* ln_w    = (const float*)d_in[2];
    const float* ln_b    = (const float*)d_in[3];
    const float* a1_bp   = (const float*)d_in[7];
    const float* m1_b1   = (const float*)d_in[9];
    const float* m1_b2   = (const float*)d_in[11];
    const float* a2_bp   = (const float*)d_in[15];
    const float* m2_b1   = (const float*)d_in[17];
    const float* m2_b2   = (const float*)d_in[19];

    float* out   = (float*)d_out;
    float* out_c = out;                       // first half: c
    float* out_q = out + (size_t)CRQ * CE;    // second half: ln(query)

    __half *cn, *Qp, *KVp, *Sp, *AOp, *tp, *tq, *Hp, *W;
    float *cp;
    cudaGetSymbolAddress((void**)&cn,  g_cn);
    cudaGetSymbolAddress((void**)&Qp,  g_Q);
    cudaGetSymbolAddress((void**)&KVp, g_KV);
    cudaGetSymbolAddress((void**)&Sp,  g_S);
    cudaGetSymbolAddress((void**)&AOp, g_AO);
    cudaGetSymbolAddress((void**)&cp,  g_c);
    cudaGetSymbolAddress((void**)&tp,  g_t);
    cudaGetSymbolAddress((void**)&tq,  g_tq);
    cudaGetSymbolAddress((void**)&Hp,  g_H);
    cudaGetSymbolAddress((void**)&W,   g_W);

    // pre-round weights to fp16 into g_W (no transpose: B consumed row-major)
    const int widx[10] = {4,5,6,8,10,12,13,14,16,18};
    const int wsz [10] = {CE*CD, CE*2*CD, CD*CE, CE*CHID, CHID*CE,
                          CE*CD, CE*2*CD, CD*CE, CE*CHID, CHID*CE};
    __half* wptr[10];
    {
        size_t off = 0;
        for (int i=0;i<10;i++){ wptr[i] = W + off; off += wsz[i]; }
    }
    for (int i=0;i<10;i++)
        round_kernel<<<(wsz[i]+255)/256, 256>>>((const float*)d_in[widx[i]], wptr[i], wsz[i]);
    __half* a1_wq = wptr[0];  __half* a1_wkv = wptr[1]; __half* a1_wp = wptr[2];
    __half* m1_w1 = wptr[3];  __half* m1_w2  = wptr[4];
    __half* a2_wq = wptr[5];  __half* a2_wkv = wptr[6]; __half* a2_wp = wptr[7];
    __half* m2_w1 = wptr[8];  __half* m2_w2  = wptr[9];

    // q = LN(query) -> out_q(exact fp32) + tq(fp16) ; cn = LN(context) fp16
    ln_kernel<<<CRQ, 256>>>(query,   ln_w, ln_b, out_q, tq);
    ln_kernel<<<CRC, 256>>>(context, ln_w, ln_b, nullptr, cn);

    // ---- block 1: cross-attention over context (m=2048) ----
    gemm_kernel<<<dim3(3, 64),  256>>>(tq, a1_wq,  nullptr, Qp,  nullptr, nullptr, CRQ, CD,   CE, 0);
    gemm_kernel<<<dim3(6, 128), 256>>>(cn, a1_wkv, nullptr, KVp, nullptr, nullptr, CRC, 2*CD, CE, 0);
    scores_kernel<<<dim3(16, 8, 48), 256>>>(Qp, KVp, Sp, CNC);
    softmax_kernel<4><<<CB*CNH*CNQ, 256>>>(Sp);
    pv_kernel<<<dim3(8, 48), 256>>>(Sp, KVp, AOp, CNC);
    gemm_kernel<<<dim3(6, 64), 256>>>(AOp, a1_wp, cp, nullptr, a1_bp, nullptr, CRQ, CE, CD, 0);

    // ---- MLP 1 (with residual) ----
    ln_kernel<<<CRQ, 256>>>(cp, ln_w, ln_b, nullptr, tp);
    gemm_kernel<<<dim3(24, 64), 256>>>(tp, m1_w1, nullptr, Hp, m1_b1, nullptr, CRQ, CHID, CE,   1);
    gemm_kernel<<<dim3(6, 64),  256>>>(Hp, m1_w2, cp, nullptr, m1_b2, cp,      CRQ, CE,   CHID, 0);

    // ---- block 2: cross-attention over c (m=1024), residual ----
    ln_kernel<<<CRQ, 256>>>(cp, ln_w, ln_b, nullptr, tp);
    gemm_kernel<<<dim3(3, 64), 256>>>(tq, a2_wq,  nullptr, Qp,  nullptr, nullptr, CRQ, CD,   CE, 0);
    gemm_kernel<<<dim3(6, 64), 256>>>(tp, a2_wkv, nullptr, KVp, nullptr, nullptr, CRQ, 2*CD, CE, 0);
    scores_kernel<<<dim3(8, 8, 48), 256>>>(Qp, KVp, Sp, CNQ);
    softmax_kernel<2><<<CB*CNH*CNQ, 256>>>(Sp);
    pv_kernel<<<dim3(8, 48), 256>>>(Sp, KVp, AOp, CNQ);
    gemm_kernel<<<dim3(6, 64), 256>>>(AOp, a2_wp, cp, nullptr, a2_bp, cp, CRQ, CE, CD, 0);

    // ---- MLP 2 (with residual), final write straight into d_out ----
    ln_kernel<<<CRQ, 256>>>(cp, ln_w, ln_b, nullptr, tp);
    gemm_kernel<<<dim3(24, 64), 256>>>(tp, m2_w1, nullptr, Hp, m2_b1, nullptr, CRQ, CHID, CE,   1);
    gemm_kernel<<<dim3(6, 64),  256>>>(Hp, m2_w2, out_c, nullptr, m2_b2, cp,   CRQ, CE,   CHID, 0);
}

// round 6
// speedup vs baseline: 4.2342x; 1.2131x over previous
#include <cuda_runtime.h>
#include <cuda_fp16.h>
#include <mma.h>
#include <cstdint>

using namespace nvcuda;

#define CB   8
#define CNQ  1024
#define CNC  2048
#define CE   768
#define CD   384
#define CNH  6
#define CHD  64
#define CHID 3072
#define CRQ  (CB*CNQ)   /* 8192  */
#define CRC  (CB*CNC)   /* 16384 */

// ---------------- scratch (no cudaMalloc allowed) ----------------
__device__ __half g_cn[(size_t)CRC*CE];
__device__ __half g_Q [(size_t)CRQ*CD];
__device__ __half g_KV[(size_t)CRC*2*CD];
__device__ __half g_AO[(size_t)CRQ*CD];
__device__ float  g_c [(size_t)CRQ*CE];
__device__ __half g_t [(size_t)CRQ*CE];
__device__ __half g_tq[(size_t)CRQ*CE];
__device__ __half g_H [(size_t)CRQ*CHID];
__device__ __half g_W [11796480];   // all weights, fp16-rounded

// ---------------- helpers ----------------
__device__ __forceinline__ void cp16(void* smem, const void* gmem) {
    unsigned s = (unsigned)__cvta_generic_to_shared(smem);
    asm volatile("cp.async.ca.shared.global [%0], [%1], 16;\n" :: "r"(s), "l"(gmem));
}
__device__ __forceinline__ void cp_commit() {
    asm volatile("cp.async.commit_group;\n");
}
template<int N>
__device__ __forceinline__ void cp_wait() {
    asm volatile("cp.async.wait_group %0;\n" :: "n"(N));
}
__device__ __forceinline__ void ldsm_x4(uint32_t& r0, uint32_t& r1, uint32_t& r2, uint32_t& r3, uint32_t a) {
    asm volatile("ldmatrix.sync.aligned.m8n8.x4.shared.b16 {%0,%1,%2,%3}, [%4];"
                 : "=r"(r0), "=r"(r1), "=r"(r2), "=r"(r3) : "r"(a));
}
__device__ __forceinline__ void ldsm_x4t(uint32_t& r0, uint32_t& r1, uint32_t& r2, uint32_t& r3, uint32_t a) {
    asm volatile("ldmatrix.sync.aligned.m8n8.x4.trans.shared.b16 {%0,%1,%2,%3}, [%4];"
                 : "=r"(r0), "=r"(r1), "=r"(r2), "=r"(r3) : "r"(a));
}
__device__ __forceinline__ void mma16816(float* c, const uint32_t* a, const uint32_t* b) {
    asm volatile("mma.sync.aligned.m16n8k16.row.col.f32.f16.f16.f32 "
                 "{%0,%1,%2,%3}, {%4,%5,%6,%7}, {%8,%9}, {%0,%1,%2,%3};"
                 : "+f"(c[0]), "+f"(c[1]), "+f"(c[2]), "+f"(c[3])
                 : "r"(a[0]), "r"(a[1]), "r"(a[2]), "r"(a[3]), "r"(b[0]), "r"(b[1]));
}
__device__ __forceinline__ uint32_t pack2(float a, float b) {
    __half2 h = __floats2half2_rn(a, b);
    return *(uint32_t*)&h;
}

// ---------------- weight round to fp16 (all weights, one launch) ----------------
struct WArgs { const float* src[10]; __half* dst[10]; int sz[10]; };
__global__ void round_all(WArgs a)
{
    int w = blockIdx.y;
    int i = (blockIdx.x << 8) + threadIdx.x;
    if (i < a.sz[w]) a.dst[w][i] = __float2half(a.src[w][i]);
}

// ---------------- LayerNorm: one block per 768-wide row ----------------
__global__ void ln_kernel(const float* __restrict__ x, const float* __restrict__ w,
                          const float* __restrict__ b, float* __restrict__ y,
                          __half* __restrict__ y2)
{
    __shared__ float sm[8];
    size_t row = blockIdx.x;
    const float* xr = x + row * CE;
    int t = threadIdx.x;
    float v0 = xr[t], v1 = xr[t+256], v2 = xr[t+512];

    float s = v0 + v1 + v2;
    #pragma unroll
    for (int o=16;o;o>>=1) s += __shfl_xor_sync(0xffffffffu, s, o);
    if ((t&31)==0) sm[t>>5] = s;
    __syncthreads();
    if (t < 32) {
        float z = (t<8) ? sm[t] : 0.f;
        #pragma unroll
        for (int o=4;o;o>>=1) z += __shfl_xor_sync(0xffffffffu, z, o);
        if (t==0) sm[0] = z;
    }
    __syncthreads();
    float mean = sm[0] * (1.0f/CE);
    __syncthreads();

    float d0 = v0-mean, d1 = v1-mean, d2 = v2-mean;
    float q = d0*d0 + d1*d1 + d2*d2;
    #pragma unroll
    for (int o=16;o;o>>=1) q += __shfl_xor_sync(0xffffffffu, q, o);
    if ((t&31)==0) sm[t>>5] = q;
    __syncthreads();
    if (t < 32) {
        float z = (t<8) ? sm[t] : 0.f;
        #pragma unroll
        for (int o=4;o;o>>=1) z += __shfl_xor_sync(0xffffffffu, z, o);
        if (t==0) sm[0] = z;
    }
    __syncthreads();
    float inv = rsqrtf(sm[0]*(1.0f/CE) + 1e-5f);

    float r0 = d0*inv*w[t]     + b[t];
    float r1 = d1*inv*w[t+256] + b[t+256];
    float r2 = d2*inv*w[t+512] + b[t+512];
    if (y)  { float* yr = y + row*CE;
        yr[t] = r0; yr[t+256] = r1; yr[t+512] = r2; }
    if (y2) { __half* yr = y2 + row*CE;
        yr[t] = __float2half(r0); yr[t+256] = __float2half(r1); yr[t+512] = __float2half(r2); }
}

// ---------------- fp16 GEMM 128x128x32, warp tile 64x32, cp.async 2-stage ----------
__global__ void __launch_bounds__(256) gemm_kernel(
    const __half* __restrict__ A, const __half* __restrict__ Bm,
    float* __restrict__ Cf, __half* __restrict__ Ch,
    const float* __restrict__ bias, const float* __restrict__ res,
    int M, int N, int K, int gelu)
{
    __shared__ __half As[2][128*40];
    __shared__ __half Bs[2][32*136];
    int tid = threadIdx.x;
    int bm = blockIdx.y << 7, bn = blockIdx.x << 7;
    int warp = tid >> 5, lane = tid & 31;
    int wm = warp & 1, wn = warp >> 1;

    wmma::fragment<wmma::accumulator,16,16,16,float> acc[4][2];
    #pragma unroll
    for (int i=0;i<4;i++)
        #pragma unroll
        for (int j=0;j<2;j++) wmma::fill_fragment(acc[i][j], 0.0f);

    const __half* Ab = A + (size_t)bm * K;
    const __half* Bb = Bm + bn;
    int KT = K >> 5;

    auto issue = [&](int s, int kt){
        int k0 = kt << 5;
        #pragma unroll
        for (int p=0;p<2;p++){
            int id = tid + (p<<8);
            int r = id>>2, c = (id&3)<<3;
            cp16(&As[s][r*40 + c], Ab + (size_t)r*K + k0 + c);
        }
        #pragma unroll
        for (int p=0;p<2;p++){
            int id = tid + (p<<8);
            int r = id>>4, c = (id&15)<<3;
            cp16(&Bs[s][r*136 + c], Bb + (size_t)(k0+r)*N + c);
        }
        cp_commit();
    };

    issue(0, 0);

    for (int kt = 0; kt < KT; kt++) {
        int cur = kt & 1;
        if (kt + 1 < KT) { issue(cur^1, kt+1); cp_wait<1>(); }
        else             { cp_wait<0>(); }
        __syncthreads();

        const __half* Asb = As[cur];
        const __half* Bsb = Bs[cur];
        #pragma unroll
        for (int ks=0; ks<2; ks++) {
            wmma::fragment<wmma::matrix_a,16,16,16,__half,wmma::row_major> af[4];
            wmma::fragment<wmma::matrix_b,16,16,16,__half,wmma::row_major> bf[2];
            #pragma unroll
            for (int i=0;i<4;i++)
                wmma::load_matrix_sync(af[i], Asb + (wm*64 + i*16)*40 + ks*16, 40);
            #pragma unroll
            for (int j=0;j<2;j++)
                wmma::load_matrix_sync(bf[j], Bsb + (ks*16)*136 + wn*32 + j*16, 136);
            #pragma unroll
            for (int i=0;i<4;i++)
                #pragma unroll
                for (int j=0;j<2;j++)
                    wmma::mma_sync(acc[i][j], af[i], bf[j], acc[i][j]);
        }
        __syncthreads();
    }

    __syncthreads();
    float* scratch = (float*)(&As[0][0]) + warp*256;
    #pragma unroll
    for (int i=0;i<4;i++)
        #pragma unroll
        for (int j=0;j<2;j++) {
            wmma::store_matrix_sync(scratch, acc[i][j], 16, wmma::mem_row_major);
            __syncwarp();
            int r0 = bm + wm*64 + i*16;
            int c0 = bn + wn*32 + j*16;
            #pragma unroll
            for (int e=0;e<8;e++) {
                int el = (e<<5) + lane;
                int rr = el >> 4, cc = el & 15;
                float v = scratch[el];
                int gc = c0 + cc;
                if (bias) v += bias[gc];
                if (gelu) v = 0.5f*v*(1.0f + erff(v*0.70710678118654752f));
                size_t o = (size_t)(r0+rr)*N + gc;
                if (Ch) Ch[o] = __float2half(v);
                else { if (res) v += res[o]; Cf[o] = v; }
            }
            __syncwarp();
        }
}

// ---------------- flash attention: fused QK^T -> softmax -> PV ----------------
// grid (CNQ/128, B*H). Q[b,*,h*64..], KV[b,ctx,(k|v)@h]. AO fp16 [b*CNQ, CD].
#define FA_SMEM 92160
__global__ void __launch_bounds__(256) fattn_kernel(
    const __half* __restrict__ Q, const __half* __restrict__ KV,
    __half* __restrict__ AO, int ctx)
{
    extern __shared__ __align__(128) __half fsm[];
    __half* Qs  = fsm;                 // 128 x 72
    __half* Ksb[2] = { fsm + 9216,  fsm + 2*9216 };
    __half* Vsb[2] = { fsm + 3*9216, fsm + 4*9216 };

    int bh = blockIdx.y, b = bh / CNH, h = bh % CNH;
    int i0 = blockIdx.x << 7;
    const __half* Qb = Q  + (size_t)b*CNQ*CD + h*CHD;
    const __half* Kb = KV + (size_t)b*ctx*(2*CD) + h*CHD;
    const __half* Vb = Kb + CD;
    int tid = threadIdx.x, warp = tid>>5, lane = tid&31;

    // Q tile load (commit group)
    #pragma unroll
    for (int p=0;p<4;p++){
        int id = tid + (p<<8); int r = id>>3, c = (id&7)<<3;
        cp16(&Qs[r*72 + c], Qb + (size_t)(i0+r)*CD + c);
    }
    cp_commit();

    auto load_kv = [&](int s, int j){
        const __half* Kc = Kb + (size_t)(j<<7)*(2*CD);
        const __half* Vc = Vb + (size_t)(j<<7)*(2*CD);
        #pragma unroll
        for (int p=0;p<4;p++){
            int id = tid + (p<<8); int r = id>>3, c = (id&7)<<3;
            cp16(&Ksb[s][r*72 + c], Kc + (size_t)r*(2*CD) + c);
        }
        #pragma unroll
        for (int p=0;p<4;p++){
            int id = tid + (p<<8); int r = id>>3, c = (id&7)<<3;
            cp16(&Vsb[s][r*72 + c], Vc + (size_t)r*(2*CD) + c);
        }
        cp_commit();
    };
    load_kv(0, 0);

    // lane addressing for ldmatrix
    int li = lane & 7, b3 = (lane>>3)&1, b4 = (lane>>4)&1;
    uint32_t qaddr = (uint32_t)__cvta_generic_to_shared(Qs)
                   + (uint32_t)(((warp*16 + b3*8 + li)*72 + b4*8)*2);
    uint32_t koff = (uint32_t)(((b4*8 + li)*72 + b3*8)*2);   // K: row<-b4, col<-b3
    uint32_t voff = (uint32_t)(((b3*8 + li)*72 + b4*8)*2);   // V(trans): row<-b3, col<-b4

    cp_wait<1>();          // Q complete
    __syncthreads();

    uint32_t qa[4][4];
    #pragma unroll
    for (int s=0;s<4;s++)
        ldsm_x4(qa[s][0], qa[s][1], qa[s][2], qa[s][3], qaddr + s*32);

    float m0=-1e30f, m1=-1e30f, l0=0.f, l1=0.f;
    float o[8][4];
    #pragma unroll
    for (int d=0; d<8; d++){ o[d][0]=0.f; o[d][1]=0.f; o[d][2]=0.f; o[d][3]=0.f; }

    const float SC2 = 0.125f * 1.4426950408889634f;  // scale * log2(e)
    int nc = ctx >> 7;

    for (int j=0; j<nc; j++){
        int cur = j & 1;
        if (j+1 < nc){ load_kv(cur^1, j+1); cp_wait<1>(); }
        else         { cp_wait<0>(); }
        __syncthreads();

        uint32_t kb = (uint32_t)__cvta_generic_to_shared(Ksb[cur]) + koff;
        uint32_t vbs = (uint32_t)__cvta_generic_to_shared(Vsb[cur]) + voff;

        // S = Q @ K^T  (16 n8-tiles per warp, fp32 accum)
        float sc[16][4];
        #pragma unroll
        for (int t=0;t<16;t++){ sc[t][0]=0.f; sc[t][1]=0.f; sc[t][2]=0.f; sc[t][3]=0.f; }
        #pragma unroll
        for (int tp=0; tp<8; tp++){
            #pragma unroll
            for (int s=0;s<4;s++){
                uint32_t r0,r1,r2,r3;
                ldsm_x4(r0,r1,r2,r3, kb + tp*16*144 + s*32);
                uint32_t bb0[2] = {r0,r1}, bb1[2] = {r2,r3};
                mma16816(sc[2*tp],   qa[s], bb0);
                mma16816(sc[2*tp+1], qa[s], bb1);
            }
        }

        // online softmax (rows g, g+8 owned by this warp's quads)
        float mx0 = -1e30f, mx1 = -1e30f;
        #pragma unroll
        for (int t=0;t<16;t++){
            mx0 = fmaxf(mx0, fmaxf(sc[t][0], sc[t][1]));
            mx1 = fmaxf(mx1, fmaxf(sc[t][2], sc[t][3]));
        }
        mx0 = fmaxf(mx0, __shfl_xor_sync(0xffffffffu, mx0, 1));
        mx0 = fmaxf(mx0, __shfl_xor_sync(0xffffffffu, mx0, 2));
        mx1 = fmaxf(mx1, __shfl_xor_sync(0xffffffffu, mx1, 1));
        mx1 = fmaxf(mx1, __shfl_xor_sync(0xffffffffu, mx1, 2));
        float nm0 = fmaxf(m0, mx0), nm1 = fmaxf(m1, mx1);
        float r0f = exp2f((m0-nm0)*SC2), r1f = exp2f((m1-nm1)*SC2);
        m0 = nm0; m1 = nm1;
        float s0 = 0.f, s1 = 0.f;
        #pragma unroll
        for (int t=0;t<16;t++){
            sc[t][0] = exp2f((sc[t][0]-nm0)*SC2);
            sc[t][1] = exp2f((sc[t][1]-nm0)*SC2);
            sc[t][2] = exp2f((sc[t][2]-nm1)*SC2);
            sc[t][3] = exp2f((sc[t][3]-nm1)*SC2);
            s0 += sc[t][0] + sc[t][1];
            s1 += sc[t][2] + sc[t][3];
        }
        s0 += __shfl_xor_sync(0xffffffffu, s0, 1);
        s0 += __shfl_xor_sync(0xffffffffu, s0, 2);
        s1 += __shfl_xor_sync(0xffffffffu, s1, 1);
        s1 += __shfl_xor_sync(0xffffffffu, s1, 2);
        l0 = l0*r0f + s0; l1 = l1*r1f + s1;
        #pragma unroll
        for (int d=0; d<8; d++){
            o[d][0]*=r0f; o[d][1]*=r0f; o[d][2]*=r1f; o[d][3]*=r1f;
        }

        // O += P @ V
        #pragma unroll
        for (int kc=0; kc<8; kc++){
            uint32_t pa[4];
            pa[0] = pack2(sc[2*kc][0],   sc[2*kc][1]);
            pa[1] = pack2(sc[2*kc][2],   sc[2*kc][3]);
            pa[2] = pack2(sc[2*kc+1][0], sc[2*kc+1][1]);
            pa[3] = pack2(sc[2*kc+1][2], sc[2*kc+1][3]);
            #pragma unroll
            for (int dp=0; dp<4; dp++){
                uint32_t r0,r1,r2,r3;
                ldsm_x4t(r0,r1,r2,r3, vbs + kc*16*144 + dp*32);
                uint32_t bb0[2] = {r0,r1}, bb1[2] = {r2,r3};
                mma16816(o[2*dp],   pa, bb0);
                mma16816(o[2*dp+1], pa, bb1);
            }
        }
        __syncthreads();   // buffers free for next prefetch
    }

    float inv0 = 1.f/l0, inv1 = 1.f/l1;
    int g = lane>>2, cq = lane&3;
    int row0 = i0 + warp*16 + g;
    __half2* O0 = (__half2*)(AO + ((size_t)b*CNQ + row0)*CD + h*CHD + cq*2);
    __half2* O1 = (__half2*)(AO + ((size_t)b*CNQ + row0+8)*CD + h*CHD + cq*2);
    #pragma unroll
    for (int d=0; d<8; d++){
        O0[d*4] = __floats2half2_rn(o[d][0]*inv0, o[d][1]*inv0);
        O1[d*4] = __floats2half2_rn(o[d][2]*inv1, o[d][3]*inv1);
    }
}

// ---------------- driver ----------------
extern "C" void kernel_launch(void* const* d_in, const int* in_sizes, int n_in,
                              void* d_out, int out_size)
{
    const float* query   = (const float*)d_in[0];
    const float* context = (const float*)d_in[1];
    const float* ln_w    = (const float*)d_in[2];
    const float* ln_b    = (const float*)d_in[3];
    const float* a1_bp   = (const float*)d_in[7];
    const float* m1_b1   = (const float*)d_in[9];
    const float* m1_b2   = (const float*)d_in[11];
    const float* a2_bp   = (const float*)d_in[15];
    const float* m2_b1   = (const float*)d_in[17];
    const float* m2_b2   = (const float*)d_in[19];

    float* out   = (float*)d_out;
    float* out_c = out;
    float* out_q = out + (size_t)CRQ * CE;

    __half *cn, *Qp, *KVp, *AOp, *tp, *tq, *Hp, *W;
    float *cp;
    cudaGetSymbolAddress((void**)&cn,  g_cn);
    cudaGetSymbolAddress((void**)&Qp,  g_Q);
    cudaGetSymbolAddress((void**)&KVp, g_KV);
    cudaGetSymbolAddress((void**)&AOp, g_AO);
    cudaGetSymbolAddress((void**)&cp,  g_c);
    cudaGetSymbolAddress((void**)&tp,  g_t);
    cudaGetSymbolAddress((void**)&tq,  g_tq);
    cudaGetSymbolAddress((void**)&Hp,  g_H);
    cudaGetSymbolAddress((void**)&W,   g_W);

    cudaFuncSetAttribute(fattn_kernel, cudaFuncAttributeMaxDynamicSharedMemorySize, FA_SMEM);

    // weights -> fp16, one launch
    const int widx[10] = {4,5,6,8,10,12,13,14,16,18};
    const int wsz [10] = {CE*CD, CE*2*CD, CD*CE, CE*CHID, CHID*CE,
                          CE*CD, CE*2*CD, CD*CE, CE*CHID, CHID*CE};
    WArgs wa;
    __half* wptr[10];
    {
        size_t off = 0;
        int mx = 0;
        for (int i=0;i<10;i++){
            wptr[i] = W + off; off += wsz[i];
            wa.src[i] = (const float*)d_in[widx[i]];
            wa.dst[i] = wptr[i];
            wa.sz[i]  = wsz[i];
            if (wsz[i] > mx) mx = wsz[i];
        }
        round_all<<<dim3((mx+255)/256, 10), 256>>>(wa);
    }
    __half* a1_wq = wptr[0];  __half* a1_wkv = wptr[1]; __half* a1_wp = wptr[2];
    __half* m1_w1 = wptr[3];  __half* m1_w2  = wptr[4];
    __half* a2_wq = wptr[5];  __half* a2_wkv = wptr[6]; __half* a2_wp = wptr[7];
    __half* m2_w1 = wptr[8];  __half* m2_w2  = wptr[9];

    ln_kernel<<<CRQ, 256>>>(query,   ln_w, ln_b, out_q, tq);
    ln_kernel<<<CRC, 256>>>(context, ln_w, ln_b, nullptr, cn);

    // ---- block 1: cross-attention over context (m=2048) ----
    gemm_kernel<<<dim3(3, 64),  256>>>(tq, a1_wq,  nullptr, Qp,  nullptr, nullptr, CRQ, CD,   CE, 0);
    gemm_kernel<<<dim3(6, 128), 256>>>(cn, a1_wkv, nullptr, KVp, nullptr, nullptr, CRC, 2*CD, CE, 0);
    fattn_kernel<<<dim3(CNQ/128, CB*CNH), 256, FA_SMEM>>>(Qp, KVp, AOp, CNC);
    gemm_kernel<<<dim3(6, 64), 256>>>(AOp, a1_wp, cp, nullptr, a1_bp, nullptr, CRQ, CE, CD, 0);

    // ---- MLP 1 (with residual) ----
    ln_kernel<<<CRQ, 256>>>(cp, ln_w, ln_b, nullptr, tp);
    gemm_kernel<<<dim3(24, 64), 256>>>(tp, m1_w1, nullptr, Hp, m1_b1, nullptr, CRQ, CHID, CE,   1);
    gemm_kernel<<<dim3(6, 64),  256>>>(Hp, m1_w2, cp, nullptr, m1_b2, cp,      CRQ, CE,   CHID, 0);

    // ---- block 2: cross-attention over c (m=1024), residual ----
    ln_kernel<<<CRQ, 256>>>(cp, ln_w, ln_b, nullptr, tp);
    gemm_kernel<<<dim3(3, 64), 256>>>(tq, a2_wq,  nullptr, Qp,  nullptr, nullptr, CRQ, CD,   CE, 0);
    gemm_kernel<<<dim3(6, 64), 256>>>(tp, a2_wkv, nullptr, KVp, nullptr, nullptr, CRQ, 2*CD, CE, 0);
    fattn_kernel<<<dim3(CNQ/128, CB*CNH), 256, FA_SMEM>>>(Qp, KVp, AOp, CNQ);
    gemm_kernel<<<dim3(6, 64), 256>>>(AOp, a2_wp, cp, nullptr, a2_bp, cp, CRQ, CE, CD, 0);

    // ---- MLP 2 (with residual), final write straight into d_out ----
    ln_kernel<<<CRQ, 256>>>(cp, ln_w, ln_b, nullptr, tp);
    gemm_kernel<<<dim3(24, 64), 256>>>(tp, m2_w1, nullptr, Hp, m2_b1, nullptr, CRQ, CHID, CE,   1);
    gemm_kernel<<<dim3(6, 64),  256>>>(Hp, m2_w2, out_c, nullptr, m2_b2, cp,   CRQ, CE,   CHID, 0);
}

// round 7
// speedup vs baseline: 4.4734x; 1.0565x over previous
#include <cuda_runtime.h>
#include <cuda_fp16.h>
#include <cstdint>

#define CB   8
#define CNQ  1024
#define CNC  2048
#define CE   768
#define CD   384
#define CNH  6
#define CHD  64
#define CHID 3072
#define CRQ  (CB*CNQ)   /* 8192  */
#define CRC  (CB*CNC)   /* 16384 */

// ---------------- scratch (no cudaMalloc allowed) ----------------
__device__ __half g_cn[(size_t)CRC*CE];
__device__ __half g_Q [(size_t)CRQ*CD];
__device__ __half g_KV[(size_t)CRC*2*CD];
__device__ __half g_AO[(size_t)CRQ*CD];
__device__ float  g_c [(size_t)CRQ*CE];
__device__ __half g_t [(size_t)CRQ*CE];
__device__ __half g_tq[(size_t)CRQ*CE];
__device__ __half g_H [(size_t)CRQ*CHID];
__device__ __half g_W [11796480];   // all weights, fp16-rounded

// ---------------- helpers ----------------
__device__ __forceinline__ void cp16(void* smem, const void* gmem) {
    unsigned s = (unsigned)__cvta_generic_to_shared(smem);
    asm volatile("cp.async.ca.shared.global [%0], [%1], 16;\n" :: "r"(s), "l"(gmem));
}
__device__ __forceinline__ void cp_commit() {
    asm volatile("cp.async.commit_group;\n");
}
template<int N>
__device__ __forceinline__ void cp_wait() {
    asm volatile("cp.async.wait_group %0;\n" :: "n"(N));
}
__device__ __forceinline__ void ldsm_x4(uint32_t& r0, uint32_t& r1, uint32_t& r2, uint32_t& r3, uint32_t a) {
    asm volatile("ldmatrix.sync.aligned.m8n8.x4.shared.b16 {%0,%1,%2,%3}, [%4];"
                 : "=r"(r0), "=r"(r1), "=r"(r2), "=r"(r3) : "r"(a));
}
__device__ __forceinline__ void ldsm_x4t(uint32_t& r0, uint32_t& r1, uint32_t& r2, uint32_t& r3, uint32_t a) {
    asm volatile("ldmatrix.sync.aligned.m8n8.x4.trans.shared.b16 {%0,%1,%2,%3}, [%4];"
                 : "=r"(r0), "=r"(r1), "=r"(r2), "=r"(r3) : "r"(a));
}
__device__ __forceinline__ void mma16816(float* c, const uint32_t* a, const uint32_t* b) {
    asm volatile("mma.sync.aligned.m16n8k16.row.col.f32.f16.f16.f32 "
                 "{%0,%1,%2,%3}, {%4,%5,%6,%7}, {%8,%9}, {%0,%1,%2,%3};"
                 : "+f"(c[0]), "+f"(c[1]), "+f"(c[2]), "+f"(c[3])
                 : "r"(a[0]), "r"(a[1]), "r"(a[2]), "r"(a[3]), "r"(b[0]), "r"(b[1]));
}
__device__ __forceinline__ uint32_t pack2(float a, float b) {
    __half2 h = __floats2half2_rn(a, b);
    return *(uint32_t*)&h;
}
__device__ __forceinline__ float gelu_f(float v) {
    return 0.5f*v*(1.0f + erff(v*0.70710678118654752f));
}

// ---------------- weight round to fp16 (all weights, one launch) ----------------
struct WArgs { const float* src[10]; __half* dst[10]; int sz[10]; };
__global__ void round_all(WArgs a)
{
    int w = blockIdx.y;
    int i = (blockIdx.x << 8) + threadIdx.x;
    if (i < a.sz[w]) a.dst[w][i] = __float2half(a.src[w][i]);
}

// ---------------- LayerNorm: one block per 768-wide row ----------------
__global__ void ln_kernel(const float* __restrict__ x, const float* __restrict__ w,
                          const float* __restrict__ b, float* __restrict__ y,
                          __half* __restrict__ y2)
{
    __shared__ float sm[8];
    size_t row = blockIdx.x;
    const float* xr = x + row * CE;
    int t = threadIdx.x;
    float v0 = xr[t], v1 = xr[t+256], v2 = xr[t+512];

    float s = v0 + v1 + v2;
    #pragma unroll
    for (int o=16;o;o>>=1) s += __shfl_xor_sync(0xffffffffu, s, o);
    if ((t&31)==0) sm[t>>5] = s;
    __syncthreads();
    if (t < 32) {
        float z = (t<8) ? sm[t] : 0.f;
        #pragma unroll
        for (int o=4;o;o>>=1) z += __shfl_xor_sync(0xffffffffu, z, o);
        if (t==0) sm[0] = z;
    }
    __syncthreads();
    float mean = sm[0] * (1.0f/CE);
    __syncthreads();

    float d0 = v0-mean, d1 = v1-mean, d2 = v2-mean;
    float q = d0*d0 + d1*d1 + d2*d2;
    #pragma unroll
    for (int o=16;o;o>>=1) q += __shfl_xor_sync(0xffffffffu, q, o);
    if ((t&31)==0) sm[t>>5] = q;
    __syncthreads();
    if (t < 32) {
        float z = (t<8) ? sm[t] : 0.f;
        #pragma unroll
        for (int o=4;o;o>>=1) z += __shfl_xor_sync(0xffffffffu, z, o);
        if (t==0) sm[0] = z;
    }
    __syncthreads();
    float inv = rsqrtf(sm[0]*(1.0f/CE) + 1e-5f);

    float r0 = d0*inv*w[t]     + b[t];
    float r1 = d1*inv*w[t+256] + b[t+256];
    float r2 = d2*inv*w[t+512] + b[t+512];
    if (y)  { float* yr = y + row*CE;
        yr[t] = r0; yr[t+256] = r1; yr[t+512] = r2; }
    if (y2) { __half* yr = y2 + row*CE;
        yr[t] = __float2half(r0); yr[t+256] = __float2half(r1); yr[t+512] = __float2half(r2); }
}

// ---------------- fp16 GEMM 128x128x32, 4 warps, warp tile 64x64 ----------------
// raw mma.m16n8k16 + ldmatrix; 3-stage cp.async; register-direct epilogue.
// C = A@B (+bias,+gelu). Ch!=null -> fp16 out; else fp32 to Cf (+res).
__global__ void __launch_bounds__(128) gemm_kernel(
    const __half* __restrict__ A, const __half* __restrict__ Bm,
    float* __restrict__ Cf, __half* __restrict__ Ch,
    const float* __restrict__ bias, const float* __restrict__ res,
    int M, int N, int K, int gelu)
{
    __shared__ __half As[3][128*40];   // 128 rows x 32 cols (+8 pad)
    __shared__ __half Bs[3][32*136];   // 32 rows(k) x 128 cols (+8 pad)
    int tid = threadIdx.x, warp = tid >> 5, lane = tid & 31;
    int bm = blockIdx.y << 7, bn = blockIdx.x << 7;
    int wm = warp & 1, wn = warp >> 1;

    float acc[4][8][4];
    #pragma unroll
    for (int i=0;i<4;i++)
        #pragma unroll
        for (int t=0;t<8;t++){ acc[i][t][0]=0.f; acc[i][t][1]=0.f; acc[i][t][2]=0.f; acc[i][t][3]=0.f; }

    const __half* Ab = A + (size_t)bm * K;
    const __half* Bb = Bm + bn;
    int KT = K >> 5;

    auto issue = [&](int s, int kt){
        int k0 = kt << 5;
        #pragma unroll
        for (int p=0;p<4;p++){
            int id = tid + (p<<7);
            int r = id>>2, c = (id&3)<<3;
            cp16(&As[s][r*40 + c], Ab + (size_t)r*K + k0 + c);
        }
        #pragma unroll
        for (int p=0;p<4;p++){
            int id = tid + (p<<7);
            int r = id>>4, c = (id&15)<<3;
            cp16(&Bs[s][r*136 + c], Bb + (size_t)(k0+r)*N + c);
        }
        cp_commit();
    };

    issue(0, 0);
    issue(1, KT > 1 ? 1 : 0);

    int li = lane & 7, b3 = (lane>>3)&1, b4 = (lane>>4)&1;

    for (int kt = 0; kt < KT; kt++) {
        int cur = kt % 3;
        if (kt == KT-1) cp_wait<0>(); else cp_wait<1>();
        __syncthreads();

        uint32_t abase = (uint32_t)__cvta_generic_to_shared(&As[cur][0]);
        uint32_t bbase = (uint32_t)__cvta_generic_to_shared(&Bs[cur][0]);
        #pragma unroll
        for (int ks=0; ks<2; ks++) {
            uint32_t af[4][4];
            #pragma unroll
            for (int i=0;i<4;i++){
                uint32_t addr = abase + (uint32_t)((( (wm*64 + i*16 + b3*8 + li)*40 ) + ks*16 + b4*8) << 1);
                ldsm_x4(af[i][0], af[i][1], af[i][2], af[i][3], addr);
            }
            #pragma unroll
            for (int t=0;t<4;t++){
                uint32_t r0,r1,r2,r3;
                uint32_t addr = bbase + (uint32_t)((( (ks*16 + b3*8 + li)*136 ) + wn*64 + t*16 + b4*8) << 1);
                ldsm_x4t(r0,r1,r2,r3, addr);
                uint32_t bb0[2] = {r0,r1}, bb1[2] = {r2,r3};
                #pragma unroll
                for (int i=0;i<4;i++){
                    mma16816(acc[i][2*t],   af[i], bb0);
                    mma16816(acc[i][2*t+1], af[i], bb1);
                }
            }
        }
        if (kt + 2 < KT) issue((kt+2)%3, kt+2);
    }

    // register-direct epilogue
    int g = lane>>2, cq = lane&3;
    #pragma unroll
    for (int i=0;i<4;i++){
        int r0 = bm + wm*64 + i*16 + g;
        size_t o0 = (size_t)r0 * N;
        size_t o1 = (size_t)(r0+8) * N;
        #pragma unroll
        for (int t=0;t<8;t++){
            int c0 = bn + wn*64 + t*8 + cq*2;
            float v0 = acc[i][t][0], v1 = acc[i][t][1];
            float v2 = acc[i][t][2], v3 = acc[i][t][3];
            if (bias){ float bb0 = bias[c0], bb1 = bias[c0+1];
                       v0 += bb0; v1 += bb1; v2 += bb0; v3 += bb1; }
            if (gelu){ v0 = gelu_f(v0); v1 = gelu_f(v1); v2 = gelu_f(v2); v3 = gelu_f(v3); }
            if (Ch){
                *(__half2*)(Ch + o0 + c0) = __floats2half2_rn(v0, v1);
                *(__half2*)(Ch + o1 + c0) = __floats2half2_rn(v2, v3);
            } else {
                if (res){
                    float2 ra = *(const float2*)(res + o0 + c0);
                    float2 rb = *(const float2*)(res + o1 + c0);
                    v0 += ra.x; v1 += ra.y; v2 += rb.x; v3 += rb.y;
                }
                *(float2*)(Cf + o0 + c0) = make_float2(v0, v1);
                *(float2*)(Cf + o1 + c0) = make_float2(v2, v3);
            }
        }
    }
}

// ---------------- flash attention: fused QK^T -> softmax -> PV ----------------
#define FA_SMEM 92160
__global__ void __launch_bounds__(256) fattn_kernel(
    const __half* __restrict__ Q, const __half* __restrict__ KV,
    __half* __restrict__ AO, int ctx)
{
    extern __shared__ __align__(128) __half fsm[];
    __half* Qs  = fsm;                 // 128 x 72
    __half* Ksb[2] = { fsm + 9216,  fsm + 2*9216 };
    __half* Vsb[2] = { fsm + 3*9216, fsm + 4*9216 };

    int bh = blockIdx.y, b = bh / CNH, h = bh % CNH;
    int i0 = blockIdx.x << 7;
    const __half* Qb = Q  + (size_t)b*CNQ*CD + h*CHD;
    const __half* Kb = KV + (size_t)b*ctx*(2*CD) + h*CHD;
    const __half* Vb = Kb + CD;
    int tid = threadIdx.x, warp = tid>>5, lane = tid&31;

    #pragma unroll
    for (int p=0;p<4;p++){
        int id = tid + (p<<8); int r = id>>3, c = (id&7)<<3;
        cp16(&Qs[r*72 + c], Qb + (size_t)(i0+r)*CD + c);
    }
    cp_commit();

    auto load_kv = [&](int s, int j){
        const __half* Kc = Kb + (size_t)(j<<7)*(2*CD);
        const __half* Vc = Vb + (size_t)(j<<7)*(2*CD);
        #pragma unroll
        for (int p=0;p<4;p++){
            int id = tid + (p<<8); int r = id>>3, c = (id&7)<<3;
            cp16(&Ksb[s][r*72 + c], Kc + (size_t)r*(2*CD) + c);
        }
        #pragma unroll
        for (int p=0;p<4;p++){
            int id = tid + (p<<8); int r = id>>3, c = (id&7)<<3;
            cp16(&Vsb[s][r*72 + c], Vc + (size_t)r*(2*CD) + c);
        }
        cp_commit();
    };
    load_kv(0, 0);

    int li = lane & 7, b3 = (lane>>3)&1, b4 = (lane>>4)&1;
    uint32_t qaddr = (uint32_t)__cvta_generic_to_shared(Qs)
                   + (uint32_t)(((warp*16 + b3*8 + li)*72 + b4*8)*2);
    uint32_t koff = (uint32_t)(((b4*8 + li)*72 + b3*8)*2);
    uint32_t voff = (uint32_t)(((b3*8 + li)*72 + b4*8)*2);

    cp_wait<1>();
    __syncthreads();

    uint32_t qa[4][4];
    #pragma unroll
    for (int s=0;s<4;s++)
        ldsm_x4(qa[s][0], qa[s][1], qa[s][2], qa[s][3], qaddr + s*32);

    float m0=-1e30f, m1=-1e30f, l0=0.f, l1=0.f;
    float o[8][4];
    #pragma unroll
    for (int d=0; d<8; d++){ o[d][0]=0.f; o[d][1]=0.f; o[d][2]=0.f; o[d][3]=0.f; }

    const float SC2 = 0.125f * 1.4426950408889634f;
    int nc = ctx >> 7;

    for (int j=0; j<nc; j++){
        int cur = j & 1;
        if (j+1 < nc){ load_kv(cur^1, j+1); cp_wait<1>(); }
        else         { cp_wait<0>(); }
        __syncthreads();

        uint32_t kb = (uint32_t)__cvta_generic_to_shared(Ksb[cur]) + koff;
        uint32_t vbs = (uint32_t)__cvta_generic_to_shared(Vsb[cur]) + voff;

        float sc[16][4];
        #pragma unroll
        for (int t=0;t<16;t++){ sc[t][0]=0.f; sc[t][1]=0.f; sc[t][2]=0.f; sc[t][3]=0.f; }
        #pragma unroll
        for (int tp=0; tp<8; tp++){
            #pragma unroll
            for (int s=0;s<4;s++){
                uint32_t r0,r1,r2,r3;
                ldsm_x4(r0,r1,r2,r3, kb + tp*16*144 + s*32);
                uint32_t bb0[2] = {r0,r1}, bb1[2] = {r2,r3};
                mma16816(sc[2*tp],   qa[s], bb0);
                mma16816(sc[2*tp+1], qa[s], bb1);
            }
        }

        float mx0 = -1e30f, mx1 = -1e30f;
        #pragma unroll
        for (int t=0;t<16;t++){
            mx0 = fmaxf(mx0, fmaxf(sc[t][0], sc[t][1]));
            mx1 = fmaxf(mx1, fmaxf(sc[t][2], sc[t][3]));
        }
        mx0 = fmaxf(mx0, __shfl_xor_sync(0xffffffffu, mx0, 1));
        mx0 = fmaxf(mx0, __shfl_xor_sync(0xffffffffu, mx0, 2));
        mx1 = fmaxf(mx1, __shfl_xor_sync(0xffffffffu, mx1, 1));
        mx1 = fmaxf(mx1, __shfl_xor_sync(0xffffffffu, mx1, 2));
        float nm0 = fmaxf(m0, mx0), nm1 = fmaxf(m1, mx1);
        float r0f = exp2f((m0-nm0)*SC2), r1f = exp2f((m1-nm1)*SC2);
        m0 = nm0; m1 = nm1;
        float s0 = 0.f, s1 = 0.f;
        #pragma unroll
        for (int t=0;t<16;t++){
            sc[t][0] = exp2f((sc[t][0]-nm0)*SC2);
            sc[t][1] = exp2f((sc[t][1]-nm0)*SC2);
            sc[t][2] = exp2f((sc[t][2]-nm1)*SC2);
            sc[t][3] = exp2f((sc[t][3]-nm1)*SC2);
            s0 += sc[t][0] + sc[t][1];
            s1 += sc[t][2] + sc[t][3];
        }
        s0 += __shfl_xor_sync(0xffffffffu, s0, 1);
        s0 += __shfl_xor_sync(0xffffffffu, s0, 2);
        s1 += __shfl_xor_sync(0xffffffffu, s1, 1);
        s1 += __shfl_xor_sync(0xffffffffu, s1, 2);
        l0 = l0*r0f + s0; l1 = l1*r1f + s1;
        #pragma unroll
        for (int d=0; d<8; d++){
            o[d][0]*=r0f; o[d][1]*=r0f; o[d][2]*=r1f; o[d][3]*=r1f;
        }

        #pragma unroll
        for (int kc=0; kc<8; kc++){
            uint32_t pa[4];
            pa[0] = pack2(sc[2*kc][0],   sc[2*kc][1]);
            pa[1] = pack2(sc[2*kc][2],   sc[2*kc][3]);
            pa[2] = pack2(sc[2*kc+1][0], sc[2*kc+1][1]);
            pa[3] = pack2(sc[2*kc+1][2], sc[2*kc+1][3]);
            #pragma unroll
            for (int dp=0; dp<4; dp++){
                uint32_t r0,r1,r2,r3;
                ldsm_x4t(r0,r1,r2,r3, vbs + kc*16*144 + dp*32);
                uint32_t bb0[2] = {r0,r1}, bb1[2] = {r2,r3};
                mma16816(o[2*dp],   pa, bb0);
                mma16816(o[2*dp+1], pa, bb1);
            }
        }
        __syncthreads();
    }

    float inv0 = 1.f/l0, inv1 = 1.f/l1;
    int g = lane>>2, cq = lane&3;
    int row0 = i0 + warp*16 + g;
    __half2* O0 = (__half2*)(AO + ((size_t)b*CNQ + row0)*CD + h*CHD + cq*2);
    __half2* O1 = (__half2*)(AO + ((size_t)b*CNQ + row0+8)*CD + h*CHD + cq*2);
    #pragma unroll
    for (int d=0; d<8; d++){
        O0[d*4] = __floats2half2_rn(o[d][0]*inv0, o[d][1]*inv0);
        O1[d*4] = __floats2half2_rn(o[d][2]*inv1, o[d][3]*inv1);
    }
}

// ---------------- driver ----------------
extern "C" void kernel_launch(void* const* d_in, const int* in_sizes, int n_in,
                              void* d_out, int out_size)
{
    const float* query   = (const float*)d_in[0];
    const float* context = (const float*)d_in[1];
    const float* ln_w    = (const float*)d_in[2];
    const float* ln_b    = (const float*)d_in[3];
    const float* a1_bp   = (const float*)d_in[7];
    const float* m1_b1   = (const float*)d_in[9];
    const float* m1_b2   = (const float*)d_in[11];
    const float* a2_bp   = (const float*)d_in[15];
    const float* m2_b1   = (const float*)d_in[17];
    const float* m2_b2   = (const float*)d_in[19];

    float* out   = (float*)d_out;
    float* out_c = out;
    float* out_q = out + (size_t)CRQ * CE;

    __half *cn, *Qp, *KVp, *AOp, *tp, *tq, *Hp, *W;
    float *cp;
    cudaGetSymbolAddress((void**)&cn,  g_cn);
    cudaGetSymbolAddress((void**)&Qp,  g_Q);
    cudaGetSymbolAddress((void**)&KVp, g_KV);
    cudaGetSymbolAddress((void**)&AOp, g_AO);
    cudaGetSymbolAddress((void**)&cp,  g_c);
    cudaGetSymbolAddress((void**)&tp,  g_t);
    cudaGetSymbolAddress((void**)&tq,  g_tq);
    cudaGetSymbolAddress((void**)&Hp,  g_H);
    cudaGetSymbolAddress((void**)&W,   g_W);

    cudaFuncSetAttribute(fattn_kernel, cudaFuncAttributeMaxDynamicSharedMemorySize, FA_SMEM);

    const int widx[10] = {4,5,6,8,10,12,13,14,16,18};
    const int wsz [10] = {CE*CD, CE*2*CD, CD*CE, CE*CHID, CHID*CE,
                          CE*CD, CE*2*CD, CD*CE, CE*CHID, CHID*CE};
    WArgs wa;
    __half* wptr[10];
    {
        size_t off = 0;
        int mx = 0;
        for (int i=0;i<10;i++){
            wptr[i] = W + off; off += wsz[i];
            wa.src[i] = (const float*)d_in[widx[i]];
            wa.dst[i] = wptr[i];
            wa.sz[i]  = wsz[i];
            if (wsz[i] > mx) mx = wsz[i];
        }
        round_all<<<dim3((mx+255)/256, 10), 256>>>(wa);
    }
    __half* a1_wq = wptr[0];  __half* a1_wkv = wptr[1]; __half* a1_wp = wptr[2];
    __half* m1_w1 = wptr[3];  __half* m1_w2  = wptr[4];
    __half* a2_wq = wptr[5];  __half* a2_wkv = wptr[6]; __half* a2_wp = wptr[7];
    __half* m2_w1 = wptr[8];  __half* m2_w2  = wptr[9];

    ln_kernel<<<CRQ, 256>>>(query,   ln_w, ln_b, out_q, tq);
    ln_kernel<<<CRC, 256>>>(context, ln_w, ln_b, nullptr, cn);

    // ---- block 1: cross-attention over context (m=2048) ----
    gemm_kernel<<<dim3(3, 64),  128>>>(tq, a1_wq,  nullptr, Qp,  nullptr, nullptr, CRQ, CD,   CE, 0);
    gemm_kernel<<<dim3(6, 128), 128>>>(cn, a1_wkv, nullptr, KVp, nullptr, nullptr, CRC, 2*CD, CE, 0);
    fattn_kernel<<<dim3(CNQ/128, CB*CNH), 256, FA_SMEM>>>(Qp, KVp, AOp, CNC);
    gemm_kernel<<<dim3(6, 64), 128>>>(AOp, a1_wp, cp, nullptr, a1_bp, nullptr, CRQ, CE, CD, 0);

    // ---- MLP 1 (with residual) ----
    ln_kernel<<<CRQ, 256>>>(cp, ln_w, ln_b, nullptr, tp);
    gemm_kernel<<<dim3(24, 64), 128>>>(tp, m1_w1, nullptr, Hp, m1_b1, nullptr, CRQ, CHID, CE,   1);
    gemm_kernel<<<dim3(6, 64),  128>>>(Hp, m1_w2, cp, nullptr, m1_b2, cp,      CRQ, CE,   CHID, 0);

    // ---- block 2: cross-attention over c (m=1024), residual ----
    ln_kernel<<<CRQ, 256>>>(cp, ln_w, ln_b, nullptr, tp);
    gemm_kernel<<<dim3(3, 64), 128>>>(tq, a2_wq,  nullptr, Qp,  nullptr, nullptr, CRQ, CD,   CE, 0);
    gemm_kernel<<<dim3(6, 64), 128>>>(tp, a2_wkv, nullptr, KVp, nullptr, nullptr, CRQ, 2*CD, CE, 0);
    fattn_kernel<<<dim3(CNQ/128, CB*CNH), 256, FA_SMEM>>>(Qp, KVp, AOp, CNQ);
    gemm_kernel<<<dim3(6, 64), 128>>>(AOp, a2_wp, cp, nullptr, a2_bp, cp, CRQ, CE, CD, 0);

    // ---- MLP 2 (with residual), final write straight into d_out ----
    ln_kernel<<<CRQ, 256>>>(cp, ln_w, ln_b, nullptr, tp);
    gemm_kernel<<<dim3(24, 64), 128>>>(tp, m2_w1, nullptr, Hp, m2_b1, nullptr, CRQ, CHID, CE,   1);
    gemm_kernel<<<dim3(6, 64),  128>>>(Hp, m2_w2, out_c, nullptr, m2_b2, cp,   CRQ, CE,   CHID, 0);
}

// round 8
// speedup vs baseline: 4.5452x; 1.0161x over previous
#include <cuda_runtime.h>
#include <cuda_fp16.h>
#include <cstdint>

#define CB   8
#define CNQ  1024
#define CNC  2048
#define CE   768
#define CD   384
#define CNH  6
#define CHD  64
#define CHID 3072
#define CRQ  (CB*CNQ)   /* 8192  */
#define CRC  (CB*CNC)   /* 16384 */

// ---------------- scratch (no cudaMalloc allowed) ----------------
__device__ __half g_cn[(size_t)CRC*CE];
__device__ __half g_Q [(size_t)CRQ*CD];
__device__ __half g_KV[(size_t)CRC*2*CD];
__device__ __half g_AO[(size_t)CRQ*CD];
__device__ float  g_c [(size_t)CRQ*CE];
__device__ __half g_t [(size_t)CRQ*CE];
__device__ __half g_tq[(size_t)CRQ*CE];
__device__ __half g_H [(size_t)CRQ*CHID];
__device__ __half g_W [11796480];   // all weights, fp16-rounded

// ---------------- helpers ----------------
__device__ __forceinline__ void cp16(void* smem, const void* gmem) {
    unsigned s = (unsigned)__cvta_generic_to_shared(smem);
    asm volatile("cp.async.ca.shared.global [%0], [%1], 16;\n" :: "r"(s), "l"(gmem));
}
__device__ __forceinline__ void cp_commit() {
    asm volatile("cp.async.commit_group;\n");
}
template<int N>
__device__ __forceinline__ void cp_wait() {
    asm volatile("cp.async.wait_group %0;\n" :: "n"(N));
}
__device__ __forceinline__ void ldsm_x4(uint32_t& r0, uint32_t& r1, uint32_t& r2, uint32_t& r3, uint32_t a) {
    asm volatile("ldmatrix.sync.aligned.m8n8.x4.shared.b16 {%0,%1,%2,%3}, [%4];"
                 : "=r"(r0), "=r"(r1), "=r"(r2), "=r"(r3) : "r"(a));
}
__device__ __forceinline__ void ldsm_x4t(uint32_t& r0, uint32_t& r1, uint32_t& r2, uint32_t& r3, uint32_t a) {
    asm volatile("ldmatrix.sync.aligned.m8n8.x4.trans.shared.b16 {%0,%1,%2,%3}, [%4];"
                 : "=r"(r0), "=r"(r1), "=r"(r2), "=r"(r3) : "r"(a));
}
__device__ __forceinline__ void mma16816(float* c, const uint32_t* a, const uint32_t* b) {
    asm volatile("mma.sync.aligned.m16n8k16.row.col.f32.f16.f16.f32 "
                 "{%0,%1,%2,%3}, {%4,%5,%6,%7}, {%8,%9}, {%0,%1,%2,%3};"
                 : "+f"(c[0]), "+f"(c[1]), "+f"(c[2]), "+f"(c[3])
                 : "r"(a[0]), "r"(a[1]), "r"(a[2]), "r"(a[3]), "r"(b[0]), "r"(b[1]));
}
__device__ __forceinline__ uint32_t pack2(float a, float b) {
    __half2 h = __floats2half2_rn(a, b);
    return *(uint32_t*)&h;
}
__device__ __forceinline__ float gelu_f(float v) {
    return 0.5f*v*(1.0f + erff(v*0.70710678118654752f));
}

// ---------------- weight round to fp16 (all weights, one launch) ----------------
struct WArgs { const float* src[10]; __half* dst[10]; int sz[10]; };
__global__ void round_all(WArgs a)
{
    int w = blockIdx.y;
    int i = (blockIdx.x << 8) + threadIdx.x;
    if (i < a.sz[w]) a.dst[w][i] = __float2half(a.src[w][i]);
}

// ---------------- LayerNorm: one block per 768-wide row ----------------
__global__ void ln_kernel(const float* __restrict__ x, const float* __restrict__ w,
                          const float* __restrict__ b, float* __restrict__ y,
                          __half* __restrict__ y2)
{
    __shared__ float sm[8];
    size_t row = blockIdx.x;
    const float* xr = x + row * CE;
    int t = threadIdx.x;
    float v0 = xr[t], v1 = xr[t+256], v2 = xr[t+512];

    float s = v0 + v1 + v2;
    #pragma unroll
    for (int o=16;o;o>>=1) s += __shfl_xor_sync(0xffffffffu, s, o);
    if ((t&31)==0) sm[t>>5] = s;
    __syncthreads();
    if (t < 32) {
        float z = (t<8) ? sm[t] : 0.f;
        #pragma unroll
        for (int o=4;o;o>>=1) z += __shfl_xor_sync(0xffffffffu, z, o);
        if (t==0) sm[0] = z;
    }
    __syncthreads();
    float mean = sm[0] * (1.0f/CE);
    __syncthreads();

    float d0 = v0-mean, d1 = v1-mean, d2 = v2-mean;
    float q = d0*d0 + d1*d1 + d2*d2;
    #pragma unroll
    for (int o=16;o;o>>=1) q += __shfl_xor_sync(0xffffffffu, q, o);
    if ((t&31)==0) sm[t>>5] = q;
    __syncthreads();
    if (t < 32) {
        float z = (t<8) ? sm[t] : 0.f;
        #pragma unroll
        for (int o=4;o;o>>=1) z += __shfl_xor_sync(0xffffffffu, z, o);
        if (t==0) sm[0] = z;
    }
    __syncthreads();
    float inv = rsqrtf(sm[0]*(1.0f/CE) + 1e-5f);

    float r0 = d0*inv*w[t]     + b[t];
    float r1 = d1*inv*w[t+256] + b[t+256];
    float r2 = d2*inv*w[t+512] + b[t+512];
    if (y)  { float* yr = y + row*CE;
        yr[t] = r0; yr[t+256] = r1; yr[t+512] = r2; }
    if (y2) { __half* yr = y2 + row*CE;
        yr[t] = __float2half(r0); yr[t+256] = __float2half(r1); yr[t+512] = __float2half(r2); }
}

// ---------------- fp16 GEMM 128x128x32, 8 warps, warp tile 64x32 ----------------
// raw mma.m16n8k16 + ldmatrix; 3-stage cp.async; register-direct epilogue.
// C = A@B (+bias,+gelu). Ch!=null -> fp16 out; else fp32 to Cf (+res).
__global__ void __launch_bounds__(256, 2) gemm_kernel(
    const __half* __restrict__ A, const __half* __restrict__ Bm,
    float* __restrict__ Cf, __half* __restrict__ Ch,
    const float* __restrict__ bias, const float* __restrict__ res,
    int M, int N, int K, int gelu)
{
    __shared__ __half As[3][128*40];   // 128 rows x 32 cols (+8 pad)
    __shared__ __half Bs[3][32*136];   // 32 rows(k) x 128 cols (+8 pad)
    int tid = threadIdx.x, warp = tid >> 5, lane = tid & 31;
    int bm = blockIdx.y << 7, bn = blockIdx.x << 7;
    int wm = warp & 1, wn = warp >> 1;          // 2 x 4 warp grid, warp tile 64x32

    float acc[4][4][4];
    #pragma unroll
    for (int i=0;i<4;i++)
        #pragma unroll
        for (int t=0;t<4;t++){ acc[i][t][0]=0.f; acc[i][t][1]=0.f; acc[i][t][2]=0.f; acc[i][t][3]=0.f; }

    const __half* Ab = A + (size_t)bm * K;
    const __half* Bb = Bm + bn;
    int KT = K >> 5;

    auto issue = [&](int s, int kt){
        int k0 = kt << 5;
        #pragma unroll
        for (int p=0;p<2;p++){
            int id = tid + (p<<8);
            int r = id>>2, c = (id&3)<<3;
            cp16(&As[s][r*40 + c], Ab + (size_t)r*K + k0 + c);
        }
        #pragma unroll
        for (int p=0;p<2;p++){
            int id = tid + (p<<8);
            int r = id>>4, c = (id&15)<<3;
            cp16(&Bs[s][r*136 + c], Bb + (size_t)(k0+r)*N + c);
        }
        cp_commit();
    };

    issue(0, 0);
    issue(1, KT > 1 ? 1 : 0);

    int li = lane & 7, b3 = (lane>>3)&1, b4 = (lane>>4)&1;

    for (int kt = 0; kt < KT; kt++) {
        int cur = kt % 3;
        if (kt == KT-1) cp_wait<0>(); else cp_wait<1>();
        __syncthreads();

        uint32_t abase = (uint32_t)__cvta_generic_to_shared(&As[cur][0]);
        uint32_t bbase = (uint32_t)__cvta_generic_to_shared(&Bs[cur][0]);
        #pragma unroll
        for (int ks=0; ks<2; ks++) {
            uint32_t af[4][4];
            #pragma unroll
            for (int i=0;i<4;i++){
                uint32_t addr = abase + (uint32_t)((( (wm*64 + i*16 + b3*8 + li)*40 ) + ks*16 + b4*8) << 1);
                ldsm_x4(af[i][0], af[i][1], af[i][2], af[i][3], addr);
            }
            #pragma unroll
            for (int t=0;t<2;t++){
                uint32_t r0,r1,r2,r3;
                uint32_t addr = bbase + (uint32_t)((( (ks*16 + b3*8 + li)*136 ) + wn*32 + t*16 + b4*8) << 1);
                ldsm_x4t(r0,r1,r2,r3, addr);
                uint32_t bb0[2] = {r0,r1}, bb1[2] = {r2,r3};
                #pragma unroll
                for (int i=0;i<4;i++){
                    mma16816(acc[i][2*t],   af[i], bb0);
                    mma16816(acc[i][2*t+1], af[i], bb1);
                }
            }
        }
        if (kt + 2 < KT) issue((kt+2)%3, kt+2);
    }

    // register-direct epilogue
    int g = lane>>2, cq = lane&3;
    #pragma unroll
    for (int i=0;i<4;i++){
        int r0 = bm + wm*64 + i*16 + g;
        size_t o0 = (size_t)r0 * N;
        size_t o1 = (size_t)(r0+8) * N;
        #pragma unroll
        for (int t=0;t<4;t++){
            int c0 = bn + wn*32 + t*8 + cq*2;
            float v0 = acc[i][t][0], v1 = acc[i][t][1];
            float v2 = acc[i][t][2], v3 = acc[i][t][3];
            if (bias){ float bb0 = bias[c0], bb1 = bias[c0+1];
                       v0 += bb0; v1 += bb1; v2 += bb0; v3 += bb1; }
            if (gelu){ v0 = gelu_f(v0); v1 = gelu_f(v1); v2 = gelu_f(v2); v3 = gelu_f(v3); }
            if (Ch){
                *(__half2*)(Ch + o0 + c0) = __floats2half2_rn(v0, v1);
                *(__half2*)(Ch + o1 + c0) = __floats2half2_rn(v2, v3);
            } else {
                if (res){
                    float2 ra = *(const float2*)(res + o0 + c0);
                    float2 rb = *(const float2*)(res + o1 + c0);
                    v0 += ra.x; v1 += ra.y; v2 += rb.x; v3 += rb.y;
                }
                *(float2*)(Cf + o0 + c0) = make_float2(v0, v1);
                *(float2*)(Cf + o1 + c0) = make_float2(v2, v3);
            }
        }
    }
}

// ---------------- flash attention: fused QK^T -> softmax -> PV ----------------
#define FA_SMEM 92160
__global__ void __launch_bounds__(256) fattn_kernel(
    const __half* __restrict__ Q, const __half* __restrict__ KV,
    __half* __restrict__ AO, int ctx)
{
    extern __shared__ __align__(128) __half fsm[];
    __half* Qs  = fsm;                 // 128 x 72
    __half* Ksb[2] = { fsm + 9216,  fsm + 2*9216 };
    __half* Vsb[2] = { fsm + 3*9216, fsm + 4*9216 };

    int bh = blockIdx.y, b = bh / CNH, h = bh % CNH;
    int i0 = blockIdx.x << 7;
    const __half* Qb = Q  + (size_t)b*CNQ*CD + h*CHD;
    const __half* Kb = KV + (size_t)b*ctx*(2*CD) + h*CHD;
    const __half* Vb = Kb + CD;
    int tid = threadIdx.x, warp = tid>>5, lane = tid&31;

    #pragma unroll
    for (int p=0;p<4;p++){
        int id = tid + (p<<8); int r = id>>3, c = (id&7)<<3;
        cp16(&Qs[r*72 + c], Qb + (size_t)(i0+r)*CD + c);
    }
    cp_commit();

    auto load_kv = [&](int s, int j){
        const __half* Kc = Kb + (size_t)(j<<7)*(2*CD);
        const __half* Vc = Vb + (size_t)(j<<7)*(2*CD);
        #pragma unroll
        for (int p=0;p<4;p++){
            int id = tid + (p<<8); int r = id>>3, c = (id&7)<<3;
            cp16(&Ksb[s][r*72 + c], Kc + (size_t)r*(2*CD) + c);
        }
        #pragma unroll
        for (int p=0;p<4;p++){
            int id = tid + (p<<8); int r = id>>3, c = (id&7)<<3;
            cp16(&Vsb[s][r*72 + c], Vc + (size_t)r*(2*CD) + c);
        }
        cp_commit();
    };
    load_kv(0, 0);

    int li = lane & 7, b3 = (lane>>3)&1, b4 = (lane>>4)&1;
    uint32_t qaddr = (uint32_t)__cvta_generic_to_shared(Qs)
                   + (uint32_t)(((warp*16 + b3*8 + li)*72 + b4*8)*2);
    uint32_t koff = (uint32_t)(((b4*8 + li)*72 + b3*8)*2);
    uint32_t voff = (uint32_t)(((b3*8 + li)*72 + b4*8)*2);

    cp_wait<1>();
    __syncthreads();

    uint32_t qa[4][4];
    #pragma unroll
    for (int s=0;s<4;s++)
        ldsm_x4(qa[s][0], qa[s][1], qa[s][2], qa[s][3], qaddr + s*32);

    float m0=-1e30f, m1=-1e30f, l0=0.f, l1=0.f;
    float o[8][4];
    #pragma unroll
    for (int d=0; d<8; d++){ o[d][0]=0.f; o[d][1]=0.f; o[d][2]=0.f; o[d][3]=0.f; }

    const float SC2 = 0.125f * 1.4426950408889634f;
    int nc = ctx >> 7;

    for (int j=0; j<nc; j++){
        int cur = j & 1;
        if (j+1 < nc){ load_kv(cur^1, j+1); cp_wait<1>(); }
        else         { cp_wait<0>(); }
        __syncthreads();

        uint32_t kb = (uint32_t)__cvta_generic_to_shared(Ksb[cur]) + koff;
        uint32_t vbs = (uint32_t)__cvta_generic_to_shared(Vsb[cur]) + voff;

        float sc[16][4];
        #pragma unroll
        for (int t=0;t<16;t++){ sc[t][0]=0.f; sc[t][1]=0.f; sc[t][2]=0.f; sc[t][3]=0.f; }
        #pragma unroll
        for (int tp=0; tp<8; tp++){
            #pragma unroll
            for (int s=0;s<4;s++){
                uint32_t r0,r1,r2,r3;
                ldsm_x4(r0,r1,r2,r3, kb + tp*16*144 + s*32);
                uint32_t bb0[2] = {r0,r1}, bb1[2] = {r2,r3};
                mma16816(sc[2*tp],   qa[s], bb0);
                mma16816(sc[2*tp+1], qa[s], bb1);
            }
        }

        float mx0 = -1e30f, mx1 = -1e30f;
        #pragma unroll
        for (int t=0;t<16;t++){
            mx0 = fmaxf(mx0, fmaxf(sc[t][0], sc[t][1]));
            mx1 = fmaxf(mx1, fmaxf(sc[t][2], sc[t][3]));
        }
        mx0 = fmaxf(mx0, __shfl_xor_sync(0xffffffffu, mx0, 1));
        mx0 = fmaxf(mx0, __shfl_xor_sync(0xffffffffu, mx0, 2));
        mx1 = fmaxf(mx1, __shfl_xor_sync(0xffffffffu, mx1, 1));
        mx1 = fmaxf(mx1, __shfl_xor_sync(0xffffffffu, mx1, 2));
        float nm0 = fmaxf(m0, mx0), nm1 = fmaxf(m1, mx1);
        float r0f = exp2f((m0-nm0)*SC2), r1f = exp2f((m1-nm1)*SC2);
        m0 = nm0; m1 = nm1;
        float s0 = 0.f, s1 = 0.f;
        #pragma unroll
        for (int t=0;t<16;t++){
            sc[t][0] = exp2f((sc[t][0]-nm0)*SC2);
            sc[t][1] = exp2f((sc[t][1]-nm0)*SC2);
            sc[t][2] = exp2f((sc[t][2]-nm1)*SC2);
            sc[t][3] = exp2f((sc[t][3]-nm1)*SC2);
            s0 += sc[t][0] + sc[t][1];
            s1 += sc[t][2] + sc[t][3];
        }
        s0 += __shfl_xor_sync(0xffffffffu, s0, 1);
        s0 += __shfl_xor_sync(0xffffffffu, s0, 2);
        s1 += __shfl_xor_sync(0xffffffffu, s1, 1);
        s1 += __shfl_xor_sync(0xffffffffu, s1, 2);
        l0 = l0*r0f + s0; l1 = l1*r1f + s1;
        #pragma unroll
        for (int d=0; d<8; d++){
            o[d][0]*=r0f; o[d][1]*=r0f; o[d][2]*=r1f; o[d][3]*=r1f;
        }

        #pragma unroll
        for (int kc=0; kc<8; kc++){
            uint32_t pa[4];
            pa[0] = pack2(sc[2*kc][0],   sc[2*kc][1]);
            pa[1] = pack2(sc[2*kc][2],   sc[2*kc][3]);
            pa[2] = pack2(sc[2*kc+1][0], sc[2*kc+1][1]);
            pa[3] = pack2(sc[2*kc+1][2], sc[2*kc+1][3]);
            #pragma unroll
            for (int dp=0; dp<4; dp++){
                uint32_t r0,r1,r2,r3;
                ldsm_x4t(r0,r1,r2,r3, vbs + kc*16*144 + dp*32);
                uint32_t bb0[2] = {r0,r1}, bb1[2] = {r2,r3};
                mma16816(o[2*dp],   pa, bb0);
                mma16816(o[2*dp+1], pa, bb1);
            }
        }
        __syncthreads();
    }

    float inv0 = 1.f/l0, inv1 = 1.f/l1;
    int g = lane>>2, cq = lane&3;
    int row0 = i0 + warp*16 + g;
    __half2* O0 = (__half2*)(AO + ((size_t)b*CNQ + row0)*CD + h*CHD + cq*2);
    __half2* O1 = (__half2*)(AO + ((size_t)b*CNQ + row0+8)*CD + h*CHD + cq*2);
    #pragma unroll
    for (int d=0; d<8; d++){
        O0[d*4] = __floats2half2_rn(o[d][0]*inv0, o[d][1]*inv0);
        O1[d*4] = __floats2half2_rn(o[d][2]*inv1, o[d][3]*inv1);
    }
}

// ---------------- driver ----------------
extern "C" void kernel_launch(void* const* d_in, const int* in_sizes, int n_in,
                              void* d_out, int out_size)
{
    const float* query   = (const float*)d_in[0];
    const float* context = (const float*)d_in[1];
    const float* ln_w    = (const float*)d_in[2];
    const float* ln_b    = (const float*)d_in[3];
    const float* a1_bp   = (const float*)d_in[7];
    const float* m1_b1   = (const float*)d_in[9];
    const float* m1_b2   = (const float*)d_in[11];
    const float* a2_bp   = (const float*)d_in[15];
    const float* m2_b1   = (const float*)d_in[17];
    const float* m2_b2   = (const float*)d_in[19];

    float* out   = (float*)d_out;
    float* out_c = out;
    float* out_q = out + (size_t)CRQ * CE;

    __half *cn, *Qp, *KVp, *AOp, *tp, *tq, *Hp, *W;
    float *cp;
    cudaGetSymbolAddress((void**)&cn,  g_cn);
    cudaGetSymbolAddress((void**)&Qp,  g_Q);
    cudaGetSymbolAddress((void**)&KVp, g_KV);
    cudaGetSymbolAddress((void**)&AOp, g_AO);
    cudaGetSymbolAddress((void**)&cp,  g_c);
    cudaGetSymbolAddress((void**)&tp,  g_t);
    cudaGetSymbolAddress((void**)&tq,  g_tq);
    cudaGetSymbolAddress((void**)&Hp,  g_H);
    cudaGetSymbolAddress((void**)&W,   g_W);

    cudaFuncSetAttribute(fattn_kernel, cudaFuncAttributeMaxDynamicSharedMemorySize, FA_SMEM);

    const int widx[10] = {4,5,6,8,10,12,13,14,16,18};
    const int wsz [10] = {CE*CD, CE*2*CD, CD*CE, CE*CHID, CHID*CE,
                          CE*CD, CE*2*CD, CD*CE, CE*CHID, CHID*CE};
    WArgs wa;
    __half* wptr[10];
    {
        size_t off = 0;
        int mx = 0;
        for (int i=0;i<10;i++){
            wptr[i] = W + off; off += wsz[i];
            wa.src[i] = (const float*)d_in[widx[i]];
            wa.dst[i] = wptr[i];
            wa.sz[i]  = wsz[i];
            if (wsz[i] > mx) mx = wsz[i];
        }
        round_all<<<dim3((mx+255)/256, 10), 256>>>(wa);
    }
    __half* a1_wq = wptr[0];  __half* a1_wkv = wptr[1]; __half* a1_wp = wptr[2];
    __half* m1_w1 = wptr[3];  __half* m1_w2  = wptr[4];
    __half* a2_wq = wptr[5];  __half* a2_wkv = wptr[6]; __half* a2_wp = wptr[7];
    __half* m2_w1 = wptr[8];  __half* m2_w2  = wptr[9];

    ln_kernel<<<CRQ, 256>>>(query,   ln_w, ln_b, out_q, tq);
    ln_kernel<<<CRC, 256>>>(context, ln_w, ln_b, nullptr, cn);

    // ---- block 1: cross-attention over context (m=2048) ----
    gemm_kernel<<<dim3(3, 64),  256>>>(tq, a1_wq,  nullptr, Qp,  nullptr, nullptr, CRQ, CD,   CE, 0);
    gemm_kernel<<<dim3(6, 128), 256>>>(cn, a1_wkv, nullptr, KVp, nullptr, nullptr, CRC, 2*CD, CE, 0);
    fattn_kernel<<<dim3(CNQ/128, CB*CNH), 256, FA_SMEM>>>(Qp, KVp, AOp, CNC);
    gemm_kernel<<<dim3(6, 64), 256>>>(AOp, a1_wp, cp, nullptr, a1_bp, nullptr, CRQ, CE, CD, 0);

    // ---- MLP 1 (with residual) ----
    ln_kernel<<<CRQ, 256>>>(cp, ln_w, ln_b, nullptr, tp);
    gemm_kernel<<<dim3(24, 64), 256>>>(tp, m1_w1, nullptr, Hp, m1_b1, nullptr, CRQ, CHID, CE,   1);
    gemm_kernel<<<dim3(6, 64),  256>>>(Hp, m1_w2, cp, nullptr, m1_b2, cp,      CRQ, CE,   CHID, 0);

    // ---- block 2: cross-attention over c (m=1024), residual ----
    ln_kernel<<<CRQ, 256>>>(cp, ln_w, ln_b, nullptr, tp);
    gemm_kernel<<<dim3(3, 64), 256>>>(tq, a2_wq,  nullptr, Qp,  nullptr, nullptr, CRQ, CD,   CE, 0);
    gemm_kernel<<<dim3(6, 64), 256>>>(tp, a2_wkv, nullptr, KVp, nullptr, nullptr, CRQ, 2*CD, CE, 0);
    fattn_kernel<<<dim3(CNQ/128, CB*CNH), 256, FA_SMEM>>>(Qp, KVp, AOp, CNQ);
    gemm_kernel<<<dim3(6, 64), 256>>>(AOp, a2_wp, cp, nullptr, a2_bp, cp, CRQ, CE, CD, 0);

    // ---- MLP 2 (with residual), final write straight into d_out ----
    ln_kernel<<<CRQ, 256>>>(cp, ln_w, ln_b, nullptr, tp);
    gemm_kernel<<<dim3(24, 64), 256>>>(tp, m2_w1, nullptr, Hp, m2_b1, nullptr, CRQ, CHID, CE,   1);
    gemm_kernel<<<dim3(6, 64),  256>>>(Hp, m2_w2, out_c, nullptr, m2_b2, cp,   CRQ, CE,   CHID, 0);
}

// round 9
// speedup vs baseline: 4.8653x; 1.0704x over previous
#include <cuda_runtime.h>
#include <cuda_fp16.h>
#include <cstdint>

#define CB   8
#define CNQ  1024
#define CNC  2048
#define CE   768
#define CD   384
#define CNH  6
#define CHD  64
#define CHID 3072
#define CRQ  (CB*CNQ)   /* 8192  */
#define CRC  (CB*CNC)   /* 16384 */

// ---------------- scratch (no cudaMalloc allowed) ----------------
__device__ __half g_cn[(size_t)CRC*CE];
__device__ __half g_Q [(size_t)CRQ*CD];
__device__ __half g_KV[(size_t)CRC*2*CD];
__device__ __half g_AO[(size_t)CRQ*CD];
__device__ float  g_c [(size_t)CRQ*CE];
__device__ __half g_t [(size_t)CRQ*CE];
__device__ __half g_tq[(size_t)CRQ*CE];
__device__ __half g_H [(size_t)CRQ*CHID];
__device__ __half g_W [11796480];   // all weights, fp16-rounded

// ---------------- helpers ----------------
__device__ __forceinline__ void cp16(void* smem, const void* gmem) {
    unsigned s = (unsigned)__cvta_generic_to_shared(smem);
    asm volatile("cp.async.ca.shared.global [%0], [%1], 16;\n" :: "r"(s), "l"(gmem));
}
__device__ __forceinline__ void cp_commit() {
    asm volatile("cp.async.commit_group;\n");
}
template<int N>
__device__ __forceinline__ void cp_wait() {
    asm volatile("cp.async.wait_group %0;\n" :: "n"(N));
}
__device__ __forceinline__ void ldsm_x4(uint32_t& r0, uint32_t& r1, uint32_t& r2, uint32_t& r3, uint32_t a) {
    asm volatile("ldmatrix.sync.aligned.m8n8.x4.shared.b16 {%0,%1,%2,%3}, [%4];"
                 : "=r"(r0), "=r"(r1), "=r"(r2), "=r"(r3) : "r"(a));
}
__device__ __forceinline__ void ldsm_x4t(uint32_t& r0, uint32_t& r1, uint32_t& r2, uint32_t& r3, uint32_t a) {
    asm volatile("ldmatrix.sync.aligned.m8n8.x4.trans.shared.b16 {%0,%1,%2,%3}, [%4];"
                 : "=r"(r0), "=r"(r1), "=r"(r2), "=r"(r3) : "r"(a));
}
__device__ __forceinline__ void mma16816(float* c, const uint32_t* a, const uint32_t* b) {
    asm volatile("mma.sync.aligned.m16n8k16.row.col.f32.f16.f16.f32 "
                 "{%0,%1,%2,%3}, {%4,%5,%6,%7}, {%8,%9}, {%0,%1,%2,%3};"
                 : "+f"(c[0]), "+f"(c[1]), "+f"(c[2]), "+f"(c[3])
                 : "r"(a[0]), "r"(a[1]), "r"(a[2]), "r"(a[3]), "r"(b[0]), "r"(b[1]));
}
__device__ __forceinline__ uint32_t pack2(float a, float b) {
    __half2 h = __floats2half2_rn(a, b);
    return *(uint32_t*)&h;
}
__device__ __forceinline__ float gelu_f(float v) {
    return 0.5f*v*(1.0f + erff(v*0.70710678118654752f));
}

// ---------------- weight round to fp16 (vectorized, all weights, one launch) ----------
struct WArgs { const float* src[10]; __half* dst[10]; int sz[10]; };
__global__ void round_all(WArgs a)
{
    int w = blockIdx.y;
    int i = ((blockIdx.x << 8) + threadIdx.x) << 2;
    if (i < a.sz[w]) {
        float4 f = *(const float4*)(a.src[w] + i);
        uint2 h;
        h.x = pack2(f.x, f.y);
        h.y = pack2(f.z, f.w);
        *(uint2*)(a.dst[w] + i) = h;
    }
}

// ---------------- LayerNorm: warp per 768-wide row, float4, shfl-only ----------------
// grid = rows/8, block = 256 (8 warps)
__global__ void ln_kernel(const float* __restrict__ x, const float* __restrict__ w,
                          const float* __restrict__ b, float* __restrict__ y,
                          __half* __restrict__ y2)
{
    int warp = threadIdx.x >> 5, lane = threadIdx.x & 31;
    size_t row = ((size_t)blockIdx.x << 3) + warp;
    const float4* xr = (const float4*)(x + row * CE);

    float4 v[6];
    float s = 0.f;
    #pragma unroll
    for (int e=0;e<6;e++){
        v[e] = xr[lane + (e<<5)];
        s += v[e].x + v[e].y + v[e].z + v[e].w;
    }
    #pragma unroll
    for (int o=16;o;o>>=1) s += __shfl_xor_sync(0xffffffffu, s, o);
    float mean = s * (1.0f/CE);

    float q = 0.f;
    #pragma unroll
    for (int e=0;e<6;e++){
        v[e].x -= mean; v[e].y -= mean; v[e].z -= mean; v[e].w -= mean;
        q += v[e].x*v[e].x + v[e].y*v[e].y + v[e].z*v[e].z + v[e].w*v[e].w;
    }
    #pragma unroll
    for (int o=16;o;o>>=1) q += __shfl_xor_sync(0xffffffffu, q, o);
    float inv = rsqrtf(q*(1.0f/CE) + 1e-5f);

    float4* yr = y ? (float4*)(y + row*CE) : nullptr;
    uint2*  y2r = y2 ? (uint2*)(y2 + row*CE) : nullptr;
    #pragma unroll
    for (int e=0;e<6;e++){
        int idx = lane + (e<<5);
        float4 ww = *(const float4*)(w + (idx<<2));
        float4 bb = *(const float4*)(b + (idx<<2));
        float r0 = v[e].x*inv*ww.x + bb.x;
        float r1 = v[e].y*inv*ww.y + bb.y;
        float r2 = v[e].z*inv*ww.z + bb.z;
        float r3 = v[e].w*inv*ww.w + bb.w;
        if (yr)  yr[idx] = make_float4(r0, r1, r2, r3);
        if (y2r) { uint2 h; h.x = pack2(r0, r1); h.y = pack2(r2, r3); y2r[idx] = h; }
    }
}

// ---------------- fp16 GEMM 128x128x32, 8 warps, warp tile 64x32 ----------------
__global__ void __launch_bounds__(256, 2) gemm_kernel(
    const __half* __restrict__ A, const __half* __restrict__ Bm,
    float* __restrict__ Cf, __half* __restrict__ Ch,
    const float* __restrict__ bias, const float* __restrict__ res,
    int M, int N, int K, int gelu)
{
    __shared__ __half As[3][128*40];
    __shared__ __half Bs[3][32*136];
    int tid = threadIdx.x, warp = tid >> 5, lane = tid & 31;
    int bm = blockIdx.y << 7, bn = blockIdx.x << 7;
    int wm = warp & 1, wn = warp >> 1;

    float acc[4][4][4];
    #pragma unroll
    for (int i=0;i<4;i++)
        #pragma unroll
        for (int t=0;t<4;t++){ acc[i][t][0]=0.f; acc[i][t][1]=0.f; acc[i][t][2]=0.f; acc[i][t][3]=0.f; }

    const __half* Ab = A + (size_t)bm * K;
    const __half* Bb = Bm + bn;
    int KT = K >> 5;

    auto issue = [&](int s, int kt){
        int k0 = kt << 5;
        #pragma unroll
        for (int p=0;p<2;p++){
            int id = tid + (p<<8);
            int r = id>>2, c = (id&3)<<3;
            cp16(&As[s][r*40 + c], Ab + (size_t)r*K + k0 + c);
        }
        #pragma unroll
        for (int p=0;p<2;p++){
            int id = tid + (p<<8);
            int r = id>>4, c = (id&15)<<3;
            cp16(&Bs[s][r*136 + c], Bb + (size_t)(k0+r)*N + c);
        }
        cp_commit();
    };

    issue(0, 0);
    issue(1, KT > 1 ? 1 : 0);

    int li = lane & 7, b3 = (lane>>3)&1, b4 = (lane>>4)&1;

    for (int kt = 0; kt < KT; kt++) {
        int cur = kt % 3;
        if (kt == KT-1) cp_wait<0>(); else cp_wait<1>();
        __syncthreads();

        uint32_t abase = (uint32_t)__cvta_generic_to_shared(&As[cur][0]);
        uint32_t bbase = (uint32_t)__cvta_generic_to_shared(&Bs[cur][0]);
        #pragma unroll
        for (int ks=0; ks<2; ks++) {
            uint32_t af[4][4];
            #pragma unroll
            for (int i=0;i<4;i++){
                uint32_t addr = abase + (uint32_t)((( (wm*64 + i*16 + b3*8 + li)*40 ) + ks*16 + b4*8) << 1);
                ldsm_x4(af[i][0], af[i][1], af[i][2], af[i][3], addr);
            }
            #pragma unroll
            for (int t=0;t<2;t++){
                uint32_t r0,r1,r2,r3;
                uint32_t addr = bbase + (uint32_t)((( (ks*16 + b3*8 + li)*136 ) + wn*32 + t*16 + b4*8) << 1);
                ldsm_x4t(r0,r1,r2,r3, addr);
                uint32_t bb0[2] = {r0,r1}, bb1[2] = {r2,r3};
                #pragma unroll
                for (int i=0;i<4;i++){
                    mma16816(acc[i][2*t],   af[i], bb0);
                    mma16816(acc[i][2*t+1], af[i], bb1);
                }
            }
        }
        if (kt + 2 < KT) issue((kt+2)%3, kt+2);
    }

    int g = lane>>2, cq = lane&3;
    #pragma unroll
    for (int i=0;i<4;i++){
        int r0 = bm + wm*64 + i*16 + g;
        size_t o0 = (size_t)r0 * N;
        size_t o1 = (size_t)(r0+8) * N;
        #pragma unroll
        for (int t=0;t<4;t++){
            int c0 = bn + wn*32 + t*8 + cq*2;
            float v0 = acc[i][t][0], v1 = acc[i][t][1];
            float v2 = acc[i][t][2], v3 = acc[i][t][3];
            if (bias){ float bb0 = bias[c0], bb1 = bias[c0+1];
                       v0 += bb0; v1 += bb1; v2 += bb0; v3 += bb1; }
            if (gelu){ v0 = gelu_f(v0); v1 = gelu_f(v1); v2 = gelu_f(v2); v3 = gelu_f(v3); }
            if (Ch){
                *(__half2*)(Ch + o0 + c0) = __floats2half2_rn(v0, v1);
                *(__half2*)(Ch + o1 + c0) = __floats2half2_rn(v2, v3);
            } else {
                if (res){
                    float2 ra = *(const float2*)(res + o0 + c0);
                    float2 rb = *(const float2*)(res + o1 + c0);
                    v0 += ra.x; v1 += ra.y; v2 += rb.x; v3 += rb.y;
                }
                *(float2*)(Cf + o0 + c0) = make_float2(v0, v1);
                *(float2*)(Cf + o1 + c0) = make_float2(v2, v3);
            }
        }
    }
}

// ---------------- flash attention: fused QK^T -> softmax -> PV ----------------
#define FA_SMEM 92160
__global__ void __launch_bounds__(256) fattn_kernel(
    const __half* __restrict__ Q, const __half* __restrict__ KV,
    __half* __restrict__ AO, int ctx)
{
    extern __shared__ __align__(128) __half fsm[];
    __half* Qs  = fsm;                 // 128 x 72
    __half* Ksb[2] = { fsm + 9216,  fsm + 2*9216 };
    __half* Vsb[2] = { fsm + 3*9216, fsm + 4*9216 };

    int bh = blockIdx.y, b = bh / CNH, h = bh % CNH;
    int i0 = blockIdx.x << 7;
    const __half* Qb = Q  + (size_t)b*CNQ*CD + h*CHD;
    const __half* Kb = KV + (size_t)b*ctx*(2*CD) + h*CHD;
    const __half* Vb = Kb + CD;
    int tid = threadIdx.x, warp = tid>>5, lane = tid&31;

    #pragma unroll
    for (int p=0;p<4;p++){
        int id = tid + (p<<8); int r = id>>3, c = (id&7)<<3;
        cp16(&Qs[r*72 + c], Qb + (size_t)(i0+r)*CD + c);
    }
    cp_commit();

    auto load_kv = [&](int s, int j){
        const __half* Kc = Kb + (size_t)(j<<7)*(2*CD);
        const __half* Vc = Vb + (size_t)(j<<7)*(2*CD);
        #pragma unroll
        for (int p=0;p<4;p++){
            int id = tid + (p<<8); int r = id>>3, c = (id&7)<<3;
            cp16(&Ksb[s][r*72 + c], Kc + (size_t)r*(2*CD) + c);
        }
        #pragma unroll
        for (int p=0;p<4;p++){
            int id = tid + (p<<8); int r = id>>3, c = (id&7)<<3;
            cp16(&Vsb[s][r*72 + c], Vc + (size_t)r*(2*CD) + c);
        }
        cp_commit();
    };
    load_kv(0, 0);

    int li = lane & 7, b3 = (lane>>3)&1, b4 = (lane>>4)&1;
    uint32_t qaddr = (uint32_t)__cvta_generic_to_shared(Qs)
                   + (uint32_t)(((warp*16 + b3*8 + li)*72 + b4*8)*2);
    uint32_t koff = (uint32_t)(((b4*8 + li)*72 + b3*8)*2);
    uint32_t voff = (uint32_t)(((b3*8 + li)*72 + b4*8)*2);

    cp_wait<1>();
    __syncthreads();

    uint32_t qa[4][4];
    #pragma unroll
    for (int s=0;s<4;s++)
        ldsm_x4(qa[s][0], qa[s][1], qa[s][2], qa[s][3], qaddr + s*32);

    float m0=-1e30f, m1=-1e30f, l0=0.f, l1=0.f;
    float o[8][4];
    #pragma unroll
    for (int d=0; d<8; d++){ o[d][0]=0.f; o[d][1]=0.f; o[d][2]=0.f; o[d][3]=0.f; }

    const float SC2 = 0.125f * 1.4426950408889634f;
    int nc = ctx >> 7;

    for (int j=0; j<nc; j++){
        int cur = j & 1;
        if (j+1 < nc){ load_kv(cur^1, j+1); cp_wait<1>(); }
        else         { cp_wait<0>(); }
        __syncthreads();

        uint32_t kb = (uint32_t)__cvta_generic_to_shared(Ksb[cur]) + koff;
        uint32_t vbs = (uint32_t)__cvta_generic_to_shared(Vsb[cur]) + voff;

        float sc[16][4];
        #pragma unroll
        for (int t=0;t<16;t++){ sc[t][0]=0.f; sc[t][1]=0.f; sc[t][2]=0.f; sc[t][3]=0.f; }
        #pragma unroll
        for (int tp=0; tp<8; tp++){
            #pragma unroll
            for (int s=0;s<4;s++){
                uint32_t r0,r1,r2,r3;
                ldsm_x4(r0,r1,r2,r3, kb + tp*16*144 + s*32);
                uint32_t bb0[2] = {r0,r1}, bb1[2] = {r2,r3};
                mma16816(sc[2*tp],   qa[s], bb0);
                mma16816(sc[2*tp+1], qa[s], bb1);
            }
        }

        float mx0 = -1e30f, mx1 = -1e30f;
        #pragma unroll
        for (int t=0;t<16;t++){
            mx0 = fmaxf(mx0, fmaxf(sc[t][0], sc[t][1]));
            mx1 = fmaxf(mx1, fmaxf(sc[t][2], sc[t][3]));
        }
        mx0 = fmaxf(mx0, __shfl_xor_sync(0xffffffffu, mx0, 1));
        mx0 = fmaxf(mx0, __shfl_xor_sync(0xffffffffu, mx0, 2));
        mx1 = fmaxf(mx1, __shfl_xor_sync(0xffffffffu, mx1, 1));
        mx1 = fmaxf(mx1, __shfl_xor_sync(0xffffffffu, mx1, 2));
        float nm0 = fmaxf(m0, mx0), nm1 = fmaxf(m1, mx1);
        float r0f = exp2f((m0-nm0)*SC2), r1f = exp2f((m1-nm1)*SC2);
        m0 = nm0; m1 = nm1;
        float s0 = 0.f, s1 = 0.f;
        #pragma unroll
        for (int t=0;t<16;t++){
            sc[t][0] = exp2f((sc[t][0]-nm0)*SC2);
            sc[t][1] = exp2f((sc[t][1]-nm0)*SC2);
            sc[t][2] = exp2f((sc[t][2]-nm1)*SC2);
            sc[t][3] = exp2f((sc[t][3]-nm1)*SC2);
            s0 += sc[t][0] + sc[t][1];
            s1 += sc[t][2] + sc[t][3];
        }
        s0 += __shfl_xor_sync(0xffffffffu, s0, 1);
        s0 += __shfl_xor_sync(0xffffffffu, s0, 2);
        s1 += __shfl_xor_sync(0xffffffffu, s1, 1);
        s1 += __shfl_xor_sync(0xffffffffu, s1, 2);
        l0 = l0*r0f + s0; l1 = l1*r1f + s1;
        #pragma unroll
        for (int d=0; d<8; d++){
            o[d][0]*=r0f; o[d][1]*=r0f; o[d][2]*=r1f; o[d][3]*=r1f;
        }

        #pragma unroll
        for (int kc=0; kc<8; kc++){
            uint32_t pa[4];
            pa[0] = pack2(sc[2*kc][0],   sc[2*kc][1]);
            pa[1] = pack2(sc[2*kc][2],   sc[2*kc][3]);
            pa[2] = pack2(sc[2*kc+1][0], sc[2*kc+1][1]);
            pa[3] = pack2(sc[2*kc+1][2], sc[2*kc+1][3]);
            #pragma unroll
            for (int dp=0; dp<4; dp++){
                uint32_t r0,r1,r2,r3;
                ldsm_x4t(r0,r1,r2,r3, vbs + kc*16*144 + dp*32);
                uint32_t bb0[2] = {r0,r1}, bb1[2] = {r2,r3};
                mma16816(o[2*dp],   pa, bb0);
                mma16816(o[2*dp+1], pa, bb1);
            }
        }
        __syncthreads();
    }

    float inv0 = 1.f/l0, inv1 = 1.f/l1;
    int g = lane>>2, cq = lane&3;
    int row0 = i0 + warp*16 + g;
    __half2* O0 = (__half2*)(AO + ((size_t)b*CNQ + row0)*CD + h*CHD + cq*2);
    __half2* O1 = (__half2*)(AO + ((size_t)b*CNQ + row0+8)*CD + h*CHD + cq*2);
    #pragma unroll
    for (int d=0; d<8; d++){
        O0[d*4] = __floats2half2_rn(o[d][0]*inv0, o[d][1]*inv0);
        O1[d*4] = __floats2half2_rn(o[d][2]*inv1, o[d][3]*inv1);
    }
}

// ---------------- driver ----------------
extern "C" void kernel_launch(void* const* d_in, const int* in_sizes, int n_in,
                              void* d_out, int out_size)
{
    const float* query   = (const float*)d_in[0];
    const float* context = (const float*)d_in[1];
    const float* ln_w    = (const float*)d_in[2];
    const float* ln_b    = (const float*)d_in[3];
    const float* a1_bp   = (const float*)d_in[7];
    const float* m1_b1   = (const float*)d_in[9];
    const float* m1_b2   = (const float*)d_in[11];
    const float* a2_bp   = (const float*)d_in[15];
    const float* m2_b1   = (const float*)d_in[17];
    const float* m2_b2   = (const float*)d_in[19];

    float* out   = (float*)d_out;
    float* out_c = out;
    float* out_q = out + (size_t)CRQ * CE;

    __half *cn, *Qp, *KVp, *AOp, *tp, *tq, *Hp, *W;
    float *cp;
    cudaGetSymbolAddress((void**)&cn,  g_cn);
    cudaGetSymbolAddress((void**)&Qp,  g_Q);
    cudaGetSymbolAddress((void**)&KVp, g_KV);
    cudaGetSymbolAddress((void**)&AOp, g_AO);
    cudaGetSymbolAddress((void**)&cp,  g_c);
    cudaGetSymbolAddress((void**)&tp,  g_t);
    cudaGetSymbolAddress((void**)&tq,  g_tq);
    cudaGetSymbolAddress((void**)&Hp,  g_H);
    cudaGetSymbolAddress((void**)&W,   g_W);

    cudaFuncSetAttribute(fattn_kernel, cudaFuncAttributeMaxDynamicSharedMemorySize, FA_SMEM);

    const int widx[10] = {4,5,6,8,10,12,13,14,16,18};
    const int wsz [10] = {CE*CD, CE*2*CD, CD*CE, CE*CHID, CHID*CE,
                          CE*CD, CE*2*CD, CD*CE, CE*CHID, CHID*CE};
    WArgs wa;
    __half* wptr[10];
    {
        size_t off = 0;
        int mx = 0;
        for (int i=0;i<10;i++){
            wptr[i] = W + off; off += wsz[i];
            wa.src[i] = (const float*)d_in[widx[i]];
            wa.dst[i] = wptr[i];
            wa.sz[i]  = wsz[i];
            if (wsz[i] > mx) mx = wsz[i];
        }
        round_all<<<dim3((mx/4+255)/256, 10), 256>>>(wa);
    }
    __half* a1_wq = wptr[0];  __half* a1_wkv = wptr[1]; __half* a1_wp = wptr[2];
    __half* m1_w1 = wptr[3];  __half* m1_w2  = wptr[4];
    __half* a2_wq = wptr[5];  __half* a2_wkv = wptr[6]; __half* a2_wp = wptr[7];
    __half* m2_w1 = wptr[8];  __half* m2_w2  = wptr[9];

    ln_kernel<<<CRQ/8, 256>>>(query,   ln_w, ln_b, out_q, tq);
    ln_kernel<<<CRC/8, 256>>>(context, ln_w, ln_b, nullptr, cn);

    // ---- block 1: cross-attention over context (m=2048) ----
    gemm_kernel<<<dim3(3, 64),  256>>>(tq, a1_wq,  nullptr, Qp,  nullptr, nullptr, CRQ, CD,   CE, 0);
    gemm_kernel<<<dim3(6, 128), 256>>>(cn, a1_wkv, nullptr, KVp, nullptr, nullptr, CRC, 2*CD, CE, 0);
    fattn_kernel<<<dim3(CNQ/128, CB*CNH), 256, FA_SMEM>>>(Qp, KVp, AOp, CNC);
    gemm_kernel<<<dim3(6, 64), 256>>>(AOp, a1_wp, cp, nullptr, a1_bp, nullptr, CRQ, CE, CD, 0);

    // ---- MLP 1 (with residual) ----
    ln_kernel<<<CRQ/8, 256>>>(cp, ln_w, ln_b, nullptr, tp);
    gemm_kernel<<<dim3(24, 64), 256>>>(tp, m1_w1, nullptr, Hp, m1_b1, nullptr, CRQ, CHID, CE,   1);
    gemm_kernel<<<dim3(6, 64),  256>>>(Hp, m1_w2, cp, nullptr, m1_b2, cp,      CRQ, CE,   CHID, 0);

    // ---- block 2: cross-attention over c (m=1024), residual ----
    ln_kernel<<<CRQ/8, 256>>>(cp, ln_w, ln_b, nullptr, tp);
    gemm_kernel<<<dim3(3, 64), 256>>>(tq, a2_wq,  nullptr, Qp,  nullptr, nullptr, CRQ, CD,   CE, 0);
    gemm_kernel<<<dim3(6, 64), 256>>>(tp, a2_wkv, nullptr, KVp, nullptr, nullptr, CRQ, 2*CD, CE, 0);
    fattn_kernel<<<dim3(CNQ/128, CB*CNH), 256, FA_SMEM>>>(Qp, KVp, AOp, CNQ);
    gemm_kernel<<<dim3(6, 64), 256>>>(AOp, a2_wp, cp, nullptr, a2_bp, cp, CRQ, CE, CD, 0);

    // ---- MLP 2 (with residual), final write straight into d_out ----
    ln_kernel<<<CRQ/8, 256>>>(cp, ln_w, ln_b, nullptr, tp);
    gemm_kernel<<<dim3(24, 64), 256>>>(tp, m2_w1, nullptr, Hp, m2_b1, nullptr, CRQ, CHID, CE,   1);
    gemm_kernel<<<dim3(6, 64),  256>>>(Hp, m2_w2, out_c, nullptr, m2_b2, cp,   CRQ, CE,   CHID, 0);
}

// round 10
// speedup vs baseline: 4.8754x; 1.0021x over previous
#include <cuda_runtime.h>
#include <cuda_fp16.h>
#include <cstdint>

#define CB   8
#define CNQ  1024
#define CNC  2048
#define CE   768
#define CD   384
#define CNH  6
#define CHD  64
#define CHID 3072
#define CRQ  (CB*CNQ)   /* 8192  */
#define CRC  (CB*CNC)   /* 16384 */

// ---------------- scratch (no cudaMalloc allowed) ----------------
__device__ __half g_cn[(size_t)CRC*CE];
__device__ __half g_Q [(size_t)CRQ*2*CD];      // merged Q1|Q2, row stride 768
__device__ __half g_KV[(size_t)CRC*2*CD];
__device__ __half g_AO[(size_t)CRQ*CD];
__device__ float  g_c [(size_t)CRQ*CE];
__device__ __half g_t [(size_t)CRQ*CE];
__device__ __half g_tq[(size_t)CRQ*CE];
__device__ __half g_H [(size_t)CRQ*CHID];
__device__ __half g_W [11796480];   // all weights, fp16-rounded (Qw packed first)

// ---------------- helpers ----------------
__device__ __forceinline__ void cp16(void* smem, const void* gmem) {
    unsigned s = (unsigned)__cvta_generic_to_shared(smem);
    asm volatile("cp.async.ca.shared.global [%0], [%1], 16;\n" :: "r"(s), "l"(gmem));
}
__device__ __forceinline__ void cp_commit() {
    asm volatile("cp.async.commit_group;\n");
}
template<int N>
__device__ __forceinline__ void cp_wait() {
    asm volatile("cp.async.wait_group %0;\n" :: "n"(N));
}
__device__ __forceinline__ void ldsm_x4(uint32_t& r0, uint32_t& r1, uint32_t& r2, uint32_t& r3, uint32_t a) {
    asm volatile("ldmatrix.sync.aligned.m8n8.x4.shared.b16 {%0,%1,%2,%3}, [%4];"
                 : "=r"(r0), "=r"(r1), "=r"(r2), "=r"(r3) : "r"(a));
}
__device__ __forceinline__ void ldsm_x4t(uint32_t& r0, uint32_t& r1, uint32_t& r2, uint32_t& r3, uint32_t a) {
    asm volatile("ldmatrix.sync.aligned.m8n8.x4.trans.shared.b16 {%0,%1,%2,%3}, [%4];"
                 : "=r"(r0), "=r"(r1), "=r"(r2), "=r"(r3) : "r"(a));
}
__device__ __forceinline__ void mma16816(float* c, const uint32_t* a, const uint32_t* b) {
    asm volatile("mma.sync.aligned.m16n8k16.row.col.f32.f16.f16.f32 "
                 "{%0,%1,%2,%3}, {%4,%5,%6,%7}, {%8,%9}, {%0,%1,%2,%3};"
                 : "+f"(c[0]), "+f"(c[1]), "+f"(c[2]), "+f"(c[3])
                 : "r"(a[0]), "r"(a[1]), "r"(a[2]), "r"(a[3]), "r"(b[0]), "r"(b[1]));
}
__device__ __forceinline__ uint32_t pack2(float a, float b) {
    __half2 h = __floats2half2_rn(a, b);
    return *(uint32_t*)&h;
}
__device__ __forceinline__ float gelu_f(float v) {
    return 0.5f*v*(1.0f + erff(v*0.70710678118654752f));
}

// ---------------- weight round to fp16 (vectorized, strided dst, one launch) --------
struct WArgs { const float* src[10]; __half* dst[10]; int sz[10]; int nc[10]; int ld[10]; };
__global__ void round_all(WArgs a)
{
    int w = blockIdx.y;
    int i = ((blockIdx.x << 8) + threadIdx.x) << 2;
    if (i < a.sz[w]) {
        int nc = a.nc[w];
        int row = i / nc, col = i - row*nc;
        float4 f = *(const float4*)(a.src[w] + i);
        uint2 h;
        h.x = pack2(f.x, f.y);
        h.y = pack2(f.z, f.w);
        *(uint2*)(a.dst[w] + (size_t)row*a.ld[w] + col) = h;
    }
}

// ---------------- LayerNorm: warp per 768-wide row, float4, shfl-only ----------------
__global__ void ln_kernel(const float* __restrict__ x, const float* __restrict__ w,
                          const float* __restrict__ b, float* __restrict__ y,
                          __half* __restrict__ y2)
{
    int warp = threadIdx.x >> 5, lane = threadIdx.x & 31;
    size_t row = ((size_t)blockIdx.x << 3) + warp;
    const float4* xr = (const float4*)(x + row * CE);

    float4 v[6];
    float s = 0.f;
    #pragma unroll
    for (int e=0;e<6;e++){
        v[e] = xr[lane + (e<<5)];
        s += v[e].x + v[e].y + v[e].z + v[e].w;
    }
    #pragma unroll
    for (int o=16;o;o>>=1) s += __shfl_xor_sync(0xffffffffu, s, o);
    float mean = s * (1.0f/CE);

    float q = 0.f;
    #pragma unroll
    for (int e=0;e<6;e++){
        v[e].x -= mean; v[e].y -= mean; v[e].z -= mean; v[e].w -= mean;
        q += v[e].x*v[e].x + v[e].y*v[e].y + v[e].z*v[e].z + v[e].w*v[e].w;
    }
    #pragma unroll
    for (int o=16;o;o>>=1) q += __shfl_xor_sync(0xffffffffu, q, o);
    float inv = rsqrtf(q*(1.0f/CE) + 1e-5f);

    float4* yr = y ? (float4*)(y + row*CE) : nullptr;
    uint2*  y2r = y2 ? (uint2*)(y2 + row*CE) : nullptr;
    #pragma unroll
    for (int e=0;e<6;e++){
        int idx = lane + (e<<5);
        float4 ww = *(const float4*)(w + (idx<<2));
        float4 bb = *(const float4*)(b + (idx<<2));
        float r0 = v[e].x*inv*ww.x + bb.x;
        float r1 = v[e].y*inv*ww.y + bb.y;
        float r2 = v[e].z*inv*ww.z + bb.z;
        float r3 = v[e].w*inv*ww.w + bb.w;
        if (yr)  yr[idx] = make_float4(r0, r1, r2, r3);
        if (y2r) { uint2 h; h.x = pack2(r0, r1); h.y = pack2(r2, r3); y2r[idx] = h; }
    }
}

// ---------------- fp16 GEMM 128x128x64, 8 warps, warp tile 64x32, 3-stage ----------
// dynamic smem: 3 stages x (As 128x72 + Bs 64x136) halves
#define GEMM_SMEM (3*(128*72 + 64*136)*2)
__global__ void __launch_bounds__(256, 2) gemm_kernel(
    const __half* __restrict__ A, const __half* __restrict__ Bm,
    float* __restrict__ Cf, __half* __restrict__ Ch,
    const float* __restrict__ bias, const float* __restrict__ res,
    int M, int N, int K, int gelu)
{
    extern __shared__ __align__(16) __half gsm[];
    const int ASZ = 128*72, BSZ = 64*136, STG = ASZ + BSZ;
    int tid = threadIdx.x, warp = tid >> 5, lane = tid & 31;
    int bm = blockIdx.y << 7, bn = blockIdx.x << 7;
    int wm = warp & 1, wn = warp >> 1;

    float acc[4][4][4];
    #pragma unroll
    for (int i=0;i<4;i++)
        #pragma unroll
        for (int t=0;t<4;t++){ acc[i][t][0]=0.f; acc[i][t][1]=0.f; acc[i][t][2]=0.f; acc[i][t][3]=0.f; }

    const __half* Ab = A + (size_t)bm * K;
    const __half* Bb = Bm + bn;
    int KT = K >> 6;

    auto issue = [&](int s, int kt){
        int k0 = kt << 6;
        __half* As = gsm + s*STG;
        __half* Bs = As + ASZ;
        #pragma unroll
        for (int p=0;p<4;p++){
            int id = tid + (p<<8);
            int r = id>>3, c = (id&7)<<3;          // 128 rows x 64 cols
            cp16(&As[r*72 + c], Ab + (size_t)r*K + k0 + c);
        }
        #pragma unroll
        for (int p=0;p<4;p++){
            int id = tid + (p<<8);
            int r = id>>4, c = (id&15)<<3;         // 64 rows x 128 cols
            cp16(&Bs[r*136 + c], Bb + (size_t)(k0+r)*N + c);
        }
        cp_commit();
    };

    issue(0, 0);
    issue(1, 1);

    int li = lane & 7, b3 = (lane>>3)&1, b4 = (lane>>4)&1;

    for (int kt = 0; kt < KT; kt++) {
        int cur = kt % 3;
        if (kt == KT-1) cp_wait<0>(); else cp_wait<1>();
        __syncthreads();

        uint32_t abase = (uint32_t)__cvta_generic_to_shared(gsm + cur*STG);
        uint32_t bbase = abase + (uint32_t)(ASZ*2);
        #pragma unroll
        for (int ks=0; ks<4; ks++) {
            uint32_t af[4][4];
            #pragma unroll
            for (int i=0;i<4;i++){
                uint32_t addr = abase + (uint32_t)((( (wm*64 + i*16 + b3*8 + li)*72 ) + ks*16 + b4*8) << 1);
                ldsm_x4(af[i][0], af[i][1], af[i][2], af[i][3], addr);
            }
            #pragma unroll
            for (int t=0;t<2;t++){
                uint32_t r0,r1,r2,r3;
                uint32_t addr = bbase + (uint32_t)((( (ks*16 + b3*8 + li)*136 ) + wn*32 + t*16 + b4*8) << 1);
                ldsm_x4t(r0,r1,r2,r3, addr);
                uint32_t bb0[2] = {r0,r1}, bb1[2] = {r2,r3};
                #pragma unroll
                for (int i=0;i<4;i++){
                    mma16816(acc[i][2*t],   af[i], bb0);
                    mma16816(acc[i][2*t+1], af[i], bb1);
                }
            }
        }
        if (kt + 2 < KT) issue((kt+2)%3, kt+2);
    }

    // register-direct epilogue
    int g = lane>>2, cq = lane&3;
    #pragma unroll
    for (int i=0;i<4;i++){
        int r0 = bm + wm*64 + i*16 + g;
        size_t o0 = (size_t)r0 * N;
        size_t o1 = (size_t)(r0+8) * N;
        #pragma unroll
        for (int t=0;t<4;t++){
            int c0 = bn + wn*32 + t*8 + cq*2;
            float v0 = acc[i][t][0], v1 = acc[i][t][1];
            float v2 = acc[i][t][2], v3 = acc[i][t][3];
            if (bias){ float bb0 = bias[c0], bb1 = bias[c0+1];
                       v0 += bb0; v1 += bb1; v2 += bb0; v3 += bb1; }
            if (gelu){ v0 = gelu_f(v0); v1 = gelu_f(v1); v2 = gelu_f(v2); v3 = gelu_f(v3); }
            if (Ch){
                *(__half2*)(Ch + o0 + c0) = __floats2half2_rn(v0, v1);
                *(__half2*)(Ch + o1 + c0) = __floats2half2_rn(v2, v3);
            } else {
                if (res){
                    float2 ra = *(const float2*)(res + o0 + c0);
                    float2 rb = *(const float2*)(res + o1 + c0);
                    v0 += ra.x; v1 += ra.y; v2 += rb.x; v3 += rb.y;
                }
                *(float2*)(Cf + o0 + c0) = make_float2(v0, v1);
                *(float2*)(Cf + o1 + c0) = make_float2(v2, v3);
            }
        }
    }
}

// ---------------- flash attention: fused QK^T -> softmax -> PV ----------------
#define FA_SMEM 92160
__global__ void __launch_bounds__(256) fattn_kernel(
    const __half* __restrict__ Q, int qld, const __half* __restrict__ KV,
    __half* __restrict__ AO, int ctx)
{
    extern __shared__ __align__(128) __half fsm[];
    __half* Qs  = fsm;                 // 128 x 72
    __half* Ksb[2] = { fsm + 9216,  fsm + 2*9216 };
    __half* Vsb[2] = { fsm + 3*9216, fsm + 4*9216 };

    int bh = blockIdx.y, b = bh / CNH, h = bh % CNH;
    int i0 = blockIdx.x << 7;
    const __half* Qb = Q  + (size_t)b*CNQ*qld + h*CHD;
    const __half* Kb = KV + (size_t)b*ctx*(2*CD) + h*CHD;
    const __half* Vb = Kb + CD;
    int tid = threadIdx.x, warp = tid>>5, lane = tid&31;

    #pragma unroll
    for (int p=0;p<4;p++){
        int id = tid + (p<<8); int r = id>>3, c = (id&7)<<3;
        cp16(&Qs[r*72 + c], Qb + (size_t)(i0+r)*qld + c);
    }
    cp_commit();

    auto load_kv = [&](int s, int j){
        const __half* Kc = Kb + (size_t)(j<<7)*(2*CD);
        const __half* Vc = Vb + (size_t)(j<<7)*(2*CD);
        #pragma unroll
        for (int p=0;p<4;p++){
            int id = tid + (p<<8); int r = id>>3, c = (id&7)<<3;
            cp16(&Ksb[s][r*72 + c], Kc + (size_t)r*(2*CD) + c);
        }
        #pragma unroll
        for (int p=0;p<4;p++){
            int id = tid + (p<<8); int r = id>>3, c = (id&7)<<3;
            cp16(&Vsb[s][r*72 + c], Vc + (size_t)r*(2*CD) + c);
        }
        cp_commit();
    };
    load_kv(0, 0);

    int li = lane & 7, b3 = (lane>>3)&1, b4 = (lane>>4)&1;
    uint32_t qaddr = (uint32_t)__cvta_generic_to_shared(Qs)
                   + (uint32_t)(((warp*16 + b3*8 + li)*72 + b4*8)*2);
    uint32_t koff = (uint32_t)(((b4*8 + li)*72 + b3*8)*2);
    uint32_t voff = (uint32_t)(((b3*8 + li)*72 + b4*8)*2);

    cp_wait<1>();
    __syncthreads();

    uint32_t qa[4][4];
    #pragma unroll
    for (int s=0;s<4;s++)
        ldsm_x4(qa[s][0], qa[s][1], qa[s][2], qa[s][3], qaddr + s*32);

    float m0=-1e30f, m1=-1e30f, l0=0.f, l1=0.f;
    float o[8][4];
    #pragma unroll
    for (int d=0; d<8; d++){ o[d][0]=0.f; o[d][1]=0.f; o[d][2]=0.f; o[d][3]=0.f; }

    const float SC2 = 0.125f * 1.4426950408889634f;
    int nc = ctx >> 7;

    for (int j=0; j<nc; j++){
        int cur = j & 1;
        if (j+1 < nc){ load_kv(cur^1, j+1); cp_wait<1>(); }
        else         { cp_wait<0>(); }
        __syncthreads();

        uint32_t kb = (uint32_t)__cvta_generic_to_shared(Ksb[cur]) + koff;
        uint32_t vbs = (uint32_t)__cvta_generic_to_shared(Vsb[cur]) + voff;

        float sc[16][4];
        #pragma unroll
        for (int t=0;t<16;t++){ sc[t][0]=0.f; sc[t][1]=0.f; sc[t][2]=0.f; sc[t][3]=0.f; }
        #pragma unroll
        for (int tp=0; tp<8; tp++){
            #pragma unroll
            for (int s=0;s<4;s++){
                uint32_t r0,r1,r2,r3;
                ldsm_x4(r0,r1,r2,r3, kb + tp*16*144 + s*32);
                uint32_t bb0[2] = {r0,r1}, bb1[2] = {r2,r3};
                mma16816(sc[2*tp],   qa[s], bb0);
                mma16816(sc[2*tp+1], qa[s], bb1);
            }
        }

        float mx0 = -1e30f, mx1 = -1e30f;
        #pragma unroll
        for (int t=0;t<16;t++){
            mx0 = fmaxf(mx0, fmaxf(sc[t][0], sc[t][1]));
            mx1 = fmaxf(mx1, fmaxf(sc[t][2], sc[t][3]));
        }
        mx0 = fmaxf(mx0, __shfl_xor_sync(0xffffffffu, mx0, 1));
        mx0 = fmaxf(mx0, __shfl_xor_sync(0xffffffffu, mx0, 2));
        mx1 = fmaxf(mx1, __shfl_xor_sync(0xffffffffu, mx1, 1));
        mx1 = fmaxf(mx1, __shfl_xor_sync(0xffffffffu, mx1, 2));
        float nm0 = fmaxf(m0, mx0), nm1 = fmaxf(m1, mx1);
        float r0f = exp2f((m0-nm0)*SC2), r1f = exp2f((m1-nm1)*SC2);
        m0 = nm0; m1 = nm1;
        float s0 = 0.f, s1 = 0.f;
        #pragma unroll
        for (int t=0;t<16;t++){
            sc[t][0] = exp2f((sc[t][0]-nm0)*SC2);
            sc[t][1] = exp2f((sc[t][1]-nm0)*SC2);
            sc[t][2] = exp2f((sc[t][2]-nm1)*SC2);
            sc[t][3] = exp2f((sc[t][3]-nm1)*SC2);
            s0 += sc[t][0] + sc[t][1];
            s1 += sc[t][2] + sc[t][3];
        }
        s0 += __shfl_xor_sync(0xffffffffu, s0, 1);
        s0 += __shfl_xor_sync(0xffffffffu, s0, 2);
        s1 += __shfl_xor_sync(0xffffffffu, s1, 1);
        s1 += __shfl_xor_sync(0xffffffffu, s1, 2);
        l0 = l0*r0f + s0; l1 = l1*r1f + s1;
        #pragma unroll
        for (int d=0; d<8; d++){
            o[d][0]*=r0f; o[d][1]*=r0f; o[d][2]*=r1f; o[d][3]*=r1f;
        }

        #pragma unroll
        for (int kc=0; kc<8; kc++){
            uint32_t pa[4];
            pa[0] = pack2(sc[2*kc][0],   sc[2*kc][1]);
            pa[1] = pack2(sc[2*kc][2],   sc[2*kc][3]);
            pa[2] = pack2(sc[2*kc+1][0], sc[2*kc+1][1]);
            pa[3] = pack2(sc[2*kc+1][2], sc[2*kc+1][3]);
            #pragma unroll
            for (int dp=0; dp<4; dp++){
                uint32_t r0,r1,r2,r3;
                ldsm_x4t(r0,r1,r2,r3, vbs + kc*16*144 + dp*32);
                uint32_t bb0[2] = {r0,r1}, bb1[2] = {r2,r3};
                mma16816(o[2*dp],   pa, bb0);
                mma16816(o[2*dp+1], pa, bb1);
            }
        }
        __syncthreads();
    }

    float inv0 = 1.f/l0, inv1 = 1.f/l1;
    int g = lane>>2, cq = lane&3;
    int row0 = i0 + warp*16 + g;
    __half2* O0 = (__half2*)(AO + ((size_t)b*CNQ + row0)*CD + h*CHD + cq*2);
    __half2* O1 = (__half2*)(AO + ((size_t)b*CNQ + row0+8)*CD + h*CHD + cq*2);
    #pragma unroll
    for (int d=0; d<8; d++){
        O0[d*4] = __floats2half2_rn(o[d][0]*inv0, o[d][1]*inv0);
        O1[d*4] = __floats2half2_rn(o[d][2]*inv1, o[d][3]*inv1);
    }
}

// ---------------- driver ----------------
extern "C" void kernel_launch(void* const* d_in, const int* in_sizes, int n_in,
                              void* d_out, int out_size)
{
    const float* query   = (const float*)d_in[0];
    const float* context = (const float*)d_in[1];
    const float* ln_w    = (const float*)d_in[2];
    const float* ln_b    = (const float*)d_in[3];
    const float* a1_bp   = (const float*)d_in[7];
    const float* m1_b1   = (const float*)d_in[9];
    const float* m1_b2   = (const float*)d_in[11];
    const float* a2_bp   = (const float*)d_in[15];
    const float* m2_b1   = (const float*)d_in[17];
    const float* m2_b2   = (const float*)d_in[19];

    float* out   = (float*)d_out;
    float* out_c = out;
    float* out_q = out + (size_t)CRQ * CE;

    __half *cn, *Qp, *KVp, *AOp, *tp, *tq, *Hp, *W;
    float *cp;
    cudaGetSymbolAddress((void**)&cn,  g_cn);
    cudaGetSymbolAddress((void**)&Qp,  g_Q);
    cudaGetSymbolAddress((void**)&KVp, g_KV);
    cudaGetSymbolAddress((void**)&AOp, g_AO);
    cudaGetSymbolAddress((void**)&cp,  g_c);
    cudaGetSymbolAddress((void**)&tp,  g_t);
    cudaGetSymbolAddress((void**)&tq,  g_tq);
    cudaGetSymbolAddress((void**)&Hp,  g_H);
    cudaGetSymbolAddress((void**)&W,   g_W);

    cudaFuncSetAttribute(fattn_kernel, cudaFuncAttributeMaxDynamicSharedMemorySize, FA_SMEM);
    cudaFuncSetAttribute(gemm_kernel, cudaFuncAttributeMaxDynamicSharedMemorySize, GEMM_SMEM);

    // weight layout in g_W:
    //   Qw [768 x 768] = a1_wq (cols 0..383) | a2_wq (cols 384..767)
    //   then a1_wkv, a1_wp, m1_w1, m1_w2, a2_wkv, a2_wp, m2_w1, m2_w2
    __half* Qw = W;
    WArgs wa;
    __half* base = W + 768*768;
    const int ridx[8]  = {5, 6, 8, 10, 13, 14, 16, 18};
    const int rrow[8]  = {CE, CD, CE, CHID, CE, CD, CE, CHID};
    const int rcol[8]  = {2*CD, CE, CHID, CE, 2*CD, CE, CHID, CE};
    __half* rptr[8];
    {
        // entries 0,1: the two Q weights into packed Qw
        wa.src[0] = (const float*)d_in[4];  wa.dst[0] = Qw;        wa.sz[0] = CE*CD; wa.nc[0] = CD; wa.ld[0] = 2*CD;
        wa.src[1] = (const float*)d_in[12]; wa.dst[1] = Qw + CD;   wa.sz[1] = CE*CD; wa.nc[1] = CD; wa.ld[1] = 2*CD;
        size_t off = 0;
        int mx = wa.sz[0];
        for (int i=0;i<8;i++){
            rptr[i] = base + off; off += (size_t)rrow[i]*rcol[i];
            wa.src[i+2] = (const float*)d_in[ridx[i]];
            wa.dst[i+2] = rptr[i];
            wa.sz[i+2]  = rrow[i]*rcol[i];
            wa.nc[i+2]  = rcol[i];
            wa.ld[i+2]  = rcol[i];
            if (wa.sz[i+2] > mx) mx = wa.sz[i+2];
        }
        round_all<<<dim3((mx/4+255)/256, 10), 256>>>(wa);
    }
    __half* a1_wkv = rptr[0]; __half* a1_wp = rptr[1];
    __half* m1_w1  = rptr[2]; __half* m1_w2 = rptr[3];
    __half* a2_wkv = rptr[4]; __half* a2_wp = rptr[5];
    __half* m2_w1  = rptr[6]; __half* m2_w2 = rptr[7];

    ln_kernel<<<CRQ/8, 256>>>(query,   ln_w, ln_b, out_q, tq);
    ln_kernel<<<CRC/8, 256>>>(context, ln_w, ln_b, nullptr, cn);

    // merged Q projection for both attention blocks: Qp[CRQ, 768]
    gemm_kernel<<<dim3(6, 64), 256, GEMM_SMEM>>>(tq, Qw, nullptr, Qp, nullptr, nullptr, CRQ, 2*CD, CE, 0);

    // ---- block 1: cross-attention over context (m=2048) ----
    gemm_kernel<<<dim3(6, 128), 256, GEMM_SMEM>>>(cn, a1_wkv, nullptr, KVp, nullptr, nullptr, CRC, 2*CD, CE, 0);
    fattn_kernel<<<dim3(CNQ/128, CB*CNH), 256, FA_SMEM>>>(Qp, 2*CD, KVp, AOp, CNC);
    gemm_kernel<<<dim3(6, 64), 256, GEMM_SMEM>>>(AOp, a1_wp, cp, nullptr, a1_bp, nullptr, CRQ, CE, CD, 0);

    // ---- MLP 1 (with residual) ----
    ln_kernel<<<CRQ/8, 256>>>(cp, ln_w, ln_b, nullptr, tp);
    gemm_kernel<<<dim3(24, 64), 256, GEMM_SMEM>>>(tp, m1_w1, nullptr, Hp, m1_b1, nullptr, CRQ, CHID, CE,   1);
    gemm_kernel<<<dim3(6, 64),  256, GEMM_SMEM>>>(Hp, m1_w2, cp, nullptr, m1_b2, cp,      CRQ, CE,   CHID, 0);

    // ---- block 2: cross-attention over c (m=1024), residual ----
    ln_kernel<<<CRQ/8, 256>>>(cp, ln_w, ln_b, nullptr, tp);
    gemm_kernel<<<dim3(6, 64), 256, GEMM_SMEM>>>(tp, a2_wkv, nullptr, KVp, nullptr, nullptr, CRQ, 2*CD, CE, 0);
    fattn_kernel<<<dim3(CNQ/128, CB*CNH), 256, FA_SMEM>>>(Qp + CD, 2*CD, KVp, AOp, CNQ);
    gemm_kernel<<<dim3(6, 64), 256, GEMM_SMEM>>>(AOp, a2_wp, cp, nullptr, a2_bp, cp, CRQ, CE, CD, 0);

    // ---- MLP 2 (with residual), final write straight into d_out ----
    ln_kernel<<<CRQ/8, 256>>>(cp, ln_w, ln_b, nullptr, tp);
    gemm_kernel<<<dim3(24, 64), 256, GEMM_SMEM>>>(tp, m2_w1, nullptr, Hp, m2_b1, nullptr, CRQ, CHID, CE,   1);
    gemm_kernel<<<dim3(6, 64),  256, GEMM_SMEM>>>(Hp, m2_w2, out_c, nullptr, m2_b2, cp,   CRQ, CE,   CHID, 0);
}